// round 6
// baseline (speedup 1.0000x reference)
#include <cuda_runtime.h>
#include <cuda_bf16.h>
#include <math.h>
#include <stdint.h>

#define Bn    256
#define Tn    512
#define Dn    512
#define Hn    512
#define H3    1536
#define DICTn 1024
#define Qn    32
#define BT    (Bn*Tn)
#define NSAMP (Bn*Qn*DICTn)   // 8388608

#define NCTA_REC 128
#define WS_WORDS (48*512)

// ---------------- static device scratch -------------------------------------
__device__ float g_GI[(size_t)BT * H3];
__device__ float g_h[2][Bn * Hn];
__device__ float g_c1[Bn * Hn];
__device__ float g_c2[Bn * Hn];
__device__ float g_logits[(size_t)Bn * Qn * DICTn];
__device__ float g_gumbel[(size_t)NSAMP];
__device__ unsigned g_barrier;

// ---------------- threefry2x32-20 (JAX-exact) --------------------------------
__host__ __device__ inline void threefry2x32(unsigned k0, unsigned k1,
                                             unsigned x0, unsigned x1,
                                             unsigned* o0, unsigned* o1) {
    unsigned ks2 = k0 ^ k1 ^ 0x1BD11BDAu;
    x0 += k0; x1 += k1;
#define TF_R(r) { x0 += x1; x1 = (x1 << (r)) | (x1 >> (32-(r))); x1 ^= x0; }
    TF_R(13) TF_R(15) TF_R(26) TF_R(6)   x0 += k1;  x1 += ks2 + 1u;
    TF_R(17) TF_R(29) TF_R(16) TF_R(24)  x0 += ks2; x1 += k0  + 2u;
    TF_R(13) TF_R(15) TF_R(26) TF_R(6)   x0 += k0;  x1 += k1  + 3u;
    TF_R(17) TF_R(29) TF_R(16) TF_R(24)  x0 += k1;  x1 += ks2 + 4u;
    TF_R(13) TF_R(15) TF_R(26) TF_R(6)   x0 += ks2; x1 += k0  + 5u;
#undef TF_R
    *o0 = x0; *o1 = x1;
}

__device__ __forceinline__ unsigned tf32r(float v) {
    unsigned o; asm("cvt.rna.tf32.f32 %0, %1;" : "=r"(o) : "f"(v)); return o;
}

// ---------------- accurate fp32 exp/log --------------------------------------
__device__ __forceinline__ float exp_acc(float x) {
    x = fminf(fmaxf(x, -80.f), 80.f);
    float n = rintf(x * 1.4426950408889634f);
    float r = fmaf(n, -0.6931471824645996f, x);
    r = fmaf(n, 1.9046542121259063e-9f, r);
    float p = 1.984126984e-4f;
    p = fmaf(p, r, 1.388888889e-3f);
    p = fmaf(p, r, 8.333333333e-3f);
    p = fmaf(p, r, 4.166666667e-2f);
    p = fmaf(p, r, 1.666666667e-1f);
    p = fmaf(p, r, 0.5f);
    p = fmaf(p, r, 1.0f);
    p = fmaf(p, r, 1.0f);
    int ni = (int)n;
    float sc = __int_as_float((ni + 127) << 23);
    return p * sc;
}

__device__ __forceinline__ float log_acc(float x) {
    int xi = __float_as_int(x);
    int e = ((xi >> 23) & 0xff) - 127;
    float m = __int_as_float((xi & 0x7fffff) | 0x3f800000);
    if (m > 1.4142135623730951f) { m *= 0.5f; e += 1; }
    float fe = (float)e;
    float s = __fdiv_rn(m - 1.0f, m + 1.0f);
    float s2 = s * s;
    float p = 0.111111111f;
    p = fmaf(p, s2, 0.142857143f);
    p = fmaf(p, s2, 0.2f);
    p = fmaf(p, s2, 0.333333333f);
    p = p * s2;
    float logm = fmaf(2.0f * s, p, 2.0f * s);
    float res = fmaf(fe, 0.6931471824645996f, logm);
    res = fmaf(fe, -1.9046542121259063e-9f, res);
    return res;
}

__device__ __forceinline__ float sigmoid_acc(float x) {
    return __fdiv_rn(1.0f, 1.0f + exp_acc(-x));
}
__device__ __forceinline__ float tanh_acc(float x) {
    float a = fabsf(x);
    float e = exp_acc(-2.0f * a);
    float t = __fdiv_rn(1.0f - e, 1.0f + e);
    return copysignf(t, x);
}

#define MMA(ACC, A0,A1,A2,A3, B0,B1)                                          \
    asm volatile(                                                             \
        "mma.sync.aligned.m16n8k8.row.col.f32.tf32.tf32.f32 "                 \
        "{%0,%1,%2,%3}, {%4,%5,%6,%7}, {%8,%9}, {%0,%1,%2,%3};\n"             \
        : "+f"(ACC[0]), "+f"(ACC[1]), "+f"(ACC[2]), "+f"(ACC[3])              \
        : "r"(A0), "r"(A1), "r"(A2), "r"(A3), "r"(B0), "r"(B1))

// ---------------- 3xTF32 GEMM: C[M,N] = A[M,K]*B[N,K]^T + bias ---------------
__global__ __launch_bounds__(256, 2)
void gemm_f32(const float* __restrict__ A, int lda,
              const float* __restrict__ Bm, int ldb,
              float* __restrict__ C, int ldc,
              int K, const float* __restrict__ bias, int relu,
              const int* __restrict__ row_lens)
{
    __shared__ unsigned As_h[128][32], As_l[128][32];
    __shared__ unsigned Bs_h[64][32],  Bs_l[64][32];

    const int tid  = threadIdx.x;
    const int warp = tid >> 5, lane = tid & 31;
    const int g    = lane >> 2, tig = lane & 3;
    const int m0   = blockIdx.y * 128, n0 = blockIdx.x * 64;
    const int wm   = (warp >> 1) * 32, wn = (warp & 1) * 32;

    if (row_lens) {
        int b = m0 >> 9;
        int ts = m0 & 511;
        if (ts >= row_lens[b]) return;
    }

    float acc[2][4][4];
#pragma unroll
    for (int mi = 0; mi < 2; mi++)
#pragma unroll
        for (int ni = 0; ni < 4; ni++)
#pragma unroll
            for (int r = 0; r < 4; r++) acc[mi][ni][r] = 0.f;

    float ra[16], rb[8];
#pragma unroll
    for (int i = 0; i < 16; i++) {
        int idx = tid + i * 256; int m = idx >> 5, k = idx & 31;
        ra[i] = A[(size_t)(m0 + m) * lda + k];
    }
#pragma unroll
    for (int i = 0; i < 8; i++) {
        int idx = tid + i * 256; int n = idx >> 5, k = idx & 31;
        rb[i] = Bm[(size_t)(n0 + n) * ldb + k];
    }

    const int nchunk = K >> 5;
    for (int ch = 0; ch < nchunk; ch++) {
#pragma unroll
        for (int i = 0; i < 16; i++) {
            int idx = tid + i * 256; int m = idx >> 5, k = (idx & 31) ^ (((idx >> 5) & 7) << 2);
            unsigned hi = tf32r(ra[i]);
            As_h[m][k] = hi;
            As_l[m][k] = tf32r(ra[i] - __uint_as_float(hi));
        }
#pragma unroll
        for (int i = 0; i < 8; i++) {
            int idx = tid + i * 256; int n = idx >> 5, k = (idx & 31) ^ (((idx >> 5) & 7) << 2);
            unsigned hi = tf32r(rb[i]);
            Bs_h[n][k] = hi;
            Bs_l[n][k] = tf32r(rb[i] - __uint_as_float(hi));
        }
        __syncthreads();

        if (ch + 1 < nchunk) {
            int k0 = (ch + 1) << 5;
#pragma unroll
            for (int i = 0; i < 16; i++) {
                int idx = tid + i * 256; int m = idx >> 5, k = idx & 31;
                ra[i] = A[(size_t)(m0 + m) * lda + k0 + k];
            }
#pragma unroll
            for (int i = 0; i < 8; i++) {
                int idx = tid + i * 256; int n = idx >> 5, k = idx & 31;
                rb[i] = Bm[(size_t)(n0 + n) * ldb + k0 + k];
            }
        }

#pragma unroll
        for (int kk = 0; kk < 32; kk += 8) {
            unsigned ah[2][4], al[2][4], bh[4][2], bl[4][2];
#pragma unroll
            for (int mi = 0; mi < 2; mi++) {
                int r0 = wm + mi * 16;
                int c0k = (kk + tig) ^ (g << 2), c1k = (kk + tig + 4) ^ (g << 2);
                ah[mi][0] = As_h[r0 + g    ][c0k]; al[mi][0] = As_l[r0 + g    ][c0k];
                ah[mi][1] = As_h[r0 + g + 8][c0k]; al[mi][1] = As_l[r0 + g + 8][c0k];
                ah[mi][2] = As_h[r0 + g    ][c1k]; al[mi][2] = As_l[r0 + g    ][c1k];
                ah[mi][3] = As_h[r0 + g + 8][c1k]; al[mi][3] = As_l[r0 + g + 8][c1k];
            }
#pragma unroll
            for (int ni = 0; ni < 4; ni++) {
                int nrow = wn + ni * 8 + g;
                int c0k = (kk + tig) ^ (g << 2), c1k = (kk + tig + 4) ^ (g << 2);
                bh[ni][0] = Bs_h[nrow][c0k]; bl[ni][0] = Bs_l[nrow][c0k];
                bh[ni][1] = Bs_h[nrow][c1k]; bl[ni][1] = Bs_l[nrow][c1k];
            }
#pragma unroll
            for (int mi = 0; mi < 2; mi++)
#pragma unroll
                for (int ni = 0; ni < 4; ni++) {
                    MMA(acc[mi][ni], ah[mi][0],ah[mi][1],ah[mi][2],ah[mi][3], bl[ni][0],bl[ni][1]);
                    MMA(acc[mi][ni], al[mi][0],al[mi][1],al[mi][2],al[mi][3], bh[ni][0],bh[ni][1]);
                    MMA(acc[mi][ni], ah[mi][0],ah[mi][1],ah[mi][2],ah[mi][3], bh[ni][0],bh[ni][1]);
                }
        }
        __syncthreads();
    }

#pragma unroll
    for (int mi = 0; mi < 2; mi++)
#pragma unroll
        for (int ni = 0; ni < 4; ni++) {
            int r = m0 + wm + mi * 16 + g;
            int c = n0 + wn + ni * 8 + tig * 2;
            float b0 = bias ? bias[c]     : 0.f;
            float b1 = bias ? bias[c + 1] : 0.f;
            float v0 = acc[mi][ni][0] + b0;
            float v1 = acc[mi][ni][1] + b1;
            float v2 = acc[mi][ni][2] + b0;
            float v3 = acc[mi][ni][3] + b1;
            if (relu) { v0 = fmaxf(v0, 0.f); v1 = fmaxf(v1, 0.f);
                        v2 = fmaxf(v2, 0.f); v3 = fmaxf(v3, 0.f); }
            C[(size_t)r * ldc + c]           = v0;
            C[(size_t)r * ldc + c + 1]       = v1;
            C[(size_t)(r + 8) * ldc + c]     = v2;
            C[(size_t)(r + 8) * ldc + c + 1] = v3;
        }
}

// ---------------- persistent GRU recurrence (v2) -----------------------------
// 128 CTAs = 4 batch-groups(64 rows) x 32 col-groups(16 hidden -> 48 gh cols).
// 384 threads = 12 MMA warps (4m x 3 n-pairs); warps 0-7 also load/split A.
// W_hh slice hi/lo resident in SMEM (196.6KB); A chunk hi/lo double-buffered.
// Split accumulator chains accP (ah*bh) / accQ (ah*bl + al*bh).
__global__ __launch_bounds__(384, 1)
void gru_persistent(const float* __restrict__ GI,
                    const float* __restrict__ W_hh,
                    const float* __restrict__ b_hh,
                    const int*   __restrict__ lengths,
                    float* __restrict__ hbase,
                    unsigned* __restrict__ bar)
{
    extern __shared__ unsigned smem[];
    unsigned* Ws_h = smem;                          // 48*512
    unsigned* Ws_l = smem + WS_WORDS;               // 48*512
    unsigned* Ab_h = smem + 2 * WS_WORDS;           // 2 stages x 2048
    unsigned* Ab_l = smem + 2 * WS_WORDS + 4096;    // 2 stages x 2048
    float*    gh_s = (float*)(smem + 2 * WS_WORDS); // 64x48 reuse after K loop

    const int tid  = threadIdx.x;
    const int warp = tid >> 5, lane = tid & 31;
    const int g    = lane >> 2, tig = lane & 3;
    const int cgp  = blockIdx.x & 31;
    const int bg   = blockIdx.x >> 5;
    const int m0   = bg * 64;
    const int jj0  = cgp * 16;
    const int wm   = (warp & 3) * 16;               // 0,16,32,48
    const int wn   = (warp >> 2) * 16;              // 0,16,32
    const unsigned nc = gridDim.x;
    const bool loader = (tid < 256);

    // one-time W slice preload: row n = gate*16 + c  ->  W_hh[gate*512+jj0+c]
    for (int i = tid; i < WS_WORDS; i += 384) {
        int n = i >> 9, k = i & 511;
        int wrow = (n >> 4) * Hn + jj0 + (n & 15);
        float w = W_hh[(size_t)wrow * Hn + k];
        unsigned hi = tf32r(w);
        int off = (n << 9) + (k & ~31) + ((k & 31) ^ ((n & 7) << 2));
        Ws_h[off] = hi;
        Ws_l[off] = tf32r(w - __uint_as_float(hi));
    }
    __syncthreads();

    for (int t = 0; t < Tn; t++) {
        const float* h_in  = hbase + (t & 1) * (Bn * Hn);
        float*       h_out = hbase + ((t + 1) & 1) * (Bn * Hn);

        float accP[2][4], accQ[2][4];
#pragma unroll
        for (int ni = 0; ni < 2; ni++)
#pragma unroll
            for (int r = 0; r < 4; r++) { accP[ni][r] = 0.f; accQ[ni][r] = 0.f; }

        float ra[8];
        if (loader) {
#pragma unroll
            for (int i = 0; i < 8; i++) {
                int idx = tid + i * 256; int m = idx >> 5, k = idx & 31;
                ra[i] = h_in[(m0 + m) * Hn + k];
            }
#pragma unroll
            for (int i = 0; i < 8; i++) {
                int idx = tid + i * 256; int m = idx >> 5;
                int off = m * 32 + ((idx & 31) ^ ((m & 7) << 2));
                unsigned hi = tf32r(ra[i]);
                Ab_h[off] = hi;
                Ab_l[off] = tf32r(ra[i] - __uint_as_float(hi));
            }
        }
        __syncthreads();

        for (int ch = 0; ch < 16; ch++) {
            if (loader && ch < 15) {
                int k0 = (ch + 1) << 5;
#pragma unroll
                for (int i = 0; i < 8; i++) {
                    int idx = tid + i * 256; int m = idx >> 5, k = idx & 31;
                    ra[i] = h_in[(m0 + m) * Hn + k0 + k];
                }
            }
            const unsigned* Ah = Ab_h + (ch & 1) * 2048;
            const unsigned* Al = Ab_l + (ch & 1) * 2048;
            const int choff = ch << 5;
#pragma unroll
            for (int kk = 0; kk < 32; kk += 8) {
                int c0k = (kk + tig) ^ (g << 2);
                int c1k = (kk + tig + 4) ^ (g << 2);
                unsigned ah0 = Ah[(wm + g    ) * 32 + c0k];
                unsigned ah1 = Ah[(wm + g + 8) * 32 + c0k];
                unsigned ah2 = Ah[(wm + g    ) * 32 + c1k];
                unsigned ah3 = Ah[(wm + g + 8) * 32 + c1k];
                unsigned al0 = Al[(wm + g    ) * 32 + c0k];
                unsigned al1 = Al[(wm + g + 8) * 32 + c0k];
                unsigned al2 = Al[(wm + g    ) * 32 + c1k];
                unsigned al3 = Al[(wm + g + 8) * 32 + c1k];
#pragma unroll
                for (int ni = 0; ni < 2; ni++) {
                    int base = (wn + ni * 8 + g) * 512 + choff;
                    unsigned bh0 = Ws_h[base + c0k], bh1 = Ws_h[base + c1k];
                    unsigned bl0 = Ws_l[base + c0k], bl1 = Ws_l[base + c1k];
                    MMA(accQ[ni], ah0, ah1, ah2, ah3, bl0, bl1);
                    MMA(accQ[ni], al0, al1, al2, al3, bh0, bh1);
                    MMA(accP[ni], ah0, ah1, ah2, ah3, bh0, bh1);
                }
            }
            if (loader && ch < 15) {
                unsigned* Dh = Ab_h + ((ch + 1) & 1) * 2048;
                unsigned* Dl = Ab_l + ((ch + 1) & 1) * 2048;
#pragma unroll
                for (int i = 0; i < 8; i++) {
                    int idx = tid + i * 256; int m = idx >> 5;
                    int off = m * 32 + ((idx & 31) ^ ((m & 7) << 2));
                    unsigned hi = tf32r(ra[i]);
                    Dh[off] = hi;
                    Dl[off] = tf32r(ra[i] - __uint_as_float(hi));
                }
            }
            __syncthreads();
        }

        // stage gh tile (64x48)
#pragma unroll
        for (int ni = 0; ni < 2; ni++) {
            int r = wm + g;
            int c = wn + ni * 8 + tig * 2;
            gh_s[r * 48 + c]           = accP[ni][0] + accQ[ni][0];
            gh_s[r * 48 + c + 1]       = accP[ni][1] + accQ[ni][1];
            gh_s[(r + 8) * 48 + c]     = accP[ni][2] + accQ[ni][2];
            gh_s[(r + 8) * 48 + c + 1] = accP[ni][3] + accQ[ni][3];
        }
        __syncthreads();

        // gate math: 64 rows x 16 cols = 1024 elems over 384 threads
        for (int e = tid; e < 1024; e += 384) {
            int row = e >> 4, col = e & 15;
            int b = m0 + row, jj = jj0 + col;
            const float* gi = GI + ((size_t)b * Tn + t) * H3;
            float ghr = gh_s[row * 48 + col]      + b_hh[jj];
            float ghz = gh_s[row * 48 + 16 + col] + b_hh[Hn + jj];
            float ghn = gh_s[row * 48 + 32 + col] + b_hh[2 * Hn + jj];
            float r = sigmoid_acc(gi[jj] + ghr);
            float z = sigmoid_acc(gi[Hn + jj] + ghz);
            float n = tanh_acc(fmaf(r, ghn, gi[2 * Hn + jj]));
            float ho = h_in[b * Hn + jj];
            float hv = (t < lengths[b]) ? ((1.f - z) * n + z * ho) : ho;
            h_out[b * Hn + jj] = hv;
        }

        // grid barrier (all 128 CTAs co-resident)
        __syncthreads();
        if (tid == 0) {
            __threadfence();
            atomicAdd(bar, 1u);
            unsigned target = nc * (unsigned)(t + 1);
            unsigned v;
            do {
                asm volatile("ld.acquire.gpu.global.b32 %0, [%1];"
                             : "=r"(v) : "l"(bar) : "memory");
                if (v < target) __nanosleep(32);
            } while (v < target);
        }
        __syncthreads();
    }
}

// ---------------- misc -------------------------------------------------------
__global__ void init_kernel(float* h0, unsigned* bar) {
    int i = blockIdx.x * blockDim.x + threadIdx.x;
    if (i < Bn * Hn) h0[i] = 0.f;
    if (i == 0) *bar = 0u;
}

__global__ void value_kernel(const float* __restrict__ h2,
                             const float* __restrict__ Wc3,
                             const float* __restrict__ bc3,
                             float* __restrict__ out)
{
    int gw = (blockIdx.x * blockDim.x + threadIdx.x) >> 5;
    int lane = threadIdx.x & 31;
    if (gw >= Bn) return;
    float s = 0.f;
    for (int k = lane; k < Hn; k += 32) s = fmaf(h2[gw * Hn + k], Wc3[k], s);
#pragma unroll
    for (int o = 16; o; o >>= 1) s += __shfl_xor_sync(0xffffffffu, s, o);
    if (lane == 0) out[gw] = s + bc3[0];
}

__global__ void gumbel_kernel(unsigned k0, unsigned k1, float* __restrict__ gout)
{
    unsigned i = blockIdx.x * blockDim.x + threadIdx.x;
    unsigned o0, o1;
    threefry2x32(k0, k1, 0u, i, &o0, &o1);
    unsigned bits = o0 ^ o1;
    float f = __uint_as_float((bits >> 9) | 0x3f800000u) - 1.0f;
    float u = fmaxf(f, 1.17549435e-38f);
    float g = -log_acc(-log_acc(u));
    gout[i] = g;
}

__global__ __launch_bounds__(256)
void sample_kernel(const float* __restrict__ logits,
                   const float* __restrict__ gumbel,
                   float* __restrict__ out_query,
                   float* __restrict__ out_lp)
{
    __shared__ float red[256];
    __shared__ int   redi[256];
    int row = blockIdx.x;
    int tid = threadIdx.x;
    const float* lg = logits + (size_t)row * DICTn;
    const float* gm = gumbel + (size_t)row * DICTn;

    float l[4];
#pragma unroll
    for (int i = 0; i < 4; i++) l[i] = lg[tid + i * 256];

    float mx = fmaxf(fmaxf(l[0], l[1]), fmaxf(l[2], l[3]));
    red[tid] = mx; __syncthreads();
    for (int s = 128; s > 0; s >>= 1) {
        if (tid < s) red[tid] = fmaxf(red[tid], red[tid + s]);
        __syncthreads();
    }
    mx = red[0]; __syncthreads();

    float se = 0.f;
#pragma unroll
    for (int i = 0; i < 4; i++) se += exp_acc(l[i] - mx);
    red[tid] = se; __syncthreads();
    for (int s = 128; s > 0; s >>= 1) {
        if (tid < s) red[tid] += red[tid + s];
        __syncthreads();
    }
    float logZ = mx + log_acc(red[0]); __syncthreads();

    float bv = -1e30f; int bi = 0x7fffffff;
#pragma unroll
    for (int i = 0; i < 4; i++) {
        int idx = tid + i * 256;
        float lp = l[i] - logZ;
        out_lp[(size_t)row * DICTn + idx] = lp;
        float v = lp + gm[idx];
        if (v > bv || (v == bv && idx < bi)) { bv = v; bi = idx; }
    }
    red[tid] = bv; redi[tid] = bi; __syncthreads();
    for (int s = 128; s > 0; s >>= 1) {
        if (tid < s) {
            if (red[tid + s] > red[tid] ||
                (red[tid + s] == red[tid] && redi[tid + s] < redi[tid])) {
                red[tid] = red[tid + s]; redi[tid] = redi[tid + s];
            }
        }
        __syncthreads();
    }
    int win = redi[0];
#pragma unroll
    for (int i = 0; i < 4; i++) {
        int idx = tid + i * 256;
        out_query[(size_t)row * DICTn + idx] = (idx == win) ? 1.f : 0.f;
    }
}

// ---------------- host -------------------------------------------------------
extern "C" void kernel_launch(void* const* d_in, const int* in_sizes, int n_in,
                              void* d_out, int out_size)
{
    const float* x      = (const float*)d_in[0];
    const int*   lens   = (const int*)  d_in[1];
    const float* W_ih   = (const float*)d_in[2];
    const float* W_hh   = (const float*)d_in[3];
    const float* b_ih   = (const float*)d_in[4];
    const float* b_hh   = (const float*)d_in[5];
    const float* W_out  = (const float*)d_in[6];
    const float* b_out  = (const float*)d_in[7];
    const float* Wc1    = (const float*)d_in[8];
    const float* bc1    = (const float*)d_in[9];
    const float* Wc2    = (const float*)d_in[10];
    const float* bc2    = (const float*)d_in[11];
    const float* Wc3    = (const float*)d_in[12];
    const float* bc3    = (const float*)d_in[13];

    float* out_value = (float*)d_out;
    float* out_query = out_value + Bn;
    float* out_lp    = out_query + (size_t)NSAMP;

    float *pGI, *ph0, *pc1, *pc2, *plog, *pgum;
    unsigned* pbar;
    cudaGetSymbolAddress((void**)&pGI,  g_GI);
    cudaGetSymbolAddress((void**)&ph0,  g_h);
    cudaGetSymbolAddress((void**)&pc1,  g_c1);
    cudaGetSymbolAddress((void**)&pc2,  g_c2);
    cudaGetSymbolAddress((void**)&plog, g_logits);
    cudaGetSymbolAddress((void**)&pgum, g_gumbel);
    cudaGetSymbolAddress((void**)&pbar, g_barrier);

    const int rec_smem = (2 * WS_WORDS + 4 * 2048) * 4;   // 229376 B
    cudaFuncSetAttribute(gru_persistent,
        cudaFuncAttributeMaxDynamicSharedMemorySize, rec_smem);

    // 1) zero h0 + barrier counter
    init_kernel<<<(Bn * Hn + 255) / 256, 256>>>(ph0, pbar);

    // 2) GI = x @ W_ih^T + b_ih  (ragged tile skip)
    gemm_f32<<<dim3(H3 / 64, BT / 128), 256>>>(x, Dn, W_ih, Dn, pGI, H3,
                                               Dn, b_ih, 0, lens);

    // 3) persistent recurrence
    gru_persistent<<<NCTA_REC, 384, rec_smem>>>(pGI, W_hh, b_hh, lens,
                                                ph0, pbar);
    float* hfin = ph0;

    // 4) critic
    gemm_f32<<<dim3(Hn / 64, Bn / 128), 256>>>(hfin, Hn, Wc1, Hn, pc1, Hn,
                                               Hn, bc1, 1, nullptr);
    gemm_f32<<<dim3(Hn / 64, Bn / 128), 256>>>(pc1, Hn, Wc2, Hn, pc2, Hn,
                                               Hn, bc2, 1, nullptr);
    value_kernel<<<(Bn * 32 + 255) / 256, 256>>>(pc2, Wc3, bc3, out_value);

    // 5) actor logits
    gemm_f32<<<dim3(DICTn * Qn / 64, Bn / 128), 256>>>(hfin, Hn, W_out, Hn,
                                                       plog, DICTn * Qn,
                                                       Hn, b_out, 0, nullptr);

    // 6) gumbel noise
    unsigned s0, s1;
    threefry2x32(0u, 0u, 0u, 1234u, &s0, &s1);
    gumbel_kernel<<<NSAMP / 256, 256>>>(s0, s1, pgum);

    // 7) log-softmax + categorical sample + one-hot
    sample_kernel<<<Bn * Qn, 256>>>(plog, pgum, out_query, out_lp);
}

// round 7
// speedup vs baseline: 1.1789x; 1.1789x over previous
#include <cuda_runtime.h>
#include <cuda_bf16.h>
#include <math.h>
#include <stdint.h>

#define Bn    256
#define Tn    512
#define Dn    512
#define Hn    512
#define H3    1536
#define DICTn 1024
#define Qn    32
#define BT    (Bn*Tn)
#define NSAMP (Bn*Qn*DICTn)   // 8388608

#define NCTA_REC 128
#define WS_WORDS (48*512)

// ---------------- static device scratch -------------------------------------
__device__ float g_GI[(size_t)BT * H3];
__device__ float g_h[2][Bn * Hn];
__device__ float g_c1[Bn * Hn];
__device__ float g_c2[Bn * Hn];
__device__ float g_logits[(size_t)Bn * Qn * DICTn];
__device__ float g_gumbel[(size_t)NSAMP];
__device__ unsigned g_barrier[4];

// ---------------- threefry2x32-20 (JAX-exact) --------------------------------
__host__ __device__ inline void threefry2x32(unsigned k0, unsigned k1,
                                             unsigned x0, unsigned x1,
                                             unsigned* o0, unsigned* o1) {
    unsigned ks2 = k0 ^ k1 ^ 0x1BD11BDAu;
    x0 += k0; x1 += k1;
#define TF_R(r) { x0 += x1; x1 = (x1 << (r)) | (x1 >> (32-(r))); x1 ^= x0; }
    TF_R(13) TF_R(15) TF_R(26) TF_R(6)   x0 += k1;  x1 += ks2 + 1u;
    TF_R(17) TF_R(29) TF_R(16) TF_R(24)  x0 += ks2; x1 += k0  + 2u;
    TF_R(13) TF_R(15) TF_R(26) TF_R(6)   x0 += k0;  x1 += k1  + 3u;
    TF_R(17) TF_R(29) TF_R(16) TF_R(24)  x0 += k1;  x1 += ks2 + 4u;
    TF_R(13) TF_R(15) TF_R(26) TF_R(6)   x0 += ks2; x1 += k0  + 5u;
#undef TF_R
    *o0 = x0; *o1 = x1;
}

__device__ __forceinline__ unsigned tf32r(float v) {
    unsigned o; asm("cvt.rna.tf32.f32 %0, %1;" : "=r"(o) : "f"(v)); return o;
}
__device__ __forceinline__ uint2 split2(float v) {
    uint2 r;
    r.x = tf32r(v);
    r.y = tf32r(v - __uint_as_float(r.x));
    return r;
}

// ---------------- accurate fp32 exp/log --------------------------------------
__device__ __forceinline__ float exp_acc(float x) {
    x = fminf(fmaxf(x, -80.f), 80.f);
    float n = rintf(x * 1.4426950408889634f);
    float r = fmaf(n, -0.6931471824645996f, x);
    r = fmaf(n, 1.9046542121259063e-9f, r);
    float p = 1.984126984e-4f;
    p = fmaf(p, r, 1.388888889e-3f);
    p = fmaf(p, r, 8.333333333e-3f);
    p = fmaf(p, r, 4.166666667e-2f);
    p = fmaf(p, r, 1.666666667e-1f);
    p = fmaf(p, r, 0.5f);
    p = fmaf(p, r, 1.0f);
    p = fmaf(p, r, 1.0f);
    int ni = (int)n;
    float sc = __int_as_float((ni + 127) << 23);
    return p * sc;
}

__device__ __forceinline__ float log_acc(float x) {
    int xi = __float_as_int(x);
    int e = ((xi >> 23) & 0xff) - 127;
    float m = __int_as_float((xi & 0x7fffff) | 0x3f800000);
    if (m > 1.4142135623730951f) { m *= 0.5f; e += 1; }
    float fe = (float)e;
    float s = __fdiv_rn(m - 1.0f, m + 1.0f);
    float s2 = s * s;
    float p = 0.111111111f;
    p = fmaf(p, s2, 0.142857143f);
    p = fmaf(p, s2, 0.2f);
    p = fmaf(p, s2, 0.333333333f);
    p = p * s2;
    float logm = fmaf(2.0f * s, p, 2.0f * s);
    float res = fmaf(fe, 0.6931471824645996f, logm);
    res = fmaf(fe, -1.9046542121259063e-9f, res);
    return res;
}

__device__ __forceinline__ float sigmoid_acc(float x) {
    return __fdiv_rn(1.0f, 1.0f + exp_acc(-x));
}
__device__ __forceinline__ float tanh_acc(float x) {
    float a = fabsf(x);
    float e = exp_acc(-2.0f * a);
    float t = __fdiv_rn(1.0f - e, 1.0f + e);
    return copysignf(t, x);
}

#define MMA(ACC, A0,A1,A2,A3, B0,B1)                                          \
    asm volatile(                                                             \
        "mma.sync.aligned.m16n8k8.row.col.f32.tf32.tf32.f32 "                 \
        "{%0,%1,%2,%3}, {%4,%5,%6,%7}, {%8,%9}, {%0,%1,%2,%3};\n"             \
        : "+f"(ACC[0]), "+f"(ACC[1]), "+f"(ACC[2]), "+f"(ACC[3])              \
        : "r"(A0), "r"(A1), "r"(A2), "r"(A3), "r"(B0), "r"(B1))

// ---------------- 3xTF32 GEMM (packed hi/lo, 64-bit LDS) ---------------------
// C[M,N] = A[M,K]*B[N,K]^T + bias. 128x64 tile, 8 warps (4x2), warp 32x32.
__global__ __launch_bounds__(256, 2)
void gemm_f32(const float* __restrict__ A, int lda,
              const float* __restrict__ Bm, int ldb,
              float* __restrict__ C, int ldc,
              int K, const float* __restrict__ bias, int relu,
              const int* __restrict__ row_lens)
{
    __shared__ uint2 As2[128][32];
    __shared__ uint2 Bs2[64][32];

    const int tid  = threadIdx.x;
    const int warp = tid >> 5, lane = tid & 31;
    const int g    = lane >> 2, tig = lane & 3;
    const int m0   = blockIdx.y * 128, n0 = blockIdx.x * 64;
    const int wm   = (warp >> 1) * 32, wn = (warp & 1) * 32;

    if (row_lens) {
        int b = m0 >> 9;
        int ts = m0 & 511;
        if (ts >= row_lens[b]) return;
    }

    float acc[2][4][4];
#pragma unroll
    for (int mi = 0; mi < 2; mi++)
#pragma unroll
        for (int ni = 0; ni < 4; ni++)
#pragma unroll
            for (int r = 0; r < 4; r++) acc[mi][ni][r] = 0.f;

    float ra[16], rb[8];
#pragma unroll
    for (int i = 0; i < 16; i++) {
        int idx = tid + i * 256; int m = idx >> 5, k = idx & 31;
        ra[i] = A[(size_t)(m0 + m) * lda + k];
    }
#pragma unroll
    for (int i = 0; i < 8; i++) {
        int idx = tid + i * 256; int n = idx >> 5, k = idx & 31;
        rb[i] = Bm[(size_t)(n0 + n) * ldb + k];
    }

    const int nchunk = K >> 5;
    for (int ch = 0; ch < nchunk; ch++) {
#pragma unroll
        for (int i = 0; i < 16; i++) {
            int idx = tid + i * 256; int m = idx >> 5;
            int k = (idx & 31) ^ ((m & 7) << 2);
            As2[m][k] = split2(ra[i]);
        }
#pragma unroll
        for (int i = 0; i < 8; i++) {
            int idx = tid + i * 256; int n = idx >> 5;
            int k = (idx & 31) ^ ((n & 7) << 2);
            Bs2[n][k] = split2(rb[i]);
        }
        __syncthreads();

        if (ch + 1 < nchunk) {
            int k0 = (ch + 1) << 5;
#pragma unroll
            for (int i = 0; i < 16; i++) {
                int idx = tid + i * 256; int m = idx >> 5, k = idx & 31;
                ra[i] = A[(size_t)(m0 + m) * lda + k0 + k];
            }
#pragma unroll
            for (int i = 0; i < 8; i++) {
                int idx = tid + i * 256; int n = idx >> 5, k = idx & 31;
                rb[i] = Bm[(size_t)(n0 + n) * ldb + k0 + k];
            }
        }

#pragma unroll
        for (int kk = 0; kk < 32; kk += 8) {
            int c0k = (kk + tig) ^ (g << 2), c1k = (kk + tig + 4) ^ (g << 2);
            uint2 a[2][4];
#pragma unroll
            for (int mi = 0; mi < 2; mi++) {
                int r0 = wm + mi * 16;
                a[mi][0] = As2[r0 + g    ][c0k];
                a[mi][1] = As2[r0 + g + 8][c0k];
                a[mi][2] = As2[r0 + g    ][c1k];
                a[mi][3] = As2[r0 + g + 8][c1k];
            }
            uint2 b[4][2];
#pragma unroll
            for (int ni = 0; ni < 4; ni++) {
                int nrow = wn + ni * 8 + g;
                b[ni][0] = Bs2[nrow][c0k];
                b[ni][1] = Bs2[nrow][c1k];
            }
#pragma unroll
            for (int mi = 0; mi < 2; mi++)
#pragma unroll
                for (int ni = 0; ni < 4; ni++) {
                    MMA(acc[mi][ni], a[mi][0].x,a[mi][1].x,a[mi][2].x,a[mi][3].x,
                        b[ni][0].y, b[ni][1].y);
                    MMA(acc[mi][ni], a[mi][0].y,a[mi][1].y,a[mi][2].y,a[mi][3].y,
                        b[ni][0].x, b[ni][1].x);
                    MMA(acc[mi][ni], a[mi][0].x,a[mi][1].x,a[mi][2].x,a[mi][3].x,
                        b[ni][0].x, b[ni][1].x);
                }
        }
        __syncthreads();
    }

#pragma unroll
    for (int mi = 0; mi < 2; mi++)
#pragma unroll
        for (int ni = 0; ni < 4; ni++) {
            int r = m0 + wm + mi * 16 + g;
            int c = n0 + wn + ni * 8 + tig * 2;
            float b0 = bias ? bias[c]     : 0.f;
            float b1 = bias ? bias[c + 1] : 0.f;
            float v0 = acc[mi][ni][0] + b0;
            float v1 = acc[mi][ni][1] + b1;
            float v2 = acc[mi][ni][2] + b0;
            float v3 = acc[mi][ni][3] + b1;
            if (relu) { v0 = fmaxf(v0, 0.f); v1 = fmaxf(v1, 0.f);
                        v2 = fmaxf(v2, 0.f); v3 = fmaxf(v3, 0.f); }
            C[(size_t)r * ldc + c]           = v0;
            C[(size_t)r * ldc + c + 1]       = v1;
            C[(size_t)(r + 8) * ldc + c]     = v2;
            C[(size_t)(r + 8) * ldc + c + 1] = v3;
        }
}

// ---------------- persistent GRU recurrence (v3) -----------------------------
// 128 CTAs = 4 batch-groups(64 rows, independent barriers) x 32 col-groups.
// Packed hi/lo uint2 smem (64-bit LDS), GI prefetch hidden behind barrier.
__global__ __launch_bounds__(384, 1)
void gru_persistent(const float* __restrict__ GI,
                    const float* __restrict__ W_hh,
                    const float* __restrict__ b_hh,
                    const int*   __restrict__ lengths,
                    float* __restrict__ hbase,
                    unsigned* __restrict__ bar)
{
    extern __shared__ uint2 smem2[];
    uint2* Ws2 = smem2;                      // 48*512 uint2 = 196608 B
    uint2* Ab2 = smem2 + WS_WORDS;           // 2 stages x 2048 uint2 = 32768 B
    float* gh_s = (float*)(smem2 + WS_WORDS);

    const int tid  = threadIdx.x;
    const int warp = tid >> 5, lane = tid & 31;
    const int g    = lane >> 2, tig = lane & 3;
    const int cgp  = blockIdx.x & 31;
    const int bg   = blockIdx.x >> 5;
    const int m0   = bg * 64;
    const int jj0  = cgp * 16;
    const int wm   = (warp & 3) * 16;
    const int wn   = (warp >> 2) * 16;
    unsigned* mybar = bar + bg;
    const bool loader = (tid < 256);

    // one-time W slice preload (packed)
    for (int i = tid; i < WS_WORDS; i += 384) {
        int n = i >> 9, k = i & 511;
        int wrow = (n >> 4) * Hn + jj0 + (n & 15);
        float w = W_hh[(size_t)wrow * Hn + k];
        int off = (n << 9) + (k & ~31) + ((k & 31) ^ ((n & 7) << 2));
        Ws2[off] = split2(w);
    }
    __syncthreads();

    // GI prefetch registers (up to 3 elems/thread)
    float p_r[3], p_z[3], p_n[3];
    {
        int idx = 0;
        for (int e = tid; e < 1024; e += 384, idx++) {
            int row = e >> 4, col = e & 15;
            const float* gi = GI + ((size_t)(m0 + row) * Tn + 0) * H3 + jj0 + col;
            p_r[idx] = gi[0];
            p_z[idx] = gi[Hn];
            p_n[idx] = gi[2 * Hn];
        }
    }

    for (int t = 0; t < Tn; t++) {
        const float* h_in  = hbase + (t & 1) * (Bn * Hn);
        float*       h_out = hbase + ((t + 1) & 1) * (Bn * Hn);

        float accP[2][4], accQ[2][4];
#pragma unroll
        for (int ni = 0; ni < 2; ni++)
#pragma unroll
            for (int r = 0; r < 4; r++) { accP[ni][r] = 0.f; accQ[ni][r] = 0.f; }

        float ra[8];
        if (loader) {
#pragma unroll
            for (int i = 0; i < 8; i++) {
                int idx = tid + i * 256; int m = idx >> 5, k = idx & 31;
                ra[i] = h_in[(m0 + m) * Hn + k];
            }
#pragma unroll
            for (int i = 0; i < 8; i++) {
                int idx = tid + i * 256; int m = idx >> 5;
                int off = (m << 5) + ((idx & 31) ^ ((m & 7) << 2));
                Ab2[off] = split2(ra[i]);
            }
        }
        __syncthreads();

        for (int ch = 0; ch < 16; ch++) {
            if (loader && ch < 15) {
                int k0 = (ch + 1) << 5;
#pragma unroll
                for (int i = 0; i < 8; i++) {
                    int idx = tid + i * 256; int m = idx >> 5, k = idx & 31;
                    ra[i] = h_in[(m0 + m) * Hn + k0 + k];
                }
            }
            const uint2* Ah = Ab2 + (ch & 1) * 2048;
            const int choff = ch << 5;
#pragma unroll
            for (int kk = 0; kk < 32; kk += 8) {
                int c0k = (kk + tig) ^ (g << 2);
                int c1k = (kk + tig + 4) ^ (g << 2);
                uint2 a0 = Ah[((wm + g    ) << 5) + c0k];
                uint2 a1 = Ah[((wm + g + 8) << 5) + c0k];
                uint2 a2 = Ah[((wm + g    ) << 5) + c1k];
                uint2 a3 = Ah[((wm + g + 8) << 5) + c1k];
#pragma unroll
                for (int ni = 0; ni < 2; ni++) {
                    int base = ((wn + ni * 8 + g) << 9) + choff;
                    uint2 b0 = Ws2[base + c0k];
                    uint2 b1 = Ws2[base + c1k];
                    MMA(accQ[ni], a0.x, a1.x, a2.x, a3.x, b0.y, b1.y);
                    MMA(accQ[ni], a0.y, a1.y, a2.y, a3.y, b0.x, b1.x);
                    MMA(accP[ni], a0.x, a1.x, a2.x, a3.x, b0.x, b1.x);
                }
            }
            if (loader && ch < 15) {
                uint2* Dst = Ab2 + ((ch + 1) & 1) * 2048;
#pragma unroll
                for (int i = 0; i < 8; i++) {
                    int idx = tid + i * 256; int m = idx >> 5;
                    int off = (m << 5) + ((idx & 31) ^ ((m & 7) << 2));
                    Dst[off] = split2(ra[i]);
                }
            }
            __syncthreads();
        }

        // stage gh tile (64x48) — reuses A buffer space
#pragma unroll
        for (int ni = 0; ni < 2; ni++) {
            int r = wm + g;
            int c = wn + ni * 8 + tig * 2;
            gh_s[r * 48 + c]           = accP[ni][0] + accQ[ni][0];
            gh_s[r * 48 + c + 1]       = accP[ni][1] + accQ[ni][1];
            gh_s[(r + 8) * 48 + c]     = accP[ni][2] + accQ[ni][2];
            gh_s[(r + 8) * 48 + c + 1] = accP[ni][3] + accQ[ni][3];
        }
        __syncthreads();

        // gate math with prefetched GI
        {
            int idx = 0;
            for (int e = tid; e < 1024; e += 384, idx++) {
                int row = e >> 4, col = e & 15;
                int b = m0 + row, jj = jj0 + col;
                float ghr = gh_s[row * 48 + col]      + b_hh[jj];
                float ghz = gh_s[row * 48 + 16 + col] + b_hh[Hn + jj];
                float ghn = gh_s[row * 48 + 32 + col] + b_hh[2 * Hn + jj];
                float r = sigmoid_acc(p_r[idx] + ghr);
                float z = sigmoid_acc(p_z[idx] + ghz);
                float n = tanh_acc(fmaf(r, ghn, p_n[idx]));
                float ho = h_in[b * Hn + jj];
                float hv = (t < lengths[b]) ? ((1.f - z) * n + z * ho) : ho;
                h_out[b * Hn + jj] = hv;
            }
        }

        // per-batch-group barrier (32 CTAs) + GI prefetch for t+1 during wait
        __syncthreads();
        if (tid == 0) {
            __threadfence();
            atomicAdd(mybar, 1u);
        }
        if (t + 1 < Tn) {
            int idx = 0;
            for (int e = tid; e < 1024; e += 384, idx++) {
                int row = e >> 4, col = e & 15;
                const float* gi = GI + ((size_t)(m0 + row) * Tn + (t + 1)) * H3 + jj0 + col;
                p_r[idx] = gi[0];
                p_z[idx] = gi[Hn];
                p_n[idx] = gi[2 * Hn];
            }
        }
        if (tid == 0) {
            unsigned target = 32u * (unsigned)(t + 1);
            unsigned v;
            do {
                asm volatile("ld.acquire.gpu.global.b32 %0, [%1];"
                             : "=r"(v) : "l"(mybar) : "memory");
                if (v < target) __nanosleep(32);
            } while (v < target);
        }
        __syncthreads();
    }
}

// ---------------- misc -------------------------------------------------------
__global__ void init_kernel(float* h0, unsigned* bar) {
    int i = blockIdx.x * blockDim.x + threadIdx.x;
    if (i < Bn * Hn) h0[i] = 0.f;
    if (i < 4) bar[i] = 0u;
}

__global__ void value_kernel(const float* __restrict__ h2,
                             const float* __restrict__ Wc3,
                             const float* __restrict__ bc3,
                             float* __restrict__ out)
{
    int gw = (blockIdx.x * blockDim.x + threadIdx.x) >> 5;
    int lane = threadIdx.x & 31;
    if (gw >= Bn) return;
    float s = 0.f;
    for (int k = lane; k < Hn; k += 32) s = fmaf(h2[gw * Hn + k], Wc3[k], s);
#pragma unroll
    for (int o = 16; o; o >>= 1) s += __shfl_xor_sync(0xffffffffu, s, o);
    if (lane == 0) out[gw] = s + bc3[0];
}

__global__ void gumbel_kernel(unsigned k0, unsigned k1, float* __restrict__ gout)
{
    unsigned i = blockIdx.x * blockDim.x + threadIdx.x;
    unsigned o0, o1;
    threefry2x32(k0, k1, 0u, i, &o0, &o1);
    unsigned bits = o0 ^ o1;
    float f = __uint_as_float((bits >> 9) | 0x3f800000u) - 1.0f;
    float u = fmaxf(f, 1.17549435e-38f);
    float g = -log_acc(-log_acc(u));
    gout[i] = g;
}

__global__ __launch_bounds__(256)
void sample_kernel(const float* __restrict__ logits,
                   const float* __restrict__ gumbel,
                   float* __restrict__ out_query,
                   float* __restrict__ out_lp)
{
    __shared__ float red[256];
    __shared__ int   redi[256];
    int row = blockIdx.x;
    int tid = threadIdx.x;
    const float* lg = logits + (size_t)row * DICTn;
    const float* gm = gumbel + (size_t)row * DICTn;

    float l[4];
#pragma unroll
    for (int i = 0; i < 4; i++) l[i] = lg[tid + i * 256];

    float mx = fmaxf(fmaxf(l[0], l[1]), fmaxf(l[2], l[3]));
    red[tid] = mx; __syncthreads();
    for (int s = 128; s > 0; s >>= 1) {
        if (tid < s) red[tid] = fmaxf(red[tid], red[tid + s]);
        __syncthreads();
    }
    mx = red[0]; __syncthreads();

    float se = 0.f;
#pragma unroll
    for (int i = 0; i < 4; i++) se += exp_acc(l[i] - mx);
    red[tid] = se; __syncthreads();
    for (int s = 128; s > 0; s >>= 1) {
        if (tid < s) red[tid] += red[tid + s];
        __syncthreads();
    }
    float logZ = mx + log_acc(red[0]); __syncthreads();

    float bv = -1e30f; int bi = 0x7fffffff;
#pragma unroll
    for (int i = 0; i < 4; i++) {
        int idx = tid + i * 256;
        float lp = l[i] - logZ;
        out_lp[(size_t)row * DICTn + idx] = lp;
        float v = lp + gm[idx];
        if (v > bv || (v == bv && idx < bi)) { bv = v; bi = idx; }
    }
    red[tid] = bv; redi[tid] = bi; __syncthreads();
    for (int s = 128; s > 0; s >>= 1) {
        if (tid < s) {
            if (red[tid + s] > red[tid] ||
                (red[tid + s] == red[tid] && redi[tid + s] < redi[tid])) {
                red[tid] = red[tid + s]; redi[tid] = redi[tid + s];
            }
        }
        __syncthreads();
    }
    int win = redi[0];
#pragma unroll
    for (int i = 0; i < 4; i++) {
        int idx = tid + i * 256;
        out_query[(size_t)row * DICTn + idx] = (idx == win) ? 1.f : 0.f;
    }
}

// ---------------- host -------------------------------------------------------
extern "C" void kernel_launch(void* const* d_in, const int* in_sizes, int n_in,
                              void* d_out, int out_size)
{
    const float* x      = (const float*)d_in[0];
    const int*   lens   = (const int*)  d_in[1];
    const float* W_ih   = (const float*)d_in[2];
    const float* W_hh   = (const float*)d_in[3];
    const float* b_ih   = (const float*)d_in[4];
    const float* b_hh   = (const float*)d_in[5];
    const float* W_out  = (const float*)d_in[6];
    const float* b_out  = (const float*)d_in[7];
    const float* Wc1    = (const float*)d_in[8];
    const float* bc1    = (const float*)d_in[9];
    const float* Wc2    = (const float*)d_in[10];
    const float* bc2    = (const float*)d_in[11];
    const float* Wc3    = (const float*)d_in[12];
    const float* bc3    = (const float*)d_in[13];

    float* out_value = (float*)d_out;
    float* out_query = out_value + Bn;
    float* out_lp    = out_query + (size_t)NSAMP;

    float *pGI, *ph0, *pc1, *pc2, *plog, *pgum;
    unsigned* pbar;
    cudaGetSymbolAddress((void**)&pGI,  g_GI);
    cudaGetSymbolAddress((void**)&ph0,  g_h);
    cudaGetSymbolAddress((void**)&pc1,  g_c1);
    cudaGetSymbolAddress((void**)&pc2,  g_c2);
    cudaGetSymbolAddress((void**)&plog, g_logits);
    cudaGetSymbolAddress((void**)&pgum, g_gumbel);
    cudaGetSymbolAddress((void**)&pbar, g_barrier);

    const int rec_smem = WS_WORDS * 8 + 2 * 2048 * 8;   // 229376 B
    cudaFuncSetAttribute(gru_persistent,
        cudaFuncAttributeMaxDynamicSharedMemorySize, rec_smem);

    // 1) zero h0 + barrier counters
    init_kernel<<<(Bn * Hn + 255) / 256, 256>>>(ph0, pbar);

    // 2) GI = x @ W_ih^T + b_ih  (ragged tile skip)
    gemm_f32<<<dim3(H3 / 64, BT / 128), 256>>>(x, Dn, W_ih, Dn, pGI, H3,
                                               Dn, b_ih, 0, lens);

    // 3) persistent recurrence
    gru_persistent<<<NCTA_REC, 384, rec_smem>>>(pGI, W_hh, b_hh, lens,
                                                ph0, pbar);
    float* hfin = ph0;

    // 4) critic
    gemm_f32<<<dim3(Hn / 64, Bn / 128), 256>>>(hfin, Hn, Wc1, Hn, pc1, Hn,
                                               Hn, bc1, 1, nullptr);
    gemm_f32<<<dim3(Hn / 64, Bn / 128), 256>>>(pc1, Hn, Wc2, Hn, pc2, Hn,
                                               Hn, bc2, 1, nullptr);
    value_kernel<<<(Bn * 32 + 255) / 256, 256>>>(pc2, Wc3, bc3, out_value);

    // 5) actor logits
    gemm_f32<<<dim3(DICTn * Qn / 64, Bn / 128), 256>>>(hfin, Hn, W_out, Hn,
                                                       plog, DICTn * Qn,
                                                       Hn, b_out, 0, nullptr);

    // 6) gumbel noise
    unsigned s0, s1;
    threefry2x32(0u, 0u, 0u, 1234u, &s0, &s1);
    gumbel_kernel<<<NSAMP / 256, 256>>>(s0, s1, pgum);

    // 7) log-softmax + categorical sample + one-hot
    sample_kernel<<<Bn * Qn, 256>>>(plog, pgum, out_query, out_lp);
}

// round 8
// speedup vs baseline: 1.1999x; 1.0179x over previous
#include <cuda_runtime.h>
#include <cuda_bf16.h>
#include <math.h>
#include <stdint.h>

#define Bn    256
#define Tn    512
#define Dn    512
#define Hn    512
#define H3    1536
#define DICTn 1024
#define Qn    32
#define BT    (Bn*Tn)
#define NSAMP (Bn*Qn*DICTn)   // 8388608

#define NCTA_REC 128
#define WS_WORDS (48*512)

// ---------------- static device scratch -------------------------------------
__device__ float g_GI[(size_t)BT * H3];
__device__ float g_h[2][Bn * Hn];
__device__ float g_c1[Bn * Hn];
__device__ float g_c2[Bn * Hn];
__device__ float g_logits[(size_t)Bn * Qn * DICTn];
__device__ float g_gumbel[(size_t)NSAMP];
__device__ unsigned g_barrier[4];

// ---------------- threefry2x32-20 (JAX-exact) --------------------------------
__host__ __device__ inline void threefry2x32(unsigned k0, unsigned k1,
                                             unsigned x0, unsigned x1,
                                             unsigned* o0, unsigned* o1) {
    unsigned ks2 = k0 ^ k1 ^ 0x1BD11BDAu;
    x0 += k0; x1 += k1;
#define TF_R(r) { x0 += x1; x1 = (x1 << (r)) | (x1 >> (32-(r))); x1 ^= x0; }
    TF_R(13) TF_R(15) TF_R(26) TF_R(6)   x0 += k1;  x1 += ks2 + 1u;
    TF_R(17) TF_R(29) TF_R(16) TF_R(24)  x0 += ks2; x1 += k0  + 2u;
    TF_R(13) TF_R(15) TF_R(26) TF_R(6)   x0 += k0;  x1 += k1  + 3u;
    TF_R(17) TF_R(29) TF_R(16) TF_R(24)  x0 += k1;  x1 += ks2 + 4u;
    TF_R(13) TF_R(15) TF_R(26) TF_R(6)   x0 += ks2; x1 += k0  + 5u;
#undef TF_R
    *o0 = x0; *o1 = x1;
}

__device__ __forceinline__ unsigned tf32r(float v) {
    unsigned o; asm("cvt.rna.tf32.f32 %0, %1;" : "=r"(o) : "f"(v)); return o;
}
__device__ __forceinline__ uint2 split2(float v) {
    uint2 r;
    r.x = tf32r(v);
    r.y = tf32r(v - __uint_as_float(r.x));
    return r;
}

// ---------------- accurate fp32 exp/log --------------------------------------
__device__ __forceinline__ float exp_acc(float x) {
    x = fminf(fmaxf(x, -80.f), 80.f);
    float n = rintf(x * 1.4426950408889634f);
    float r = fmaf(n, -0.6931471824645996f, x);
    r = fmaf(n, 1.9046542121259063e-9f, r);
    float p = 1.984126984e-4f;
    p = fmaf(p, r, 1.388888889e-3f);
    p = fmaf(p, r, 8.333333333e-3f);
    p = fmaf(p, r, 4.166666667e-2f);
    p = fmaf(p, r, 1.666666667e-1f);
    p = fmaf(p, r, 0.5f);
    p = fmaf(p, r, 1.0f);
    p = fmaf(p, r, 1.0f);
    int ni = (int)n;
    float sc = __int_as_float((ni + 127) << 23);
    return p * sc;
}

__device__ __forceinline__ float log_acc(float x) {
    int xi = __float_as_int(x);
    int e = ((xi >> 23) & 0xff) - 127;
    float m = __int_as_float((xi & 0x7fffff) | 0x3f800000);
    if (m > 1.4142135623730951f) { m *= 0.5f; e += 1; }
    float fe = (float)e;
    float s = __fdiv_rn(m - 1.0f, m + 1.0f);
    float s2 = s * s;
    float p = 0.111111111f;
    p = fmaf(p, s2, 0.142857143f);
    p = fmaf(p, s2, 0.2f);
    p = fmaf(p, s2, 0.333333333f);
    p = p * s2;
    float logm = fmaf(2.0f * s, p, 2.0f * s);
    float res = fmaf(fe, 0.6931471824645996f, logm);
    res = fmaf(fe, -1.9046542121259063e-9f, res);
    return res;
}

__device__ __forceinline__ float sigmoid_acc(float x) {
    return __fdiv_rn(1.0f, 1.0f + exp_acc(-x));
}
__device__ __forceinline__ float tanh_acc(float x) {
    float a = fabsf(x);
    float e = exp_acc(-2.0f * a);
    float t = __fdiv_rn(1.0f - e, 1.0f + e);
    return copysignf(t, x);
}

#define MMA(ACC, A0,A1,A2,A3, B0,B1)                                          \
    asm volatile(                                                             \
        "mma.sync.aligned.m16n8k8.row.col.f32.tf32.tf32.f32 "                 \
        "{%0,%1,%2,%3}, {%4,%5,%6,%7}, {%8,%9}, {%0,%1,%2,%3};\n"             \
        : "+f"(ACC[0]), "+f"(ACC[1]), "+f"(ACC[2]), "+f"(ACC[3])              \
        : "r"(A0), "r"(A1), "r"(A2), "r"(A3), "r"(B0), "r"(B1))

// ---------------- 3xTF32 GEMM (packed hi/lo, term-major MMA order) -----------
// C[M,N] = A[M,K]*B[N,K]^T + bias. 128x64 tile, 8 warps (4x2), warp 32x32.
__global__ __launch_bounds__(256, 2)
void gemm_f32(const float* __restrict__ A, int lda,
              const float* __restrict__ Bm, int ldb,
              float* __restrict__ C, int ldc,
              int K, const float* __restrict__ bias, int relu,
              const int* __restrict__ row_lens)
{
    __shared__ uint2 As2[128][32];
    __shared__ uint2 Bs2[64][32];

    const int tid  = threadIdx.x;
    const int warp = tid >> 5, lane = tid & 31;
    const int g    = lane >> 2, tig = lane & 3;
    const int m0   = blockIdx.y * 128, n0 = blockIdx.x * 64;
    const int wm   = (warp >> 1) * 32, wn = (warp & 1) * 32;

    if (row_lens) {
        int b = m0 >> 9;
        int ts = m0 & 511;
        if (ts >= row_lens[b]) return;
    }

    float acc[2][4][4];
#pragma unroll
    for (int mi = 0; mi < 2; mi++)
#pragma unroll
        for (int ni = 0; ni < 4; ni++)
#pragma unroll
            for (int r = 0; r < 4; r++) acc[mi][ni][r] = 0.f;

    float ra[16], rb[8];
#pragma unroll
    for (int i = 0; i < 16; i++) {
        int idx = tid + i * 256; int m = idx >> 5, k = idx & 31;
        ra[i] = A[(size_t)(m0 + m) * lda + k];
    }
#pragma unroll
    for (int i = 0; i < 8; i++) {
        int idx = tid + i * 256; int n = idx >> 5, k = idx & 31;
        rb[i] = Bm[(size_t)(n0 + n) * ldb + k];
    }

    const int nchunk = K >> 5;
    for (int ch = 0; ch < nchunk; ch++) {
#pragma unroll
        for (int i = 0; i < 16; i++) {
            int idx = tid + i * 256; int m = idx >> 5;
            int k = (idx & 31) ^ ((m & 7) << 2);
            As2[m][k] = split2(ra[i]);
        }
#pragma unroll
        for (int i = 0; i < 8; i++) {
            int idx = tid + i * 256; int n = idx >> 5;
            int k = (idx & 31) ^ ((n & 7) << 2);
            Bs2[n][k] = split2(rb[i]);
        }
        __syncthreads();

        if (ch + 1 < nchunk) {
            int k0 = (ch + 1) << 5;
#pragma unroll
            for (int i = 0; i < 16; i++) {
                int idx = tid + i * 256; int m = idx >> 5, k = idx & 31;
                ra[i] = A[(size_t)(m0 + m) * lda + k0 + k];
            }
#pragma unroll
            for (int i = 0; i < 8; i++) {
                int idx = tid + i * 256; int n = idx >> 5, k = idx & 31;
                rb[i] = Bm[(size_t)(n0 + n) * ldb + k0 + k];
            }
        }

#pragma unroll
        for (int kk = 0; kk < 32; kk += 8) {
            int c0k = (kk + tig) ^ (g << 2), c1k = (kk + tig + 4) ^ (g << 2);
            uint2 a[2][4];
#pragma unroll
            for (int mi = 0; mi < 2; mi++) {
                int r0 = wm + mi * 16;
                a[mi][0] = As2[r0 + g    ][c0k];
                a[mi][1] = As2[r0 + g + 8][c0k];
                a[mi][2] = As2[r0 + g    ][c1k];
                a[mi][3] = As2[r0 + g + 8][c1k];
            }
            uint2 b[4][2];
#pragma unroll
            for (int ni = 0; ni < 4; ni++) {
                int nrow = wn + ni * 8 + g;
                b[ni][0] = Bs2[nrow][c0k];
                b[ni][1] = Bs2[nrow][c1k];
            }
            // term-major: dependent same-acc MMAs are 8 issues apart
#pragma unroll
            for (int mi = 0; mi < 2; mi++)
#pragma unroll
                for (int ni = 0; ni < 4; ni++)
                    MMA(acc[mi][ni], a[mi][0].x,a[mi][1].x,a[mi][2].x,a[mi][3].x,
                        b[ni][0].y, b[ni][1].y);
#pragma unroll
            for (int mi = 0; mi < 2; mi++)
#pragma unroll
                for (int ni = 0; ni < 4; ni++)
                    MMA(acc[mi][ni], a[mi][0].y,a[mi][1].y,a[mi][2].y,a[mi][3].y,
                        b[ni][0].x, b[ni][1].x);
#pragma unroll
            for (int mi = 0; mi < 2; mi++)
#pragma unroll
                for (int ni = 0; ni < 4; ni++)
                    MMA(acc[mi][ni], a[mi][0].x,a[mi][1].x,a[mi][2].x,a[mi][3].x,
                        b[ni][0].x, b[ni][1].x);
        }
        __syncthreads();
    }

#pragma unroll
    for (int mi = 0; mi < 2; mi++)
#pragma unroll
        for (int ni = 0; ni < 4; ni++) {
            int r = m0 + wm + mi * 16 + g;
            int c = n0 + wn + ni * 8 + tig * 2;
            float b0 = bias ? bias[c]     : 0.f;
            float b1 = bias ? bias[c + 1] : 0.f;
            float v0 = acc[mi][ni][0] + b0;
            float v1 = acc[mi][ni][1] + b1;
            float v2 = acc[mi][ni][2] + b0;
            float v3 = acc[mi][ni][3] + b1;
            if (relu) { v0 = fmaxf(v0, 0.f); v1 = fmaxf(v1, 0.f);
                        v2 = fmaxf(v2, 0.f); v3 = fmaxf(v3, 0.f); }
            C[(size_t)r * ldc + c]           = v0;
            C[(size_t)r * ldc + c + 1]       = v1;
            C[(size_t)(r + 8) * ldc + c]     = v2;
            C[(size_t)(r + 8) * ldc + c + 1] = v3;
        }
}

// ---------------- persistent GRU recurrence (v4: 6 indep MMA chains) ---------
__global__ __launch_bounds__(384, 1)
void gru_persistent(const float* __restrict__ GI,
                    const float* __restrict__ W_hh,
                    const float* __restrict__ b_hh,
                    const int*   __restrict__ lengths,
                    float* __restrict__ hbase,
                    unsigned* __restrict__ bar)
{
    extern __shared__ uint2 smem2[];
    uint2* Ws2 = smem2;                      // 48*512 uint2 = 196608 B
    uint2* Ab2 = smem2 + WS_WORDS;           // 2 stages x 2048 uint2 = 32768 B
    float* gh_s = (float*)(smem2 + WS_WORDS);

    const int tid  = threadIdx.x;
    const int warp = tid >> 5, lane = tid & 31;
    const int g    = lane >> 2, tig = lane & 3;
    const int cgp  = blockIdx.x & 31;
    const int bg   = blockIdx.x >> 5;
    const int m0   = bg * 64;
    const int jj0  = cgp * 16;
    const int wm   = (warp & 3) * 16;
    const int wn   = (warp >> 2) * 16;
    unsigned* mybar = bar + bg;
    const bool loader = (tid < 256);

    // one-time W slice preload (packed)
    for (int i = tid; i < WS_WORDS; i += 384) {
        int n = i >> 9, k = i & 511;
        int wrow = (n >> 4) * Hn + jj0 + (n & 15);
        float w = W_hh[(size_t)wrow * Hn + k];
        int off = (n << 9) + (k & ~31) + ((k & 31) ^ ((n & 7) << 2));
        Ws2[off] = split2(w);
    }
    __syncthreads();

    // GI prefetch registers (up to 3 elems/thread)
    float p_r[3], p_z[3], p_n[3];
    {
        int idx = 0;
        for (int e = tid; e < 1024; e += 384, idx++) {
            int row = e >> 4, col = e & 15;
            const float* gi = GI + ((size_t)(m0 + row) * Tn + 0) * H3 + jj0 + col;
            p_r[idx] = gi[0];
            p_z[idx] = gi[Hn];
            p_n[idx] = gi[2 * Hn];
        }
    }

    for (int t = 0; t < Tn; t++) {
        const float* h_in  = hbase + (t & 1) * (Bn * Hn);
        float*       h_out = hbase + ((t + 1) & 1) * (Bn * Hn);

        // 6 independent accumulator chains: P = ah*bh, Q = ah*bl, R = al*bh
        float accP[2][4], accQ[2][4], accR[2][4];
#pragma unroll
        for (int ni = 0; ni < 2; ni++)
#pragma unroll
            for (int r = 0; r < 4; r++) {
                accP[ni][r] = 0.f; accQ[ni][r] = 0.f; accR[ni][r] = 0.f;
            }

        float ra[8];
        if (loader) {
#pragma unroll
            for (int i = 0; i < 8; i++) {
                int idx = tid + i * 256; int m = idx >> 5, k = idx & 31;
                ra[i] = h_in[(m0 + m) * Hn + k];
            }
#pragma unroll
            for (int i = 0; i < 8; i++) {
                int idx = tid + i * 256; int m = idx >> 5;
                int off = (m << 5) + ((idx & 31) ^ ((m & 7) << 2));
                Ab2[off] = split2(ra[i]);
            }
        }
        __syncthreads();

        for (int ch = 0; ch < 16; ch++) {
            if (loader && ch < 15) {
                int k0 = (ch + 1) << 5;
#pragma unroll
                for (int i = 0; i < 8; i++) {
                    int idx = tid + i * 256; int m = idx >> 5, k = idx & 31;
                    ra[i] = h_in[(m0 + m) * Hn + k0 + k];
                }
            }
            const uint2* Ah = Ab2 + (ch & 1) * 2048;
            const int choff = ch << 5;
#pragma unroll
            for (int kk = 0; kk < 32; kk += 8) {
                int c0k = (kk + tig) ^ (g << 2);
                int c1k = (kk + tig + 4) ^ (g << 2);
                uint2 a0 = Ah[((wm + g    ) << 5) + c0k];
                uint2 a1 = Ah[((wm + g + 8) << 5) + c0k];
                uint2 a2 = Ah[((wm + g    ) << 5) + c1k];
                uint2 a3 = Ah[((wm + g + 8) << 5) + c1k];
                uint2 b0[2], b1[2];
#pragma unroll
                for (int ni = 0; ni < 2; ni++) {
                    int base = ((wn + ni * 8 + g) << 9) + choff;
                    b0[ni] = Ws2[base + c0k];
                    b1[ni] = Ws2[base + c1k];
                }
                // 6 independent chains, same-chain distance = 6 issues
#pragma unroll
                for (int ni = 0; ni < 2; ni++)
                    MMA(accQ[ni], a0.x, a1.x, a2.x, a3.x, b0[ni].y, b1[ni].y);
#pragma unroll
                for (int ni = 0; ni < 2; ni++)
                    MMA(accR[ni], a0.y, a1.y, a2.y, a3.y, b0[ni].x, b1[ni].x);
#pragma unroll
                for (int ni = 0; ni < 2; ni++)
                    MMA(accP[ni], a0.x, a1.x, a2.x, a3.x, b0[ni].x, b1[ni].x);
            }
            if (loader && ch < 15) {
                uint2* Dst = Ab2 + ((ch + 1) & 1) * 2048;
#pragma unroll
                for (int i = 0; i < 8; i++) {
                    int idx = tid + i * 256; int m = idx >> 5;
                    int off = (m << 5) + ((idx & 31) ^ ((m & 7) << 2));
                    Dst[off] = split2(ra[i]);
                }
            }
            __syncthreads();
        }

        // stage gh tile (64x48)
#pragma unroll
        for (int ni = 0; ni < 2; ni++) {
            int r = wm + g;
            int c = wn + ni * 8 + tig * 2;
            gh_s[r * 48 + c]           = accP[ni][0] + accQ[ni][0] + accR[ni][0];
            gh_s[r * 48 + c + 1]       = accP[ni][1] + accQ[ni][1] + accR[ni][1];
            gh_s[(r + 8) * 48 + c]     = accP[ni][2] + accQ[ni][2] + accR[ni][2];
            gh_s[(r + 8) * 48 + c + 1] = accP[ni][3] + accQ[ni][3] + accR[ni][3];
        }
        __syncthreads();

        // gate math with prefetched GI
        {
            int idx = 0;
            for (int e = tid; e < 1024; e += 384, idx++) {
                int row = e >> 4, col = e & 15;
                int b = m0 + row, jj = jj0 + col;
                float ghr = gh_s[row * 48 + col]      + b_hh[jj];
                float ghz = gh_s[row * 48 + 16 + col] + b_hh[Hn + jj];
                float ghn = gh_s[row * 48 + 32 + col] + b_hh[2 * Hn + jj];
                float r = sigmoid_acc(p_r[idx] + ghr);
                float z = sigmoid_acc(p_z[idx] + ghz);
                float n = tanh_acc(fmaf(r, ghn, p_n[idx]));
                float ho = h_in[b * Hn + jj];
                float hv = (t < lengths[b]) ? ((1.f - z) * n + z * ho) : ho;
                h_out[b * Hn + jj] = hv;
            }
        }

        // per-batch-group barrier (32 CTAs) + GI prefetch for t+1 during wait
        __syncthreads();
        if (tid == 0) {
            __threadfence();
            atomicAdd(mybar, 1u);
        }
        if (t + 1 < Tn) {
            int idx = 0;
            for (int e = tid; e < 1024; e += 384, idx++) {
                int row = e >> 4, col = e & 15;
                const float* gi = GI + ((size_t)(m0 + row) * Tn + (t + 1)) * H3 + jj0 + col;
                p_r[idx] = gi[0];
                p_z[idx] = gi[Hn];
                p_n[idx] = gi[2 * Hn];
            }
        }
        if (tid == 0) {
            unsigned target = 32u * (unsigned)(t + 1);
            unsigned v;
            do {
                asm volatile("ld.acquire.gpu.global.b32 %0, [%1];"
                             : "=r"(v) : "l"(mybar) : "memory");
                if (v < target) __nanosleep(32);
            } while (v < target);
        }
        __syncthreads();
    }
}

// ---------------- misc -------------------------------------------------------
__global__ void init_kernel(float* h0, unsigned* bar) {
    int i = blockIdx.x * blockDim.x + threadIdx.x;
    if (i < Bn * Hn) h0[i] = 0.f;
    if (i < 4) bar[i] = 0u;
}

__global__ void value_kernel(const float* __restrict__ h2,
                             const float* __restrict__ Wc3,
                             const float* __restrict__ bc3,
                             float* __restrict__ out)
{
    int gw = (blockIdx.x * blockDim.x + threadIdx.x) >> 5;
    int lane = threadIdx.x & 31;
    if (gw >= Bn) return;
    float s = 0.f;
    for (int k = lane; k < Hn; k += 32) s = fmaf(h2[gw * Hn + k], Wc3[k], s);
#pragma unroll
    for (int o = 16; o; o >>= 1) s += __shfl_xor_sync(0xffffffffu, s, o);
    if (lane == 0) out[gw] = s + bc3[0];
}

__global__ void gumbel_kernel(unsigned k0, unsigned k1, float* __restrict__ gout)
{
    unsigned i = blockIdx.x * blockDim.x + threadIdx.x;
    unsigned o0, o1;
    threefry2x32(k0, k1, 0u, i, &o0, &o1);
    unsigned bits = o0 ^ o1;
    float f = __uint_as_float((bits >> 9) | 0x3f800000u) - 1.0f;
    float u = fmaxf(f, 1.17549435e-38f);
    float g = -log_acc(-log_acc(u));
    gout[i] = g;
}

__global__ __launch_bounds__(256)
void sample_kernel(const float* __restrict__ logits,
                   const float* __restrict__ gumbel,
                   float* __restrict__ out_query,
                   float* __restrict__ out_lp)
{
    __shared__ float red[256];
    __shared__ int   redi[256];
    int row = blockIdx.x;
    int tid = threadIdx.x;
    const float* lg = logits + (size_t)row * DICTn;
    const float* gm = gumbel + (size_t)row * DICTn;

    float l[4];
#pragma unroll
    for (int i = 0; i < 4; i++) l[i] = lg[tid + i * 256];

    float mx = fmaxf(fmaxf(l[0], l[1]), fmaxf(l[2], l[3]));
    red[tid] = mx; __syncthreads();
    for (int s = 128; s > 0; s >>= 1) {
        if (tid < s) red[tid] = fmaxf(red[tid], red[tid + s]);
        __syncthreads();
    }
    mx = red[0]; __syncthreads();

    float se = 0.f;
#pragma unroll
    for (int i = 0; i < 4; i++) se += exp_acc(l[i] - mx);
    red[tid] = se; __syncthreads();
    for (int s = 128; s > 0; s >>= 1) {
        if (tid < s) red[tid] += red[tid + s];
        __syncthreads();
    }
    float logZ = mx + log_acc(red[0]); __syncthreads();

    float bv = -1e30f; int bi = 0x7fffffff;
#pragma unroll
    for (int i = 0; i < 4; i++) {
        int idx = tid + i * 256;
        float lp = l[i] - logZ;
        out_lp[(size_t)row * DICTn + idx] = lp;
        float v = lp + gm[idx];
        if (v > bv || (v == bv && idx < bi)) { bv = v; bi = idx; }
    }
    red[tid] = bv; redi[tid] = bi; __syncthreads();
    for (int s = 128; s > 0; s >>= 1) {
        if (tid < s) {
            if (red[tid + s] > red[tid] ||
                (red[tid + s] == red[tid] && redi[tid + s] < redi[tid])) {
                red[tid] = red[tid + s]; redi[tid] = redi[tid + s];
            }
        }
        __syncthreads();
    }
    int win = redi[0];
#pragma unroll
    for (int i = 0; i < 4; i++) {
        int idx = tid + i * 256;
        out_query[(size_t)row * DICTn + idx] = (idx == win) ? 1.f : 0.f;
    }
}

// ---------------- host -------------------------------------------------------
extern "C" void kernel_launch(void* const* d_in, const int* in_sizes, int n_in,
                              void* d_out, int out_size)
{
    const float* x      = (const float*)d_in[0];
    const int*   lens   = (const int*)  d_in[1];
    const float* W_ih   = (const float*)d_in[2];
    const float* W_hh   = (const float*)d_in[3];
    const float* b_ih   = (const float*)d_in[4];
    const float* b_hh   = (const float*)d_in[5];
    const float* W_out  = (const float*)d_in[6];
    const float* b_out  = (const float*)d_in[7];
    const float* Wc1    = (const float*)d_in[8];
    const float* bc1    = (const float*)d_in[9];
    const float* Wc2    = (const float*)d_in[10];
    const float* bc2    = (const float*)d_in[11];
    const float* Wc3    = (const float*)d_in[12];
    const float* bc3    = (const float*)d_in[13];

    float* out_value = (float*)d_out;
    float* out_query = out_value + Bn;
    float* out_lp    = out_query + (size_t)NSAMP;

    float *pGI, *ph0, *pc1, *pc2, *plog, *pgum;
    unsigned* pbar;
    cudaGetSymbolAddress((void**)&pGI,  g_GI);
    cudaGetSymbolAddress((void**)&ph0,  g_h);
    cudaGetSymbolAddress((void**)&pc1,  g_c1);
    cudaGetSymbolAddress((void**)&pc2,  g_c2);
    cudaGetSymbolAddress((void**)&plog, g_logits);
    cudaGetSymbolAddress((void**)&pgum, g_gumbel);
    cudaGetSymbolAddress((void**)&pbar, g_barrier);

    const int rec_smem = WS_WORDS * 8 + 2 * 2048 * 8;   // 229376 B
    cudaFuncSetAttribute(gru_persistent,
        cudaFuncAttributeMaxDynamicSharedMemorySize, rec_smem);

    // 1) zero h0 + barrier counters
    init_kernel<<<(Bn * Hn + 255) / 256, 256>>>(ph0, pbar);

    // 2) GI = x @ W_ih^T + b_ih  (ragged tile skip)
    gemm_f32<<<dim3(H3 / 64, BT / 128), 256>>>(x, Dn, W_ih, Dn, pGI, H3,
                                               Dn, b_ih, 0, lens);

    // 3) persistent recurrence
    gru_persistent<<<NCTA_REC, 384, rec_smem>>>(pGI, W_hh, b_hh, lens,
                                                ph0, pbar);
    float* hfin = ph0;

    // 4) critic
    gemm_f32<<<dim3(Hn / 64, Bn / 128), 256>>>(hfin, Hn, Wc1, Hn, pc1, Hn,
                                               Hn, bc1, 1, nullptr);
    gemm_f32<<<dim3(Hn / 64, Bn / 128), 256>>>(pc1, Hn, Wc2, Hn, pc2, Hn,
                                               Hn, bc2, 1, nullptr);
    value_kernel<<<(Bn * 32 + 255) / 256, 256>>>(pc2, Wc3, bc3, out_value);

    // 5) actor logits
    gemm_f32<<<dim3(DICTn * Qn / 64, Bn / 128), 256>>>(hfin, Hn, W_out, Hn,
                                                       plog, DICTn * Qn,
                                                       Hn, b_out, 0, nullptr);

    // 6) gumbel noise
    unsigned s0, s1;
    threefry2x32(0u, 0u, 0u, 1234u, &s0, &s1);
    gumbel_kernel<<<NSAMP / 256, 256>>>(s0, s1, pgum);

    // 7) log-softmax + categorical sample + one-hot
    sample_kernel<<<Bn * Qn, 256>>>(plog, pgum, out_query, out_lp);
}

// round 9
// speedup vs baseline: 1.6330x; 1.3610x over previous
#include <cuda_runtime.h>
#include <cuda_fp16.h>
#include <math.h>
#include <stdint.h>

#define Bn    256
#define Tn    512
#define Dn    512
#define Hn    512
#define H3    1536
#define DICTn 1024
#define Qn    32
#define BT    (Bn*Tn)
#define NSAMP (Bn*Qn*DICTn)   // 8388608

#define NCTA_REC 128
#define WS_UNITS (48*256)     // W slice in uint2 units (packed k-pairs)
#define INV2048  4.8828125e-4f

// ---------------- static device scratch -------------------------------------
__device__ float g_GI[(size_t)BT * H3];
__device__ float g_h[2][Bn * Hn];
__device__ float g_c1[Bn * Hn];
__device__ float g_c2[Bn * Hn];
__device__ float g_logits[(size_t)Bn * Qn * DICTn];
__device__ float g_gumbel[(size_t)NSAMP];
__device__ unsigned g_barrier[4];

// ---------------- threefry2x32-20 (JAX-exact) --------------------------------
__host__ __device__ inline void threefry2x32(unsigned k0, unsigned k1,
                                             unsigned x0, unsigned x1,
                                             unsigned* o0, unsigned* o1) {
    unsigned ks2 = k0 ^ k1 ^ 0x1BD11BDAu;
    x0 += k0; x1 += k1;
#define TF_R(r) { x0 += x1; x1 = (x1 << (r)) | (x1 >> (32-(r))); x1 ^= x0; }
    TF_R(13) TF_R(15) TF_R(26) TF_R(6)   x0 += k1;  x1 += ks2 + 1u;
    TF_R(17) TF_R(29) TF_R(16) TF_R(24)  x0 += ks2; x1 += k0  + 2u;
    TF_R(13) TF_R(15) TF_R(26) TF_R(6)   x0 += k0;  x1 += k1  + 3u;
    TF_R(17) TF_R(29) TF_R(16) TF_R(24)  x0 += k1;  x1 += ks2 + 4u;
    TF_R(13) TF_R(15) TF_R(26) TF_R(6)   x0 += ks2; x1 += k0  + 5u;
#undef TF_R
    *o0 = x0; *o1 = x1;
}

// fp16x3 split: pack 2 consecutive k. .x = hi pair, .y = lo pair scaled x2048.
__device__ __forceinline__ uint2 splitpk(float2 v) {
    __half hx = __float2half_rn(v.x);
    __half hy = __float2half_rn(v.y);
    float rx = (v.x - __half2float(hx)) * 2048.0f;
    float ry = (v.y - __half2float(hy)) * 2048.0f;
    __half lx = __float2half_rn(rx);
    __half ly = __float2half_rn(ry);
    uint2 r;
    r.x = (unsigned)__half_as_ushort(hx) | ((unsigned)__half_as_ushort(hy) << 16);
    r.y = (unsigned)__half_as_ushort(lx) | ((unsigned)__half_as_ushort(ly) << 16);
    return r;
}

// ---------------- accurate fp32 exp/log --------------------------------------
__device__ __forceinline__ float exp_acc(float x) {
    x = fminf(fmaxf(x, -80.f), 80.f);
    float n = rintf(x * 1.4426950408889634f);
    float r = fmaf(n, -0.6931471824645996f, x);
    r = fmaf(n, 1.9046542121259063e-9f, r);
    float p = 1.984126984e-4f;
    p = fmaf(p, r, 1.388888889e-3f);
    p = fmaf(p, r, 8.333333333e-3f);
    p = fmaf(p, r, 4.166666667e-2f);
    p = fmaf(p, r, 1.666666667e-1f);
    p = fmaf(p, r, 0.5f);
    p = fmaf(p, r, 1.0f);
    p = fmaf(p, r, 1.0f);
    int ni = (int)n;
    float sc = __int_as_float((ni + 127) << 23);
    return p * sc;
}

__device__ __forceinline__ float log_acc(float x) {
    int xi = __float_as_int(x);
    int e = ((xi >> 23) & 0xff) - 127;
    float m = __int_as_float((xi & 0x7fffff) | 0x3f800000);
    if (m > 1.4142135623730951f) { m *= 0.5f; e += 1; }
    float fe = (float)e;
    float s = __fdiv_rn(m - 1.0f, m + 1.0f);
    float s2 = s * s;
    float p = 0.111111111f;
    p = fmaf(p, s2, 0.142857143f);
    p = fmaf(p, s2, 0.2f);
    p = fmaf(p, s2, 0.333333333f);
    p = p * s2;
    float logm = fmaf(2.0f * s, p, 2.0f * s);
    float res = fmaf(fe, 0.6931471824645996f, logm);
    res = fmaf(fe, -1.9046542121259063e-9f, res);
    return res;
}

__device__ __forceinline__ float sigmoid_acc(float x) {
    return __fdiv_rn(1.0f, 1.0f + exp_acc(-x));
}
__device__ __forceinline__ float tanh_acc(float x) {
    float a = fabsf(x);
    float e = exp_acc(-2.0f * a);
    float t = __fdiv_rn(1.0f - e, 1.0f + e);
    return copysignf(t, x);
}

#define MMA16(ACC, A0,A1,A2,A3, B0,B1)                                        \
    asm volatile(                                                             \
        "mma.sync.aligned.m16n8k16.row.col.f32.f16.f16.f32 "                  \
        "{%0,%1,%2,%3}, {%4,%5,%6,%7}, {%8,%9}, {%0,%1,%2,%3};\n"             \
        : "+f"(ACC[0]), "+f"(ACC[1]), "+f"(ACC[2]), "+f"(ACC[3])              \
        : "r"(A0), "r"(A1), "r"(A2), "r"(A3), "r"(B0), "r"(B1))

// ---------------- fp16x3 GEMM: C[M,N] = A[M,K]*B[N,K]^T + bias ---------------
// 128x64 tile, 8 warps (4x2), warp 32x32. accH = hi*hi, accC = scaled cross.
__global__ __launch_bounds__(256)
void gemm_f32(const float* __restrict__ A, int lda,
              const float* __restrict__ Bm, int ldb,
              float* __restrict__ C, int ldc,
              int K, const float* __restrict__ bias, int relu,
              const int* __restrict__ row_lens)
{
    __shared__ uint2 As2[128][16];
    __shared__ uint2 Bs2[64][16];

    const int tid  = threadIdx.x;
    const int warp = tid >> 5, lane = tid & 31;
    const int g    = lane >> 2, tig = lane & 3;
    const int m0   = blockIdx.y * 128, n0 = blockIdx.x * 64;
    const int wm   = (warp >> 1) * 32, wn = (warp & 1) * 32;
    const int swz  = (g & 3) << 2;

    if (row_lens) {
        int b = m0 >> 9;
        int ts = m0 & 511;
        if (ts >= row_lens[b]) return;
    }

    float accH[2][4][4], accC[2][4][4];
#pragma unroll
    for (int mi = 0; mi < 2; mi++)
#pragma unroll
        for (int ni = 0; ni < 4; ni++)
#pragma unroll
            for (int r = 0; r < 4; r++) { accH[mi][ni][r] = 0.f; accC[mi][ni][r] = 0.f; }

    float2 ra2[8], rb2[4];
#pragma unroll
    for (int i = 0; i < 8; i++) {
        int idx = tid + i * 256; int m = idx >> 4, kp = idx & 15;
        ra2[i] = *(const float2*)(A + (size_t)(m0 + m) * lda + kp * 2);
    }
#pragma unroll
    for (int i = 0; i < 4; i++) {
        int idx = tid + i * 256; int n = idx >> 4, kp = idx & 15;
        rb2[i] = *(const float2*)(Bm + (size_t)(n0 + n) * ldb + kp * 2);
    }

    const int nchunk = K >> 5;
    for (int ch = 0; ch < nchunk; ch++) {
#pragma unroll
        for (int i = 0; i < 8; i++) {
            int idx = tid + i * 256; int m = idx >> 4, kp = idx & 15;
            As2[m][kp ^ ((m & 3) << 2)] = splitpk(ra2[i]);
        }
#pragma unroll
        for (int i = 0; i < 4; i++) {
            int idx = tid + i * 256; int n = idx >> 4, kp = idx & 15;
            Bs2[n][kp ^ ((n & 3) << 2)] = splitpk(rb2[i]);
        }
        __syncthreads();

        if (ch + 1 < nchunk) {
            int k0 = (ch + 1) << 5;
#pragma unroll
            for (int i = 0; i < 8; i++) {
                int idx = tid + i * 256; int m = idx >> 4, kp = idx & 15;
                ra2[i] = *(const float2*)(A + (size_t)(m0 + m) * lda + k0 + kp * 2);
            }
#pragma unroll
            for (int i = 0; i < 4; i++) {
                int idx = tid + i * 256; int n = idx >> 4, kp = idx & 15;
                rb2[i] = *(const float2*)(Bm + (size_t)(n0 + n) * ldb + k0 + kp * 2);
            }
        }

#pragma unroll
        for (int sub = 0; sub < 2; sub++) {
            int i0 = ((sub << 3) + tig)     ^ swz;
            int i1 = ((sub << 3) + tig + 4) ^ swz;
            uint2 a[2][4];
#pragma unroll
            for (int mi = 0; mi < 2; mi++) {
                int r0 = wm + mi * 16;
                a[mi][0] = As2[r0 + g    ][i0];
                a[mi][1] = As2[r0 + g + 8][i0];
                a[mi][2] = As2[r0 + g    ][i1];
                a[mi][3] = As2[r0 + g + 8][i1];
            }
            uint2 b[4][2];
#pragma unroll
            for (int ni = 0; ni < 4; ni++) {
                int nrow = wn + ni * 8 + g;
                b[ni][0] = Bs2[nrow][i0];
                b[ni][1] = Bs2[nrow][i1];
            }
            // cross terms (scaled) then hi*hi; same-acc distance = 8 issues
#pragma unroll
            for (int mi = 0; mi < 2; mi++)
#pragma unroll
                for (int ni = 0; ni < 4; ni++)
                    MMA16(accC[mi][ni], a[mi][0].x,a[mi][1].x,a[mi][2].x,a[mi][3].x,
                          b[ni][0].y, b[ni][1].y);
#pragma unroll
            for (int mi = 0; mi < 2; mi++)
#pragma unroll
                for (int ni = 0; ni < 4; ni++)
                    MMA16(accC[mi][ni], a[mi][0].y,a[mi][1].y,a[mi][2].y,a[mi][3].y,
                          b[ni][0].x, b[ni][1].x);
#pragma unroll
            for (int mi = 0; mi < 2; mi++)
#pragma unroll
                for (int ni = 0; ni < 4; ni++)
                    MMA16(accH[mi][ni], a[mi][0].x,a[mi][1].x,a[mi][2].x,a[mi][3].x,
                          b[ni][0].x, b[ni][1].x);
        }
        __syncthreads();
    }

#pragma unroll
    for (int mi = 0; mi < 2; mi++)
#pragma unroll
        for (int ni = 0; ni < 4; ni++) {
            int r = m0 + wm + mi * 16 + g;
            int c = n0 + wn + ni * 8 + tig * 2;
            float b0 = bias ? bias[c]     : 0.f;
            float b1 = bias ? bias[c + 1] : 0.f;
            float v0 = fmaf(accC[mi][ni][0], INV2048, accH[mi][ni][0]) + b0;
            float v1 = fmaf(accC[mi][ni][1], INV2048, accH[mi][ni][1]) + b1;
            float v2 = fmaf(accC[mi][ni][2], INV2048, accH[mi][ni][2]) + b0;
            float v3 = fmaf(accC[mi][ni][3], INV2048, accH[mi][ni][3]) + b1;
            if (relu) { v0 = fmaxf(v0, 0.f); v1 = fmaxf(v1, 0.f);
                        v2 = fmaxf(v2, 0.f); v3 = fmaxf(v3, 0.f); }
            C[(size_t)r * ldc + c]           = v0;
            C[(size_t)r * ldc + c + 1]       = v1;
            C[(size_t)(r + 8) * ldc + c]     = v2;
            C[(size_t)(r + 8) * ldc + c + 1] = v3;
        }
}

// ---------------- persistent GRU recurrence (fp16x3) -------------------------
// 128 CTAs = 4 batch-groups(64 rows, own barrier) x 32 col-groups(16 cols).
// 384 threads = 12 warps (4m x 3n). W slice packed fp16 hi/lo in SMEM (96KB).
__global__ __launch_bounds__(384, 1)
void gru_persistent(const float* __restrict__ GI,
                    const float* __restrict__ W_hh,
                    const float* __restrict__ b_hh,
                    const int*   __restrict__ lengths,
                    float* __restrict__ hbase,
                    unsigned* __restrict__ bar)
{
    extern __shared__ uint2 smem2[];
    uint2* Ws2 = smem2;                      // 48*256 uint2 = 98304 B
    uint2* Ab2 = smem2 + WS_UNITS;           // 2 stages x 1024 uint2 = 16384 B
    float* gh_s = (float*)(smem2 + WS_UNITS);

    const int tid  = threadIdx.x;
    const int warp = tid >> 5, lane = tid & 31;
    const int g    = lane >> 2, tig = lane & 3;
    const int swz  = (g & 3) << 2;
    const int cgp  = blockIdx.x & 31;
    const int bg   = blockIdx.x >> 5;
    const int m0   = bg * 64;
    const int jj0  = cgp * 16;
    const int wm   = (warp & 3) * 16;
    const int wn   = (warp >> 2) * 16;
    unsigned* mybar = bar + bg;
    const bool loader = (tid < 256);

    // one-time W slice preload: row n = gate*16 + c  ->  W_hh[gate*512+jj0+c]
    for (int i = tid; i < WS_UNITS; i += 384) {
        int n = i >> 8, kp = i & 255;
        int wrow = (n >> 4) * Hn + jj0 + (n & 15);
        float2 w = *(const float2*)(W_hh + (size_t)wrow * Hn + kp * 2);
        int off = (n << 8) + (kp & ~15) + ((kp & 15) ^ ((n & 3) << 2));
        Ws2[off] = splitpk(w);
    }
    __syncthreads();

    // GI prefetch registers (up to 3 elems/thread)
    float p_r[3], p_z[3], p_n[3];
    {
        int idx = 0;
        for (int e = tid; e < 1024; e += 384, idx++) {
            int row = e >> 4, col = e & 15;
            const float* gi = GI + ((size_t)(m0 + row) * Tn + 0) * H3 + jj0 + col;
            p_r[idx] = gi[0];
            p_z[idx] = gi[Hn];
            p_n[idx] = gi[2 * Hn];
        }
    }

    for (int t = 0; t < Tn; t++) {
        const float* h_in  = hbase + (t & 1) * (Bn * Hn);
        float*       h_out = hbase + ((t + 1) & 1) * (Bn * Hn);

        float accP[2][4], accQ[2][4], accR[2][4];
#pragma unroll
        for (int ni = 0; ni < 2; ni++)
#pragma unroll
            for (int r = 0; r < 4; r++) {
                accP[ni][r] = 0.f; accQ[ni][r] = 0.f; accR[ni][r] = 0.f;
            }

        float2 raw2[4];
        if (loader) {
#pragma unroll
            for (int i = 0; i < 4; i++) {
                int idx = tid + i * 256; int m = idx >> 4, kp = idx & 15;
                raw2[i] = *(const float2*)(h_in + (size_t)(m0 + m) * Hn + kp * 2);
            }
#pragma unroll
            for (int i = 0; i < 4; i++) {
                int idx = tid + i * 256; int m = idx >> 4, kp = idx & 15;
                Ab2[(m << 4) + (kp ^ ((m & 3) << 2))] = splitpk(raw2[i]);
            }
        }
        __syncthreads();

        for (int ch = 0; ch < 16; ch++) {
            if (loader && ch < 15) {
                int k0 = (ch + 1) << 5;
#pragma unroll
                for (int i = 0; i < 4; i++) {
                    int idx = tid + i * 256; int m = idx >> 4, kp = idx & 15;
                    raw2[i] = *(const float2*)(h_in + (size_t)(m0 + m) * Hn + k0 + kp * 2);
                }
            }
            const uint2* Ah = Ab2 + (ch & 1) * 1024;
            const int chbase = ch << 4;
#pragma unroll
            for (int sub = 0; sub < 2; sub++) {
                int i0 = ((sub << 3) + tig)     ^ swz;
                int i1 = ((sub << 3) + tig + 4) ^ swz;
                uint2 a0 = Ah[((wm + g)     << 4) + i0];
                uint2 a1 = Ah[((wm + g + 8) << 4) + i0];
                uint2 a2 = Ah[((wm + g)     << 4) + i1];
                uint2 a3 = Ah[((wm + g + 8) << 4) + i1];
                uint2 b0[2], b1[2];
#pragma unroll
                for (int ni = 0; ni < 2; ni++) {
                    int base = ((wn + ni * 8 + g) << 8) + chbase;
                    b0[ni] = Ws2[base + i0];
                    b1[ni] = Ws2[base + i1];
                }
#pragma unroll
                for (int ni = 0; ni < 2; ni++)
                    MMA16(accQ[ni], a0.x, a1.x, a2.x, a3.x, b0[ni].y, b1[ni].y);
#pragma unroll
                for (int ni = 0; ni < 2; ni++)
                    MMA16(accR[ni], a0.y, a1.y, a2.y, a3.y, b0[ni].x, b1[ni].x);
#pragma unroll
                for (int ni = 0; ni < 2; ni++)
                    MMA16(accP[ni], a0.x, a1.x, a2.x, a3.x, b0[ni].x, b1[ni].x);
            }
            if (loader && ch < 15) {
                uint2* Dst = Ab2 + ((ch + 1) & 1) * 1024;
#pragma unroll
                for (int i = 0; i < 4; i++) {
                    int idx = tid + i * 256; int m = idx >> 4, kp = idx & 15;
                    Dst[(m << 4) + (kp ^ ((m & 3) << 2))] = splitpk(raw2[i]);
                }
            }
            __syncthreads();
        }

        // stage gh tile (64x48)
#pragma unroll
        for (int ni = 0; ni < 2; ni++) {
            int r = wm + g;
            int c = wn + ni * 8 + tig * 2;
            gh_s[r * 48 + c]           = fmaf(accQ[ni][0] + accR[ni][0], INV2048, accP[ni][0]);
            gh_s[r * 48 + c + 1]       = fmaf(accQ[ni][1] + accR[ni][1], INV2048, accP[ni][1]);
            gh_s[(r + 8) * 48 + c]     = fmaf(accQ[ni][2] + accR[ni][2], INV2048, accP[ni][2]);
            gh_s[(r + 8) * 48 + c + 1] = fmaf(accQ[ni][3] + accR[ni][3], INV2048, accP[ni][3]);
        }
        __syncthreads();

        // gate math with prefetched GI
        {
            int idx = 0;
            for (int e = tid; e < 1024; e += 384, idx++) {
                int row = e >> 4, col = e & 15;
                int b = m0 + row, jj = jj0 + col;
                float ghr = gh_s[row * 48 + col]      + b_hh[jj];
                float ghz = gh_s[row * 48 + 16 + col] + b_hh[Hn + jj];
                float ghn = gh_s[row * 48 + 32 + col] + b_hh[2 * Hn + jj];
                float r = sigmoid_acc(p_r[idx] + ghr);
                float z = sigmoid_acc(p_z[idx] + ghz);
                float n = tanh_acc(fmaf(r, ghn, p_n[idx]));
                float ho = h_in[b * Hn + jj];
                float hv = (t < lengths[b]) ? ((1.f - z) * n + z * ho) : ho;
                h_out[b * Hn + jj] = hv;
            }
        }

        // per-batch-group barrier (32 CTAs) + GI prefetch for t+1 during wait
        __syncthreads();
        if (tid == 0) {
            __threadfence();
            atomicAdd(mybar, 1u);
        }
        if (t + 1 < Tn) {
            int idx = 0;
            for (int e = tid; e < 1024; e += 384, idx++) {
                int row = e >> 4, col = e & 15;
                const float* gi = GI + ((size_t)(m0 + row) * Tn + (t + 1)) * H3 + jj0 + col;
                p_r[idx] = gi[0];
                p_z[idx] = gi[Hn];
                p_n[idx] = gi[2 * Hn];
            }
        }
        if (tid == 0) {
            unsigned target = 32u * (unsigned)(t + 1);
            unsigned v;
            do {
                asm volatile("ld.acquire.gpu.global.b32 %0, [%1];"
                             : "=r"(v) : "l"(mybar) : "memory");
                if (v < target) __nanosleep(32);
            } while (v < target);
        }
        __syncthreads();
    }
}

// ---------------- misc -------------------------------------------------------
__global__ void init_kernel(float* h0, unsigned* bar) {
    int i = blockIdx.x * blockDim.x + threadIdx.x;
    if (i < Bn * Hn) h0[i] = 0.f;
    if (i < 4) bar[i] = 0u;
}

__global__ void nop_kernel() {}

__global__ void value_kernel(const float* __restrict__ h2,
                             const float* __restrict__ Wc3,
                             const float* __restrict__ bc3,
                             float* __restrict__ out)
{
    int gw = (blockIdx.x * blockDim.x + threadIdx.x) >> 5;
    int lane = threadIdx.x & 31;
    if (gw >= Bn) return;
    float s = 0.f;
    for (int k = lane; k < Hn; k += 32) s = fmaf(h2[gw * Hn + k], Wc3[k], s);
#pragma unroll
    for (int o = 16; o; o >>= 1) s += __shfl_xor_sync(0xffffffffu, s, o);
    if (lane == 0) out[gw] = s + bc3[0];
}

__global__ void gumbel_kernel(unsigned k0, unsigned k1, float* __restrict__ gout)
{
    unsigned i = blockIdx.x * blockDim.x + threadIdx.x;
    unsigned o0, o1;
    threefry2x32(k0, k1, 0u, i, &o0, &o1);
    unsigned bits = o0 ^ o1;
    float f = __uint_as_float((bits >> 9) | 0x3f800000u) - 1.0f;
    float u = fmaxf(f, 1.17549435e-38f);
    float g = -log_acc(-log_acc(u));
    gout[i] = g;
}

__global__ __launch_bounds__(256)
void sample_kernel(const float* __restrict__ logits,
                   const float* __restrict__ gumbel,
                   float* __restrict__ out_query,
                   float* __restrict__ out_lp)
{
    __shared__ float red[256];
    __shared__ int   redi[256];
    int row = blockIdx.x;
    int tid = threadIdx.x;
    const float* lg = logits + (size_t)row * DICTn;
    const float* gm = gumbel + (size_t)row * DICTn;

    float l[4];
#pragma unroll
    for (int i = 0; i < 4; i++) l[i] = lg[tid + i * 256];

    float mx = fmaxf(fmaxf(l[0], l[1]), fmaxf(l[2], l[3]));
    red[tid] = mx; __syncthreads();
    for (int s = 128; s > 0; s >>= 1) {
        if (tid < s) red[tid] = fmaxf(red[tid], red[tid + s]);
        __syncthreads();
    }
    mx = red[0]; __syncthreads();

    float se = 0.f;
#pragma unroll
    for (int i = 0; i < 4; i++) se += exp_acc(l[i] - mx);
    red[tid] = se; __syncthreads();
    for (int s = 128; s > 0; s >>= 1) {
        if (tid < s) red[tid] += red[tid + s];
        __syncthreads();
    }
    float logZ = mx + log_acc(red[0]); __syncthreads();

    float bv = -1e30f; int bi = 0x7fffffff;
#pragma unroll
    for (int i = 0; i < 4; i++) {
        int idx = tid + i * 256;
        float lp = l[i] - logZ;
        out_lp[(size_t)row * DICTn + idx] = lp;
        float v = lp + gm[idx];
        if (v > bv || (v == bv && idx < bi)) { bv = v; bi = idx; }
    }
    red[tid] = bv; redi[tid] = bi; __syncthreads();
    for (int s = 128; s > 0; s >>= 1) {
        if (tid < s) {
            if (red[tid + s] > red[tid] ||
                (red[tid + s] == red[tid] && redi[tid + s] < redi[tid])) {
                red[tid] = red[tid + s]; redi[tid] = redi[tid + s];
            }
        }
        __syncthreads();
    }
    int win = redi[0];
#pragma unroll
    for (int i = 0; i < 4; i++) {
        int idx = tid + i * 256;
        out_query[(size_t)row * DICTn + idx] = (idx == win) ? 1.f : 0.f;
    }
}

// ---------------- host -------------------------------------------------------
extern "C" void kernel_launch(void* const* d_in, const int* in_sizes, int n_in,
                              void* d_out, int out_size)
{
    const float* x      = (const float*)d_in[0];
    const int*   lens   = (const int*)  d_in[1];
    const float* W_ih   = (const float*)d_in[2];
    const float* W_hh   = (const float*)d_in[3];
    const float* b_ih   = (const float*)d_in[4];
    const float* b_hh   = (const float*)d_in[5];
    const float* W_out  = (const float*)d_in[6];
    const float* b_out  = (const float*)d_in[7];
    const float* Wc1    = (const float*)d_in[8];
    const float* bc1    = (const float*)d_in[9];
    const float* Wc2    = (const float*)d_in[10];
    const float* bc2    = (const float*)d_in[11];
    const float* Wc3    = (const float*)d_in[12];
    const float* bc3    = (const float*)d_in[13];

    float* out_value = (float*)d_out;
    float* out_query = out_value + Bn;
    float* out_lp    = out_query + (size_t)NSAMP;

    float *pGI, *ph0, *pc1, *pc2, *plog, *pgum;
    unsigned* pbar;
    cudaGetSymbolAddress((void**)&pGI,  g_GI);
    cudaGetSymbolAddress((void**)&ph0,  g_h);
    cudaGetSymbolAddress((void**)&pc1,  g_c1);
    cudaGetSymbolAddress((void**)&pc2,  g_c2);
    cudaGetSymbolAddress((void**)&plog, g_logits);
    cudaGetSymbolAddress((void**)&pgum, g_gumbel);
    cudaGetSymbolAddress((void**)&pbar, g_barrier);

    const int rec_smem = WS_UNITS * 8 + 2 * 1024 * 8;   // 114688 B
    cudaFuncSetAttribute(gru_persistent,
        cudaFuncAttributeMaxDynamicSharedMemorySize, rec_smem);

    // launches 0..4 so gru_persistent lands at ncu's -s 5 slot
    init_kernel<<<(Bn * Hn + 255) / 256, 256>>>(ph0, pbar);          // 0
    gemm_f32<<<dim3(H3 / 64, BT / 128), 256>>>(x, Dn, W_ih, Dn,      // 1
                                               pGI, H3, Dn, b_ih, 0, lens);
    nop_kernel<<<1, 32>>>();                                         // 2
    nop_kernel<<<1, 32>>>();                                         // 3
    nop_kernel<<<1, 32>>>();                                         // 4

    gru_persistent<<<NCTA_REC, 384, rec_smem>>>(pGI, W_hh, b_hh,     // 5
                                                lens, ph0, pbar);
    float* hfin = ph0;

    gemm_f32<<<dim3(Hn / 64, Bn / 128), 256>>>(hfin, Hn, Wc1, Hn, pc1, Hn,
                                               Hn, bc1, 1, nullptr);
    gemm_f32<<<dim3(Hn / 64, Bn / 128), 256>>>(pc1, Hn, Wc2, Hn, pc2, Hn,
                                               Hn, bc2, 1, nullptr);
    value_kernel<<<(Bn * 32 + 255) / 256, 256>>>(pc2, Wc3, bc3, out_value);

    gemm_f32<<<dim3(DICTn * Qn / 64, Bn / 128), 256>>>(hfin, Hn, W_out, Hn,
                                                       plog, DICTn * Qn,
                                                       Hn, b_out, 0, nullptr);

    unsigned s0, s1;
    threefry2x32(0u, 0u, 0u, 1234u, &s0, &s1);
    gumbel_kernel<<<NSAMP / 256, 256>>>(s0, s1, pgum);

    sample_kernel<<<Bn * Qn, 256>>>(plog, pgum, out_query, out_lp);
}

// round 10
// speedup vs baseline: 1.7912x; 1.0969x over previous
#include <cuda_runtime.h>
#include <cuda_fp16.h>
#include <math.h>
#include <stdint.h>

#define Bn    256
#define Tn    512
#define Dn    512
#define Hn    512
#define H3    1536
#define DICTn 1024
#define Qn    32
#define BT    (Bn*Tn)
#define NSAMP (Bn*Qn*DICTn)   // 8388608

#define NCTA_REC 128
#define WS_UNITS (96*256)     // W slice in uint2 units (96 gh rows x 256 k-pairs)
#define INV2048  4.8828125e-4f

// ---------------- static device scratch -------------------------------------
__device__ float g_GI[(size_t)BT * H3];
__device__ float g_h[2][Bn * Hn];
__device__ float g_c1[Bn * Hn];
__device__ float g_c2[Bn * Hn];
__device__ float g_logits[(size_t)Bn * Qn * DICTn];
__device__ float g_gumbel[(size_t)NSAMP];
__device__ unsigned g_barrier[8];

// ---------------- threefry2x32-20 (JAX-exact) --------------------------------
__host__ __device__ inline void threefry2x32(unsigned k0, unsigned k1,
                                             unsigned x0, unsigned x1,
                                             unsigned* o0, unsigned* o1) {
    unsigned ks2 = k0 ^ k1 ^ 0x1BD11BDAu;
    x0 += k0; x1 += k1;
#define TF_R(r) { x0 += x1; x1 = (x1 << (r)) | (x1 >> (32-(r))); x1 ^= x0; }
    TF_R(13) TF_R(15) TF_R(26) TF_R(6)   x0 += k1;  x1 += ks2 + 1u;
    TF_R(17) TF_R(29) TF_R(16) TF_R(24)  x0 += ks2; x1 += k0  + 2u;
    TF_R(13) TF_R(15) TF_R(26) TF_R(6)   x0 += k0;  x1 += k1  + 3u;
    TF_R(17) TF_R(29) TF_R(16) TF_R(24)  x0 += k1;  x1 += ks2 + 4u;
    TF_R(13) TF_R(15) TF_R(26) TF_R(6)   x0 += ks2; x1 += k0  + 5u;
#undef TF_R
    *o0 = x0; *o1 = x1;
}

// fp16x3 split: pack 2 consecutive k. .x = hi pair, .y = lo pair scaled x2048.
__device__ __forceinline__ uint2 splitpk(float2 v) {
    __half hx = __float2half_rn(v.x);
    __half hy = __float2half_rn(v.y);
    float rx = (v.x - __half2float(hx)) * 2048.0f;
    float ry = (v.y - __half2float(hy)) * 2048.0f;
    __half lx = __float2half_rn(rx);
    __half ly = __float2half_rn(ry);
    uint2 r;
    r.x = (unsigned)__half_as_ushort(hx) | ((unsigned)__half_as_ushort(hy) << 16);
    r.y = (unsigned)__half_as_ushort(lx) | ((unsigned)__half_as_ushort(ly) << 16);
    return r;
}

// ---------------- accurate fp32 exp/log --------------------------------------
__device__ __forceinline__ float exp_acc(float x) {
    x = fminf(fmaxf(x, -80.f), 80.f);
    float n = rintf(x * 1.4426950408889634f);
    float r = fmaf(n, -0.6931471824645996f, x);
    r = fmaf(n, 1.9046542121259063e-9f, r);
    float p = 1.984126984e-4f;
    p = fmaf(p, r, 1.388888889e-3f);
    p = fmaf(p, r, 8.333333333e-3f);
    p = fmaf(p, r, 4.166666667e-2f);
    p = fmaf(p, r, 1.666666667e-1f);
    p = fmaf(p, r, 0.5f);
    p = fmaf(p, r, 1.0f);
    p = fmaf(p, r, 1.0f);
    int ni = (int)n;
    float sc = __int_as_float((ni + 127) << 23);
    return p * sc;
}

__device__ __forceinline__ float log_acc(float x) {
    int xi = __float_as_int(x);
    int e = ((xi >> 23) & 0xff) - 127;
    float m = __int_as_float((xi & 0x7fffff) | 0x3f800000);
    if (m > 1.4142135623730951f) { m *= 0.5f; e += 1; }
    float fe = (float)e;
    float s = __fdiv_rn(m - 1.0f, m + 1.0f);
    float s2 = s * s;
    float p = 0.111111111f;
    p = fmaf(p, s2, 0.142857143f);
    p = fmaf(p, s2, 0.2f);
    p = fmaf(p, s2, 0.333333333f);
    p = p * s2;
    float logm = fmaf(2.0f * s, p, 2.0f * s);
    float res = fmaf(fe, 0.6931471824645996f, logm);
    res = fmaf(fe, -1.9046542121259063e-9f, res);
    return res;
}

__device__ __forceinline__ float sigmoid_acc(float x) {
    return __fdiv_rn(1.0f, 1.0f + exp_acc(-x));
}
__device__ __forceinline__ float tanh_acc(float x) {
    float a = fabsf(x);
    float e = exp_acc(-2.0f * a);
    float t = __fdiv_rn(1.0f - e, 1.0f + e);
    return copysignf(t, x);
}

#define MMA16(ACC, A0,A1,A2,A3, B0,B1)                                        \
    asm volatile(                                                             \
        "mma.sync.aligned.m16n8k16.row.col.f32.f16.f16.f32 "                  \
        "{%0,%1,%2,%3}, {%4,%5,%6,%7}, {%8,%9}, {%0,%1,%2,%3};\n"             \
        : "+f"(ACC[0]), "+f"(ACC[1]), "+f"(ACC[2]), "+f"(ACC[3])              \
        : "r"(A0), "r"(A1), "r"(A2), "r"(A3), "r"(B0), "r"(B1))

// ---------------- fp16x3 GEMM: C[M,N] = A[M,K]*B[N,K]^T + bias ---------------
// 128x64 tile, 8 warps (4x2), warp 32x32. accH = hi*hi, accC = scaled cross.
__global__ __launch_bounds__(256)
void gemm_f32(const float* __restrict__ A, int lda,
              const float* __restrict__ Bm, int ldb,
              float* __restrict__ C, int ldc,
              int K, const float* __restrict__ bias, int relu,
              const int* __restrict__ row_lens)
{
    __shared__ uint2 As2[128][16];
    __shared__ uint2 Bs2[64][16];

    const int tid  = threadIdx.x;
    const int warp = tid >> 5, lane = tid & 31;
    const int g    = lane >> 2, tig = lane & 3;
    const int m0   = blockIdx.y * 128, n0 = blockIdx.x * 64;
    const int wm   = (warp >> 1) * 32, wn = (warp & 1) * 32;
    const int swz  = (g & 3) << 2;

    if (row_lens) {
        int b = m0 >> 9;
        int ts = m0 & 511;
        if (ts >= row_lens[b]) return;
    }

    float accH[2][4][4], accC[2][4][4];
#pragma unroll
    for (int mi = 0; mi < 2; mi++)
#pragma unroll
        for (int ni = 0; ni < 4; ni++)
#pragma unroll
            for (int r = 0; r < 4; r++) { accH[mi][ni][r] = 0.f; accC[mi][ni][r] = 0.f; }

    float2 ra2[8], rb2[4];
#pragma unroll
    for (int i = 0; i < 8; i++) {
        int idx = tid + i * 256; int m = idx >> 4, kp = idx & 15;
        ra2[i] = *(const float2*)(A + (size_t)(m0 + m) * lda + kp * 2);
    }
#pragma unroll
    for (int i = 0; i < 4; i++) {
        int idx = tid + i * 256; int n = idx >> 4, kp = idx & 15;
        rb2[i] = *(const float2*)(Bm + (size_t)(n0 + n) * ldb + kp * 2);
    }

    const int nchunk = K >> 5;
    for (int ch = 0; ch < nchunk; ch++) {
#pragma unroll
        for (int i = 0; i < 8; i++) {
            int idx = tid + i * 256; int m = idx >> 4, kp = idx & 15;
            As2[m][kp ^ ((m & 3) << 2)] = splitpk(ra2[i]);
        }
#pragma unroll
        for (int i = 0; i < 4; i++) {
            int idx = tid + i * 256; int n = idx >> 4, kp = idx & 15;
            Bs2[n][kp ^ ((n & 3) << 2)] = splitpk(rb2[i]);
        }
        __syncthreads();

        if (ch + 1 < nchunk) {
            int k0 = (ch + 1) << 5;
#pragma unroll
            for (int i = 0; i < 8; i++) {
                int idx = tid + i * 256; int m = idx >> 4, kp = idx & 15;
                ra2[i] = *(const float2*)(A + (size_t)(m0 + m) * lda + k0 + kp * 2);
            }
#pragma unroll
            for (int i = 0; i < 4; i++) {
                int idx = tid + i * 256; int n = idx >> 4, kp = idx & 15;
                rb2[i] = *(const float2*)(Bm + (size_t)(n0 + n) * ldb + k0 + kp * 2);
            }
        }

#pragma unroll
        for (int sub = 0; sub < 2; sub++) {
            int i0 = ((sub << 3) + tig)     ^ swz;
            int i1 = ((sub << 3) + tig + 4) ^ swz;
            uint2 a[2][4];
#pragma unroll
            for (int mi = 0; mi < 2; mi++) {
                int r0 = wm + mi * 16;
                a[mi][0] = As2[r0 + g    ][i0];
                a[mi][1] = As2[r0 + g + 8][i0];
                a[mi][2] = As2[r0 + g    ][i1];
                a[mi][3] = As2[r0 + g + 8][i1];
            }
            uint2 b[4][2];
#pragma unroll
            for (int ni = 0; ni < 4; ni++) {
                int nrow = wn + ni * 8 + g;
                b[ni][0] = Bs2[nrow][i0];
                b[ni][1] = Bs2[nrow][i1];
            }
#pragma unroll
            for (int mi = 0; mi < 2; mi++)
#pragma unroll
                for (int ni = 0; ni < 4; ni++)
                    MMA16(accC[mi][ni], a[mi][0].x,a[mi][1].x,a[mi][2].x,a[mi][3].x,
                          b[ni][0].y, b[ni][1].y);
#pragma unroll
            for (int mi = 0; mi < 2; mi++)
#pragma unroll
                for (int ni = 0; ni < 4; ni++)
                    MMA16(accC[mi][ni], a[mi][0].y,a[mi][1].y,a[mi][2].y,a[mi][3].y,
                          b[ni][0].x, b[ni][1].x);
#pragma unroll
            for (int mi = 0; mi < 2; mi++)
#pragma unroll
                for (int ni = 0; ni < 4; ni++)
                    MMA16(accH[mi][ni], a[mi][0].x,a[mi][1].x,a[mi][2].x,a[mi][3].x,
                          b[ni][0].x, b[ni][1].x);
        }
        __syncthreads();
    }

#pragma unroll
    for (int mi = 0; mi < 2; mi++)
#pragma unroll
        for (int ni = 0; ni < 4; ni++) {
            int r = m0 + wm + mi * 16 + g;
            int c = n0 + wn + ni * 8 + tig * 2;
            float b0 = bias ? bias[c]     : 0.f;
            float b1 = bias ? bias[c + 1] : 0.f;
            float v0 = fmaf(accC[mi][ni][0], INV2048, accH[mi][ni][0]) + b0;
            float v1 = fmaf(accC[mi][ni][1], INV2048, accH[mi][ni][1]) + b1;
            float v2 = fmaf(accC[mi][ni][2], INV2048, accH[mi][ni][2]) + b0;
            float v3 = fmaf(accC[mi][ni][3], INV2048, accH[mi][ni][3]) + b1;
            if (relu) { v0 = fmaxf(v0, 0.f); v1 = fmaxf(v1, 0.f);
                        v2 = fmaxf(v2, 0.f); v3 = fmaxf(v3, 0.f); }
            C[(size_t)r * ldc + c]           = v0;
            C[(size_t)r * ldc + c + 1]       = v1;
            C[(size_t)(r + 8) * ldc + c]     = v2;
            C[(size_t)(r + 8) * ldc + c + 1] = v3;
        }
}

// ---------------- persistent GRU recurrence (v5) -----------------------------
// 128 CTAs = 8 batch-groups(32 rows, own 16-CTA barrier) x 16 col-groups(32 cols
// -> 96 gh rows). 384 threads = 12 warps (2m x 6n), warp tile 16x16.
// W slice fp16 hi/lo packed in SMEM (196.6KB); K-chunk 64 (8 chunks/step).
__global__ __launch_bounds__(384, 1)
void gru_persistent(const float* __restrict__ GI,
                    const float* __restrict__ W_hh,
                    const float* __restrict__ b_hh,
                    const int*   __restrict__ lengths,
                    float* __restrict__ hbase,
                    unsigned* __restrict__ bar)
{
    extern __shared__ uint2 smem2[];
    uint2* Ws2 = smem2;                      // 96*256 uint2 = 196608 B
    uint2* Ab2 = smem2 + WS_UNITS;           // 2 stages x 1024 uint2 = 16384 B
    float* gh_s = (float*)(smem2 + WS_UNITS);// 32x96 f32 = 12288 B (reuse)

    const int tid  = threadIdx.x;
    const int warp = tid >> 5, lane = tid & 31;
    const int g    = lane >> 2, tig = lane & 3;
    const int swz  = (g & 3) << 2;
    const int cgp  = blockIdx.x & 15;        // 16 col-groups
    const int bg   = blockIdx.x >> 4;        // 8 batch-groups
    const int m0   = bg * 32;
    const int jj0  = cgp * 32;
    const int wm   = (warp & 1) * 16;        // 2 m-tiles
    const int wn   = (warp >> 1) * 16;       // 6 n-groups (0..80)
    unsigned* mybar = bar + bg;
    const bool loader = (tid < 256);

    // one-time W slice preload: row n = gate*32 + c  ->  W_hh[gate*512+jj0+c]
    for (int i = tid; i < WS_UNITS; i += 384) {
        int n = i >> 8, kp = i & 255;
        int wrow = (n >> 5) * Hn + jj0 + (n & 31);
        float2 w = *(const float2*)(W_hh + (size_t)wrow * Hn + kp * 2);
        int off = (n << 8) + (kp & ~15) + ((kp & 15) ^ ((n & 3) << 2));
        Ws2[off] = splitpk(w);
    }
    __syncthreads();

    // GI prefetch registers (up to 3 elems/thread: 1024 elems / 384 thr)
    float p_r[3], p_z[3], p_n[3];
    {
        int idx = 0;
        for (int e = tid; e < 1024; e += 384, idx++) {
            int row = e >> 5, col = e & 31;
            const float* gi = GI + ((size_t)(m0 + row) * Tn + 0) * H3 + jj0 + col;
            p_r[idx] = gi[0];
            p_z[idx] = gi[Hn];
            p_n[idx] = gi[2 * Hn];
        }
    }

    for (int t = 0; t < Tn; t++) {
        const float* h_in  = hbase + (t & 1) * (Bn * Hn);
        float*       h_out = hbase + ((t + 1) & 1) * (Bn * Hn);

        float accP[2][4], accQ[2][4], accR[2][4];
#pragma unroll
        for (int ni = 0; ni < 2; ni++)
#pragma unroll
            for (int r = 0; r < 4; r++) {
                accP[ni][r] = 0.f; accQ[ni][r] = 0.f; accR[ni][r] = 0.f;
            }

        // chunk = 64 k (32 pairs); A tile 32 rows x 32 kp = 1024 units
        float2 raw2[4];
        if (loader) {
#pragma unroll
            for (int i = 0; i < 4; i++) {
                int idx = tid + i * 256; int m = idx >> 5, kp = idx & 31;
                raw2[i] = *(const float2*)(h_in + (size_t)(m0 + m) * Hn + kp * 2);
            }
#pragma unroll
            for (int i = 0; i < 4; i++) {
                int idx = tid + i * 256; int m = idx >> 5, kp = idx & 31;
                Ab2[(m << 5) + (kp & ~15) + ((kp & 15) ^ ((m & 3) << 2))] = splitpk(raw2[i]);
            }
        }
        __syncthreads();

        for (int ch = 0; ch < 8; ch++) {
            if (loader && ch < 7) {
                int k0 = (ch + 1) << 6;
#pragma unroll
                for (int i = 0; i < 4; i++) {
                    int idx = tid + i * 256; int m = idx >> 5, kp = idx & 31;
                    raw2[i] = *(const float2*)(h_in + (size_t)(m0 + m) * Hn + k0 + kp * 2);
                }
            }
            const uint2* Ah = Ab2 + (ch & 1) * 1024;
            const int chbase = ch << 5;
#pragma unroll
            for (int sub = 0; sub < 4; sub++) {
                int i0 = ((sub << 3) + tig)     ^ swz;
                int i1 = ((sub << 3) + tig + 4) ^ swz;
                uint2 a0 = Ah[((wm + g)     << 5) + i0];
                uint2 a1 = Ah[((wm + g + 8) << 5) + i0];
                uint2 a2 = Ah[((wm + g)     << 5) + i1];
                uint2 a3 = Ah[((wm + g + 8) << 5) + i1];
                uint2 b0[2], b1[2];
#pragma unroll
                for (int ni = 0; ni < 2; ni++) {
                    int base = ((wn + ni * 8 + g) << 8) + chbase;
                    b0[ni] = Ws2[base + i0];
                    b1[ni] = Ws2[base + i1];
                }
#pragma unroll
                for (int ni = 0; ni < 2; ni++)
                    MMA16(accQ[ni], a0.x, a1.x, a2.x, a3.x, b0[ni].y, b1[ni].y);
#pragma unroll
                for (int ni = 0; ni < 2; ni++)
                    MMA16(accR[ni], a0.y, a1.y, a2.y, a3.y, b0[ni].x, b1[ni].x);
#pragma unroll
                for (int ni = 0; ni < 2; ni++)
                    MMA16(accP[ni], a0.x, a1.x, a2.x, a3.x, b0[ni].x, b1[ni].x);
            }
            if (loader && ch < 7) {
                uint2* Dst = Ab2 + ((ch + 1) & 1) * 1024;
#pragma unroll
                for (int i = 0; i < 4; i++) {
                    int idx = tid + i * 256; int m = idx >> 5, kp = idx & 31;
                    Dst[(m << 5) + (kp & ~15) + ((kp & 15) ^ ((m & 3) << 2))] = splitpk(raw2[i]);
                }
            }
            __syncthreads();
        }

        // stage gh tile (32 rows x 96 cols)
#pragma unroll
        for (int ni = 0; ni < 2; ni++) {
            int r = wm + g;
            int c = wn + ni * 8 + tig * 2;
            gh_s[r * 96 + c]           = fmaf(accQ[ni][0] + accR[ni][0], INV2048, accP[ni][0]);
            gh_s[r * 96 + c + 1]       = fmaf(accQ[ni][1] + accR[ni][1], INV2048, accP[ni][1]);
            gh_s[(r + 8) * 96 + c]     = fmaf(accQ[ni][2] + accR[ni][2], INV2048, accP[ni][2]);
            gh_s[(r + 8) * 96 + c + 1] = fmaf(accQ[ni][3] + accR[ni][3], INV2048, accP[ni][3]);
        }
        __syncthreads();

        // gate math: 32 rows x 32 cols = 1024 elems over 384 threads
        {
            int idx = 0;
            for (int e = tid; e < 1024; e += 384, idx++) {
                int row = e >> 5, col = e & 31;
                int b = m0 + row, jj = jj0 + col;
                float ghr = gh_s[row * 96 + col]      + b_hh[jj];
                float ghz = gh_s[row * 96 + 32 + col] + b_hh[Hn + jj];
                float ghn = gh_s[row * 96 + 64 + col] + b_hh[2 * Hn + jj];
                float r = sigmoid_acc(p_r[idx] + ghr);
                float z = sigmoid_acc(p_z[idx] + ghz);
                float n = tanh_acc(fmaf(r, ghn, p_n[idx]));
                float ho = h_in[b * Hn + jj];
                float hv = (t < lengths[b]) ? ((1.f - z) * n + z * ho) : ho;
                h_out[b * Hn + jj] = hv;
            }
        }

        // per-batch-group barrier (16 CTAs) + GI prefetch for t+1 during wait
        __syncthreads();
        if (tid == 0) {
            __threadfence();
            atomicAdd(mybar, 1u);
        }
        if (t + 1 < Tn) {
            int idx = 0;
            for (int e = tid; e < 1024; e += 384, idx++) {
                int row = e >> 5, col = e & 31;
                const float* gi = GI + ((size_t)(m0 + row) * Tn + (t + 1)) * H3 + jj0 + col;
                p_r[idx] = gi[0];
                p_z[idx] = gi[Hn];
                p_n[idx] = gi[2 * Hn];
            }
        }
        if (tid == 0) {
            unsigned target = 16u * (unsigned)(t + 1);
            unsigned v;
            do {
                asm volatile("ld.acquire.gpu.global.b32 %0, [%1];"
                             : "=r"(v) : "l"(mybar) : "memory");
                if (v < target) __nanosleep(32);
            } while (v < target);
        }
        __syncthreads();
    }
}

// ---------------- misc -------------------------------------------------------
__global__ void init_kernel(float* h0, unsigned* bar) {
    int i = blockIdx.x * blockDim.x + threadIdx.x;
    if (i < Bn * Hn) h0[i] = 0.f;
    if (i < 8) bar[i] = 0u;
}

__global__ void nop_kernel() {}

__global__ void value_kernel(const float* __restrict__ h2,
                             const float* __restrict__ Wc3,
                             const float* __restrict__ bc3,
                             float* __restrict__ out)
{
    int gw = (blockIdx.x * blockDim.x + threadIdx.x) >> 5;
    int lane = threadIdx.x & 31;
    if (gw >= Bn) return;
    float s = 0.f;
    for (int k = lane; k < Hn; k += 32) s = fmaf(h2[gw * Hn + k], Wc3[k], s);
#pragma unroll
    for (int o = 16; o; o >>= 1) s += __shfl_xor_sync(0xffffffffu, s, o);
    if (lane == 0) out[gw] = s + bc3[0];
}

__global__ void gumbel_kernel(unsigned k0, unsigned k1, float* __restrict__ gout)
{
    unsigned i = blockIdx.x * blockDim.x + threadIdx.x;
    unsigned o0, o1;
    threefry2x32(k0, k1, 0u, i, &o0, &o1);
    unsigned bits = o0 ^ o1;
    float f = __uint_as_float((bits >> 9) | 0x3f800000u) - 1.0f;
    float u = fmaxf(f, 1.17549435e-38f);
    float g = -log_acc(-log_acc(u));
    gout[i] = g;
}

__global__ __launch_bounds__(256)
void sample_kernel(const float* __restrict__ logits,
                   const float* __restrict__ gumbel,
                   float* __restrict__ out_query,
                   float* __restrict__ out_lp)
{
    __shared__ float red[256];
    __shared__ int   redi[256];
    int row = blockIdx.x;
    int tid = threadIdx.x;
    const float* lg = logits + (size_t)row * DICTn;
    const float* gm = gumbel + (size_t)row * DICTn;

    float l[4];
#pragma unroll
    for (int i = 0; i < 4; i++) l[i] = lg[tid + i * 256];

    float mx = fmaxf(fmaxf(l[0], l[1]), fmaxf(l[2], l[3]));
    red[tid] = mx; __syncthreads();
    for (int s = 128; s > 0; s >>= 1) {
        if (tid < s) red[tid] = fmaxf(red[tid], red[tid + s]);
        __syncthreads();
    }
    mx = red[0]; __syncthreads();

    float se = 0.f;
#pragma unroll
    for (int i = 0; i < 4; i++) se += exp_acc(l[i] - mx);
    red[tid] = se; __syncthreads();
    for (int s = 128; s > 0; s >>= 1) {
        if (tid < s) red[tid] += red[tid + s];
        __syncthreads();
    }
    float logZ = mx + log_acc(red[0]); __syncthreads();

    float bv = -1e30f; int bi = 0x7fffffff;
#pragma unroll
    for (int i = 0; i < 4; i++) {
        int idx = tid + i * 256;
        float lp = l[i] - logZ;
        out_lp[(size_t)row * DICTn + idx] = lp;
        float v = lp + gm[idx];
        if (v > bv || (v == bv && idx < bi)) { bv = v; bi = idx; }
    }
    red[tid] = bv; redi[tid] = bi; __syncthreads();
    for (int s = 128; s > 0; s >>= 1) {
        if (tid < s) {
            if (red[tid + s] > red[tid] ||
                (red[tid + s] == red[tid] && redi[tid + s] < redi[tid])) {
                red[tid] = red[tid + s]; redi[tid] = redi[tid + s];
            }
        }
        __syncthreads();
    }
    int win = redi[0];
#pragma unroll
    for (int i = 0; i < 4; i++) {
        int idx = tid + i * 256;
        out_query[(size_t)row * DICTn + idx] = (idx == win) ? 1.f : 0.f;
    }
}

// ---------------- host -------------------------------------------------------
extern "C" void kernel_launch(void* const* d_in, const int* in_sizes, int n_in,
                              void* d_out, int out_size)
{
    const float* x      = (const float*)d_in[0];
    const int*   lens   = (const int*)  d_in[1];
    const float* W_ih   = (const float*)d_in[2];
    const float* W_hh   = (const float*)d_in[3];
    const float* b_ih   = (const float*)d_in[4];
    const float* b_hh   = (const float*)d_in[5];
    const float* W_out  = (const float*)d_in[6];
    const float* b_out  = (const float*)d_in[7];
    const float* Wc1    = (const float*)d_in[8];
    const float* bc1    = (const float*)d_in[9];
    const float* Wc2    = (const float*)d_in[10];
    const float* bc2    = (const float*)d_in[11];
    const float* Wc3    = (const float*)d_in[12];
    const float* bc3    = (const float*)d_in[13];

    float* out_value = (float*)d_out;
    float* out_query = out_value + Bn;
    float* out_lp    = out_query + (size_t)NSAMP;

    float *pGI, *ph0, *pc1, *pc2, *plog, *pgum;
    unsigned* pbar;
    cudaGetSymbolAddress((void**)&pGI,  g_GI);
    cudaGetSymbolAddress((void**)&ph0,  g_h);
    cudaGetSymbolAddress((void**)&pc1,  g_c1);
    cudaGetSymbolAddress((void**)&pc2,  g_c2);
    cudaGetSymbolAddress((void**)&plog, g_logits);
    cudaGetSymbolAddress((void**)&pgum, g_gumbel);
    cudaGetSymbolAddress((void**)&pbar, g_barrier);

    const int rec_smem = WS_UNITS * 8 + 2 * 1024 * 8;   // 212992 B
    cudaFuncSetAttribute(gru_persistent,
        cudaFuncAttributeMaxDynamicSharedMemorySize, rec_smem);

    // harness pre-launch is idx 0; place gru at global idx 5 for ncu -s 5
    init_kernel<<<(Bn * Hn + 255) / 256, 256>>>(ph0, pbar);          // 1
    gemm_f32<<<dim3(H3 / 64, BT / 128), 256>>>(x, Dn, W_ih, Dn,      // 2
                                               pGI, H3, Dn, b_ih, 0, lens);
    nop_kernel<<<1, 32>>>();                                         // 3
    nop_kernel<<<1, 32>>>();                                         // 4

    gru_persistent<<<NCTA_REC, 384, rec_smem>>>(pGI, W_hh, b_hh,     // 5
                                                lens, ph0, pbar);
    float* hfin = ph0;

    gemm_f32<<<dim3(Hn / 64, Bn / 128), 256>>>(hfin, Hn, Wc1, Hn, pc1, Hn,
                                               Hn, bc1, 1, nullptr);
    gemm_f32<<<dim3(Hn / 64, Bn / 128), 256>>>(pc1, Hn, Wc2, Hn, pc2, Hn,
                                               Hn, bc2, 1, nullptr);
    value_kernel<<<(Bn * 32 + 255) / 256, 256>>>(pc2, Wc3, bc3, out_value);

    gemm_f32<<<dim3(DICTn * Qn / 64, Bn / 128), 256>>>(hfin, Hn, W_out, Hn,
                                                       plog, DICTn * Qn,
                                                       Hn, b_out, 0, nullptr);

    unsigned s0, s1;
    threefry2x32(0u, 0u, 0u, 1234u, &s0, &s1);
    gumbel_kernel<<<NSAMP / 256, 256>>>(s0, s1, pgum);

    sample_kernel<<<Bn * Qn, 256>>>(plog, pgum, out_query, out_lp);
}

// round 11
// speedup vs baseline: 1.8974x; 1.0593x over previous
#include <cuda_runtime.h>
#include <cuda_fp16.h>
#include <math.h>
#include <stdint.h>

#define Bn    256
#define Tn    512
#define Dn    512
#define Hn    512
#define H3    1536
#define DICTn 1024
#define Qn    32
#define BT    (Bn*Tn)
#define NSAMP (Bn*Qn*DICTn)   // 8388608

#define NCTA_REC 128
#define WS_UNITS (96*256)     // W slice uint2 units (96 gh rows x 256 k-pairs)
#define INV2048  4.8828125e-4f

// ---------------- static device scratch -------------------------------------
__device__ float g_GI[(size_t)BT * H3];
__device__ float g_h[2][Bn * Hn];
__device__ float g_c1[Bn * Hn];
__device__ float g_c2[Bn * Hn];
__device__ float g_logits[(size_t)Bn * Qn * DICTn];
__device__ float g_gumbel[(size_t)NSAMP];
__device__ unsigned g_barrier[8];

// ---------------- threefry2x32-20 (JAX-exact) --------------------------------
__host__ __device__ inline void threefry2x32(unsigned k0, unsigned k1,
                                             unsigned x0, unsigned x1,
                                             unsigned* o0, unsigned* o1) {
    unsigned ks2 = k0 ^ k1 ^ 0x1BD11BDAu;
    x0 += k0; x1 += k1;
#define TF_R(r) { x0 += x1; x1 = (x1 << (r)) | (x1 >> (32-(r))); x1 ^= x0; }
    TF_R(13) TF_R(15) TF_R(26) TF_R(6)   x0 += k1;  x1 += ks2 + 1u;
    TF_R(17) TF_R(29) TF_R(16) TF_R(24)  x0 += ks2; x1 += k0  + 2u;
    TF_R(13) TF_R(15) TF_R(26) TF_R(6)   x0 += k0;  x1 += k1  + 3u;
    TF_R(17) TF_R(29) TF_R(16) TF_R(24)  x0 += k1;  x1 += ks2 + 4u;
    TF_R(13) TF_R(15) TF_R(26) TF_R(6)   x0 += ks2; x1 += k0  + 5u;
#undef TF_R
    *o0 = x0; *o1 = x1;
}

// fp16x3 split: pack 2 consecutive k. .x = hi pair, .y = lo pair scaled x2048.
__device__ __forceinline__ uint2 splitpk(float2 v) {
    __half hx = __float2half_rn(v.x);
    __half hy = __float2half_rn(v.y);
    float rx = (v.x - __half2float(hx)) * 2048.0f;
    float ry = (v.y - __half2float(hy)) * 2048.0f;
    __half lx = __float2half_rn(rx);
    __half ly = __float2half_rn(ry);
    uint2 r;
    r.x = (unsigned)__half_as_ushort(hx) | ((unsigned)__half_as_ushort(hy) << 16);
    r.y = (unsigned)__half_as_ushort(lx) | ((unsigned)__half_as_ushort(ly) << 16);
    return r;
}

// ---------------- accurate fp32 exp/log --------------------------------------
__device__ __forceinline__ float exp_acc(float x) {
    x = fminf(fmaxf(x, -80.f), 80.f);
    float n = rintf(x * 1.4426950408889634f);
    float r = fmaf(n, -0.6931471824645996f, x);
    r = fmaf(n, 1.9046542121259063e-9f, r);
    float p = 1.984126984e-4f;
    p = fmaf(p, r, 1.388888889e-3f);
    p = fmaf(p, r, 8.333333333e-3f);
    p = fmaf(p, r, 4.166666667e-2f);
    p = fmaf(p, r, 1.666666667e-1f);
    p = fmaf(p, r, 0.5f);
    p = fmaf(p, r, 1.0f);
    p = fmaf(p, r, 1.0f);
    int ni = (int)n;
    float sc = __int_as_float((ni + 127) << 23);
    return p * sc;
}

__device__ __forceinline__ float log_acc(float x) {
    int xi = __float_as_int(x);
    int e = ((xi >> 23) & 0xff) - 127;
    float m = __int_as_float((xi & 0x7fffff) | 0x3f800000);
    if (m > 1.4142135623730951f) { m *= 0.5f; e += 1; }
    float fe = (float)e;
    float s = __fdiv_rn(m - 1.0f, m + 1.0f);
    float s2 = s * s;
    float p = 0.111111111f;
    p = fmaf(p, s2, 0.142857143f);
    p = fmaf(p, s2, 0.2f);
    p = fmaf(p, s2, 0.333333333f);
    p = p * s2;
    float logm = fmaf(2.0f * s, p, 2.0f * s);
    float res = fmaf(fe, 0.6931471824645996f, logm);
    res = fmaf(fe, -1.9046542121259063e-9f, res);
    return res;
}

__device__ __forceinline__ float sigmoid_acc(float x) {
    return __fdiv_rn(1.0f, 1.0f + exp_acc(-x));
}
__device__ __forceinline__ float tanh_acc(float x) {
    float a = fabsf(x);
    float e = exp_acc(-2.0f * a);
    float t = __fdiv_rn(1.0f - e, 1.0f + e);
    return copysignf(t, x);
}

#define MMA16(ACC, A0,A1,A2,A3, B0,B1)                                        \
    asm volatile(                                                             \
        "mma.sync.aligned.m16n8k16.row.col.f32.f16.f16.f32 "                  \
        "{%0,%1,%2,%3}, {%4,%5,%6,%7}, {%8,%9}, {%0,%1,%2,%3};\n"             \
        : "+f"(ACC[0]), "+f"(ACC[1]), "+f"(ACC[2]), "+f"(ACC[3])              \
        : "r"(A0), "r"(A1), "r"(A2), "r"(A3), "r"(B0), "r"(B1))

// ---------------- fp16x3 GEMM: C[M,N] = A[M,K]*B[N,K]^T + bias ---------------
__global__ __launch_bounds__(256)
void gemm_f32(const float* __restrict__ A, int lda,
              const float* __restrict__ Bm, int ldb,
              float* __restrict__ C, int ldc,
              int K, const float* __restrict__ bias, int relu,
              const int* __restrict__ row_lens)
{
    __shared__ uint2 As2[128][16];
    __shared__ uint2 Bs2[64][16];

    const int tid  = threadIdx.x;
    const int warp = tid >> 5, lane = tid & 31;
    const int g    = lane >> 2, tig = lane & 3;
    const int m0   = blockIdx.y * 128, n0 = blockIdx.x * 64;
    const int wm   = (warp >> 1) * 32, wn = (warp & 1) * 32;
    const int swz  = (g & 3) << 2;

    if (row_lens) {
        int b = m0 >> 9;
        int ts = m0 & 511;
        if (ts >= row_lens[b]) return;
    }

    float accH[2][4][4], accC[2][4][4];
#pragma unroll
    for (int mi = 0; mi < 2; mi++)
#pragma unroll
        for (int ni = 0; ni < 4; ni++)
#pragma unroll
            for (int r = 0; r < 4; r++) { accH[mi][ni][r] = 0.f; accC[mi][ni][r] = 0.f; }

    float2 ra2[8], rb2[4];
#pragma unroll
    for (int i = 0; i < 8; i++) {
        int idx = tid + i * 256; int m = idx >> 4, kp = idx & 15;
        ra2[i] = *(const float2*)(A + (size_t)(m0 + m) * lda + kp * 2);
    }
#pragma unroll
    for (int i = 0; i < 4; i++) {
        int idx = tid + i * 256; int n = idx >> 4, kp = idx & 15;
        rb2[i] = *(const float2*)(Bm + (size_t)(n0 + n) * ldb + kp * 2);
    }

    const int nchunk = K >> 5;
    for (int ch = 0; ch < nchunk; ch++) {
#pragma unroll
        for (int i = 0; i < 8; i++) {
            int idx = tid + i * 256; int m = idx >> 4, kp = idx & 15;
            As2[m][kp ^ ((m & 3) << 2)] = splitpk(ra2[i]);
        }
#pragma unroll
        for (int i = 0; i < 4; i++) {
            int idx = tid + i * 256; int n = idx >> 4, kp = idx & 15;
            Bs2[n][kp ^ ((n & 3) << 2)] = splitpk(rb2[i]);
        }
        __syncthreads();

        if (ch + 1 < nchunk) {
            int k0 = (ch + 1) << 5;
#pragma unroll
            for (int i = 0; i < 8; i++) {
                int idx = tid + i * 256; int m = idx >> 4, kp = idx & 15;
                ra2[i] = *(const float2*)(A + (size_t)(m0 + m) * lda + k0 + kp * 2);
            }
#pragma unroll
            for (int i = 0; i < 4; i++) {
                int idx = tid + i * 256; int n = idx >> 4, kp = idx & 15;
                rb2[i] = *(const float2*)(Bm + (size_t)(n0 + n) * ldb + k0 + kp * 2);
            }
        }

#pragma unroll
        for (int sub = 0; sub < 2; sub++) {
            int i0 = ((sub << 3) + tig)     ^ swz;
            int i1 = ((sub << 3) + tig + 4) ^ swz;
            uint2 a[2][4];
#pragma unroll
            for (int mi = 0; mi < 2; mi++) {
                int r0 = wm + mi * 16;
                a[mi][0] = As2[r0 + g    ][i0];
                a[mi][1] = As2[r0 + g + 8][i0];
                a[mi][2] = As2[r0 + g    ][i1];
                a[mi][3] = As2[r0 + g + 8][i1];
            }
            uint2 b[4][2];
#pragma unroll
            for (int ni = 0; ni < 4; ni++) {
                int nrow = wn + ni * 8 + g;
                b[ni][0] = Bs2[nrow][i0];
                b[ni][1] = Bs2[nrow][i1];
            }
#pragma unroll
            for (int mi = 0; mi < 2; mi++)
#pragma unroll
                for (int ni = 0; ni < 4; ni++)
                    MMA16(accC[mi][ni], a[mi][0].x,a[mi][1].x,a[mi][2].x,a[mi][3].x,
                          b[ni][0].y, b[ni][1].y);
#pragma unroll
            for (int mi = 0; mi < 2; mi++)
#pragma unroll
                for (int ni = 0; ni < 4; ni++)
                    MMA16(accC[mi][ni], a[mi][0].y,a[mi][1].y,a[mi][2].y,a[mi][3].y,
                          b[ni][0].x, b[ni][1].x);
#pragma unroll
            for (int mi = 0; mi < 2; mi++)
#pragma unroll
                for (int ni = 0; ni < 4; ni++)
                    MMA16(accH[mi][ni], a[mi][0].x,a[mi][1].x,a[mi][2].x,a[mi][3].x,
                          b[ni][0].x, b[ni][1].x);
        }
        __syncthreads();
    }

#pragma unroll
    for (int mi = 0; mi < 2; mi++)
#pragma unroll
        for (int ni = 0; ni < 4; ni++) {
            int r = m0 + wm + mi * 16 + g;
            int c = n0 + wn + ni * 8 + tig * 2;
            float b0 = bias ? bias[c]     : 0.f;
            float b1 = bias ? bias[c + 1] : 0.f;
            float v0 = fmaf(accC[mi][ni][0], INV2048, accH[mi][ni][0]) + b0;
            float v1 = fmaf(accC[mi][ni][1], INV2048, accH[mi][ni][1]) + b1;
            float v2 = fmaf(accC[mi][ni][2], INV2048, accH[mi][ni][2]) + b0;
            float v3 = fmaf(accC[mi][ni][3], INV2048, accH[mi][ni][3]) + b1;
            if (relu) { v0 = fmaxf(v0, 0.f); v1 = fmaxf(v1, 0.f);
                        v2 = fmaxf(v2, 0.f); v3 = fmaxf(v3, 0.f); }
            C[(size_t)r * ldc + c]           = v0;
            C[(size_t)r * ldc + c + 1]       = v1;
            C[(size_t)(r + 8) * ldc + c]     = v2;
            C[(size_t)(r + 8) * ldc + c + 1] = v3;
        }
}

// ---------------- persistent GRU recurrence (v6: fragment gate math) ---------
// 128 CTAs = 8 batch-groups(32 rows, 16-CTA barrier) x 16 col-groups(32 cols).
// 256 threads = 8 warps (2m x 4 col-groups of 8 h-cols). Each warp owns 3 MMA
// n-tiles = [r|z|n] for ITS 8 h-cols -> gate math fully in registers.
// h_old, b_hh, lengths register-resident across all 512 steps.
__global__ __launch_bounds__(256, 1)
void gru_persistent(const float* __restrict__ GI,
                    const float* __restrict__ W_hh,
                    const float* __restrict__ b_hh,
                    const int*   __restrict__ lengths,
                    float* __restrict__ hbase,
                    unsigned* __restrict__ bar)
{
    extern __shared__ uint2 smem2[];
    uint2* Ws2 = smem2;                      // 96*256 uint2 = 196608 B
    uint2* Ab2 = smem2 + WS_UNITS;           // 2 stages x 1024 uint2 = 16384 B

    const int tid  = threadIdx.x;
    const int warp = tid >> 5, lane = tid & 31;
    const int g    = lane >> 2, tig = lane & 3;
    const int swz  = (g & 3) << 2;
    const int cgp  = blockIdx.x & 15;        // 16 col-groups
    const int bg   = blockIdx.x >> 4;        // 8 batch-groups
    const int m0   = bg * 32;
    const int jj0  = cgp * 32;
    const int wm   = (warp & 1) * 16;        // m-tile
    const int jg   = warp >> 1;              // col-subgroup 0..3 (8 h-cols each)
    unsigned* mybar = bar + bg;

    // one-time W slice preload. SMEM row n = jg*24 + gate*8 + jo maps to
    // W_hh row = gate*512 + jj0 + jg*8 + jo.
    for (int i = tid; i < WS_UNITS; i += 256) {
        int n = i >> 8, kp = i & 255;
        int jgn = n / 24, rem = n - jgn * 24;
        int gate = rem >> 3, jo = rem & 7;
        int wrow = gate * Hn + jj0 + jgn * 8 + jo;
        float2 w = *(const float2*)(W_hh + (size_t)wrow * Hn + kp * 2);
        int off = (n << 8) + (kp & ~15) + ((kp & 15) ^ ((n & 3) << 2));
        Ws2[off] = splitpk(w);
    }
    __syncthreads();

    // per-thread constants (positions k: 0=(r0,cA) 1=(r0,cB) 2=(r1,cA) 3=(r1,cB))
    const int b0i = m0 + wm + g, b1i = b0i + 8;
    const int jjA = jj0 + jg * 8 + tig * 2, jjB = jjA + 1;
    const int len0 = lengths[b0i], len1 = lengths[b1i];
    float bb[3][2];
#pragma unroll
    for (int gate = 0; gate < 3; gate++) {
        bb[gate][0] = b_hh[gate * Hn + jjA];
        bb[gate][1] = b_hh[gate * Hn + jjB];
    }
    float h_old[4] = {0.f, 0.f, 0.f, 0.f};

    // GI prefetch for t=0
    float pg[3][4];
#pragma unroll
    for (int gate = 0; gate < 3; gate++) {
        const float* gb = GI + gate * Hn;
        pg[gate][0] = gb[(size_t)b0i * Tn * H3 + jjA];
        pg[gate][1] = gb[(size_t)b0i * Tn * H3 + jjB];
        pg[gate][2] = gb[(size_t)b1i * Tn * H3 + jjA];
        pg[gate][3] = gb[(size_t)b1i * Tn * H3 + jjB];
    }

    for (int t = 0; t < Tn; t++) {
        const float* h_in  = hbase + (t & 1) * (Bn * Hn);
        float*       h_out = hbase + ((t + 1) & 1) * (Bn * Hn);

        float accP[3][4], accQ[3][4], accR[3][4];
#pragma unroll
        for (int nt = 0; nt < 3; nt++)
#pragma unroll
            for (int r = 0; r < 4; r++) {
                accP[nt][r] = 0.f; accQ[nt][r] = 0.f; accR[nt][r] = 0.f;
            }

        // chunk = 64 k (32 pairs); A tile 32 rows x 32 kp = 1024 units
        float2 raw2[4];
#pragma unroll
        for (int i = 0; i < 4; i++) {
            int idx = tid + i * 256; int m = idx >> 5, kp = idx & 31;
            raw2[i] = *(const float2*)(h_in + (size_t)(m0 + m) * Hn + kp * 2);
        }
#pragma unroll
        for (int i = 0; i < 4; i++) {
            int idx = tid + i * 256; int m = idx >> 5, kp = idx & 31;
            Ab2[(m << 5) + (kp & ~15) + ((kp & 15) ^ ((m & 3) << 2))] = splitpk(raw2[i]);
        }
        __syncthreads();

        for (int ch = 0; ch < 8; ch++) {
            if (ch < 7) {
                int k0 = (ch + 1) << 6;
#pragma unroll
                for (int i = 0; i < 4; i++) {
                    int idx = tid + i * 256; int m = idx >> 5, kp = idx & 31;
                    raw2[i] = *(const float2*)(h_in + (size_t)(m0 + m) * Hn + k0 + kp * 2);
                }
            }
            const uint2* Ah = Ab2 + (ch & 1) * 1024;
            const int chbase = ch << 5;
#pragma unroll
            for (int sub = 0; sub < 4; sub++) {
                int i0 = ((sub << 3) + tig)     ^ swz;
                int i1 = ((sub << 3) + tig + 4) ^ swz;
                uint2 a0 = Ah[((wm + g)     << 5) + i0];
                uint2 a1 = Ah[((wm + g + 8) << 5) + i0];
                uint2 a2 = Ah[((wm + g)     << 5) + i1];
                uint2 a3 = Ah[((wm + g + 8) << 5) + i1];
                uint2 b0v[3], b1v[3];
#pragma unroll
                for (int nt = 0; nt < 3; nt++) {
                    int nrow = jg * 24 + nt * 8 + g;
                    int base = (nrow << 8) + chbase;
                    b0v[nt] = Ws2[base + i0];
                    b1v[nt] = Ws2[base + i1];
                }
#pragma unroll
                for (int nt = 0; nt < 3; nt++)
                    MMA16(accQ[nt], a0.x, a1.x, a2.x, a3.x, b0v[nt].y, b1v[nt].y);
#pragma unroll
                for (int nt = 0; nt < 3; nt++)
                    MMA16(accR[nt], a0.y, a1.y, a2.y, a3.y, b0v[nt].x, b1v[nt].x);
#pragma unroll
                for (int nt = 0; nt < 3; nt++)
                    MMA16(accP[nt], a0.x, a1.x, a2.x, a3.x, b0v[nt].x, b1v[nt].x);
            }
            if (ch < 7) {
                uint2* Dst = Ab2 + ((ch + 1) & 1) * 1024;
#pragma unroll
                for (int i = 0; i < 4; i++) {
                    int idx = tid + i * 256; int m = idx >> 5, kp = idx & 31;
                    Dst[(m << 5) + (kp & ~15) + ((kp & 15) ^ ((m & 3) << 2))] = splitpk(raw2[i]);
                }
            }
            __syncthreads();
        }

        // gate math fully in registers (nt 0=r, 1=z, 2=n)
        float gh[3][4];
#pragma unroll
        for (int nt = 0; nt < 3; nt++)
#pragma unroll
            for (int k = 0; k < 4; k++)
                gh[nt][k] = fmaf(accQ[nt][k] + accR[nt][k], INV2048,
                                 accP[nt][k]) + bb[nt][k & 1];
#pragma unroll
        for (int k = 0; k < 4; k++) {
            float r = sigmoid_acc(pg[0][k] + gh[0][k]);
            float z = sigmoid_acc(pg[1][k] + gh[1][k]);
            float n = tanh_acc(fmaf(r, gh[2][k], pg[2][k]));
            int blen = (k < 2) ? len0 : len1;
            float hv = (1.f - z) * n + z * h_old[k];
            h_old[k] = (t < blen) ? hv : h_old[k];
        }
        h_out[(size_t)b0i * Hn + jjA] = h_old[0];
        h_out[(size_t)b0i * Hn + jjB] = h_old[1];
        h_out[(size_t)b1i * Hn + jjA] = h_old[2];
        h_out[(size_t)b1i * Hn + jjB] = h_old[3];

        // per-batch-group barrier (16 CTAs) + GI prefetch for t+1 during wait
        __syncthreads();
        if (tid == 0) {
            __threadfence();
            atomicAdd(mybar, 1u);
        }
        if (t + 1 < Tn) {
            size_t off0 = ((size_t)b0i * Tn + (t + 1)) * H3;
            size_t off1 = ((size_t)b1i * Tn + (t + 1)) * H3;
#pragma unroll
            for (int gate = 0; gate < 3; gate++) {
                pg[gate][0] = GI[off0 + gate * Hn + jjA];
                pg[gate][1] = GI[off0 + gate * Hn + jjB];
                pg[gate][2] = GI[off1 + gate * Hn + jjA];
                pg[gate][3] = GI[off1 + gate * Hn + jjB];
            }
        }
        if (tid == 0) {
            unsigned target = 16u * (unsigned)(t + 1);
            unsigned v;
            do {
                asm volatile("ld.acquire.gpu.global.b32 %0, [%1];"
                             : "=r"(v) : "l"(mybar) : "memory");
                if (v < target) __nanosleep(32);
            } while (v < target);
        }
        __syncthreads();
    }
}

// ---------------- misc -------------------------------------------------------
__global__ void init_kernel(float* h0, unsigned* bar) {
    int i = blockIdx.x * blockDim.x + threadIdx.x;
    if (i < Bn * Hn) h0[i] = 0.f;
    if (i < 8) bar[i] = 0u;
}

__global__ void nop_kernel() {}

__global__ void value_kernel(const float* __restrict__ h2,
                             const float* __restrict__ Wc3,
                             const float* __restrict__ bc3,
                             float* __restrict__ out)
{
    int gw = (blockIdx.x * blockDim.x + threadIdx.x) >> 5;
    int lane = threadIdx.x & 31;
    if (gw >= Bn) return;
    float s = 0.f;
    for (int k = lane; k < Hn; k += 32) s = fmaf(h2[gw * Hn + k], Wc3[k], s);
#pragma unroll
    for (int o = 16; o; o >>= 1) s += __shfl_xor_sync(0xffffffffu, s, o);
    if (lane == 0) out[gw] = s + bc3[0];
}

__global__ void gumbel_kernel(unsigned k0, unsigned k1, float* __restrict__ gout)
{
    unsigned i = blockIdx.x * blockDim.x + threadIdx.x;
    unsigned o0, o1;
    threefry2x32(k0, k1, 0u, i, &o0, &o1);
    unsigned bits = o0 ^ o1;
    float f = __uint_as_float((bits >> 9) | 0x3f800000u) - 1.0f;
    float u = fmaxf(f, 1.17549435e-38f);
    float g = -log_acc(-log_acc(u));
    gout[i] = g;
}

__global__ __launch_bounds__(256)
void sample_kernel(const float* __restrict__ logits,
                   const float* __restrict__ gumbel,
                   float* __restrict__ out_query,
                   float* __restrict__ out_lp)
{
    __shared__ float red[256];
    __shared__ int   redi[256];
    int row = blockIdx.x;
    int tid = threadIdx.x;
    const float* lg = logits + (size_t)row * DICTn;
    const float* gm = gumbel + (size_t)row * DICTn;

    float l[4];
#pragma unroll
    for (int i = 0; i < 4; i++) l[i] = lg[tid + i * 256];

    float mx = fmaxf(fmaxf(l[0], l[1]), fmaxf(l[2], l[3]));
    red[tid] = mx; __syncthreads();
    for (int s = 128; s > 0; s >>= 1) {
        if (tid < s) red[tid] = fmaxf(red[tid], red[tid + s]);
        __syncthreads();
    }
    mx = red[0]; __syncthreads();

    float se = 0.f;
#pragma unroll
    for (int i = 0; i < 4; i++) se += exp_acc(l[i] - mx);
    red[tid] = se; __syncthreads();
    for (int s = 128; s > 0; s >>= 1) {
        if (tid < s) red[tid] += red[tid + s];
        __syncthreads();
    }
    float logZ = mx + log_acc(red[0]); __syncthreads();

    float bv = -1e30f; int bi = 0x7fffffff;
#pragma unroll
    for (int i = 0; i < 4; i++) {
        int idx = tid + i * 256;
        float lp = l[i] - logZ;
        out_lp[(size_t)row * DICTn + idx] = lp;
        float v = lp + gm[idx];
        if (v > bv || (v == bv && idx < bi)) { bv = v; bi = idx; }
    }
    red[tid] = bv; redi[tid] = bi; __syncthreads();
    for (int s = 128; s > 0; s >>= 1) {
        if (tid < s) {
            if (red[tid + s] > red[tid] ||
                (red[tid + s] == red[tid] && redi[tid + s] < redi[tid])) {
                red[tid] = red[tid + s]; redi[tid] = redi[tid + s];
            }
        }
        __syncthreads();
    }
    int win = redi[0];
#pragma unroll
    for (int i = 0; i < 4; i++) {
        int idx = tid + i * 256;
        out_query[(size_t)row * DICTn + idx] = (idx == win) ? 1.f : 0.f;
    }
}

// ---------------- host -------------------------------------------------------
extern "C" void kernel_launch(void* const* d_in, const int* in_sizes, int n_in,
                              void* d_out, int out_size)
{
    const float* x      = (const float*)d_in[0];
    const int*   lens   = (const int*)  d_in[1];
    const float* W_ih   = (const float*)d_in[2];
    const float* W_hh   = (const float*)d_in[3];
    const float* b_ih   = (const float*)d_in[4];
    const float* b_hh   = (const float*)d_in[5];
    const float* W_out  = (const float*)d_in[6];
    const float* b_out  = (const float*)d_in[7];
    const float* Wc1    = (const float*)d_in[8];
    const float* bc1    = (const float*)d_in[9];
    const float* Wc2    = (const float*)d_in[10];
    const float* bc2    = (const float*)d_in[11];
    const float* Wc3    = (const float*)d_in[12];
    const float* bc3    = (const float*)d_in[13];

    float* out_value = (float*)d_out;
    float* out_query = out_value + Bn;
    float* out_lp    = out_query + (size_t)NSAMP;

    float *pGI, *ph0, *pc1, *pc2, *plog, *pgum;
    unsigned* pbar;
    cudaGetSymbolAddress((void**)&pGI,  g_GI);
    cudaGetSymbolAddress((void**)&ph0,  g_h);
    cudaGetSymbolAddress((void**)&pc1,  g_c1);
    cudaGetSymbolAddress((void**)&pc2,  g_c2);
    cudaGetSymbolAddress((void**)&plog, g_logits);
    cudaGetSymbolAddress((void**)&pgum, g_gumbel);
    cudaGetSymbolAddress((void**)&pbar, g_barrier);

    const int rec_smem = WS_UNITS * 8 + 2 * 1024 * 8;   // 212992 B
    cudaFuncSetAttribute(gru_persistent,
        cudaFuncAttributeMaxDynamicSharedMemorySize, rec_smem);

    // harness emits 2 pre-launches; with 1 nop gru_persistent sits at ncu -s 5
    init_kernel<<<(Bn * Hn + 255) / 256, 256>>>(ph0, pbar);
    gemm_f32<<<dim3(H3 / 64, BT / 128), 256>>>(x, Dn, W_ih, Dn,
                                               pGI, H3, Dn, b_ih, 0, lens);
    nop_kernel<<<1, 32>>>();

    gru_persistent<<<NCTA_REC, 256, rec_smem>>>(pGI, W_hh, b_hh,
                                                lens, ph0, pbar);
    float* hfin = ph0;

    gemm_f32<<<dim3(Hn / 64, Bn / 128), 256>>>(hfin, Hn, Wc1, Hn, pc1, Hn,
                                               Hn, bc1, 1, nullptr);
    gemm_f32<<<dim3(Hn / 64, Bn / 128), 256>>>(pc1, Hn, Wc2, Hn, pc2, Hn,
                                               Hn, bc2, 1, nullptr);
    value_kernel<<<(Bn * 32 + 255) / 256, 256>>>(pc2, Wc3, bc3, out_value);

    gemm_f32<<<dim3(DICTn * Qn / 64, Bn / 128), 256>>>(hfin, Hn, W_out, Hn,
                                                       plog, DICTn * Qn,
                                                       Hn, b_out, 0, nullptr);

    unsigned s0, s1;
    threefry2x32(0u, 0u, 0u, 1234u, &s0, &s1);
    gumbel_kernel<<<NSAMP / 256, 256>>>(s0, s1, pgum);

    sample_kernel<<<Bn * Qn, 256>>>(plog, pgum, out_query, out_lp);
}

// round 12
// speedup vs baseline: 2.2164x; 1.1681x over previous
#include <cuda_runtime.h>
#include <cuda_fp16.h>
#include <math.h>
#include <stdint.h>

#define Bn    256
#define Tn    512
#define Dn    512
#define Hn    512
#define H3    1536
#define DICTn 1024
#define Qn    32
#define BT    (Bn*Tn)
#define NSAMP (Bn*Qn*DICTn)   // 8388608

#define NCTA_REC 128
#define WS_UNITS (96*256)     // W slice uint2 units (96 gh rows x 256 k-pairs)
#define INV2048  4.8828125e-4f

// ---------------- static device scratch -------------------------------------
__device__ float g_GI[(size_t)BT * H3];
__device__ float g_h[2][Bn * Hn];
__device__ float g_c1[Bn * Hn];
__device__ float g_c2[Bn * Hn];
__device__ float g_logits[(size_t)Bn * Qn * DICTn];
__device__ float g_gumbel[(size_t)NSAMP];
__device__ unsigned g_barrier[8];
__device__ uint2 g_hsplit[2][Bn * 256];            // packed split h (dbl buf)
__device__ uint2 g_xsp[(size_t)BT * 256];          // packed split x
__device__ uint2 g_wihsp[(size_t)H3 * 256];        // packed split W_ih

// ---------------- threefry2x32-20 (JAX-exact) --------------------------------
__host__ __device__ inline void threefry2x32(unsigned k0, unsigned k1,
                                             unsigned x0, unsigned x1,
                                             unsigned* o0, unsigned* o1) {
    unsigned ks2 = k0 ^ k1 ^ 0x1BD11BDAu;
    x0 += k0; x1 += k1;
#define TF_R(r) { x0 += x1; x1 = (x1 << (r)) | (x1 >> (32-(r))); x1 ^= x0; }
    TF_R(13) TF_R(15) TF_R(26) TF_R(6)   x0 += k1;  x1 += ks2 + 1u;
    TF_R(17) TF_R(29) TF_R(16) TF_R(24)  x0 += ks2; x1 += k0  + 2u;
    TF_R(13) TF_R(15) TF_R(26) TF_R(6)   x0 += k0;  x1 += k1  + 3u;
    TF_R(17) TF_R(29) TF_R(16) TF_R(24)  x0 += k1;  x1 += ks2 + 4u;
    TF_R(13) TF_R(15) TF_R(26) TF_R(6)   x0 += ks2; x1 += k0  + 5u;
#undef TF_R
    *o0 = x0; *o1 = x1;
}

// fp16x3 split: pack 2 consecutive k. .x = hi pair, .y = lo pair scaled x2048.
__device__ __forceinline__ uint2 splitpk(float2 v) {
    __half hx = __float2half_rn(v.x);
    __half hy = __float2half_rn(v.y);
    float rx = (v.x - __half2float(hx)) * 2048.0f;
    float ry = (v.y - __half2float(hy)) * 2048.0f;
    __half lx = __float2half_rn(rx);
    __half ly = __float2half_rn(ry);
    uint2 r;
    r.x = (unsigned)__half_as_ushort(hx) | ((unsigned)__half_as_ushort(hy) << 16);
    r.y = (unsigned)__half_as_ushort(lx) | ((unsigned)__half_as_ushort(ly) << 16);
    return r;
}

// ---------------- accurate fp32 exp/log --------------------------------------
__device__ __forceinline__ float exp_acc(float x) {
    x = fminf(fmaxf(x, -80.f), 80.f);
    float n = rintf(x * 1.4426950408889634f);
    float r = fmaf(n, -0.6931471824645996f, x);
    r = fmaf(n, 1.9046542121259063e-9f, r);
    float p = 1.984126984e-4f;
    p = fmaf(p, r, 1.388888889e-3f);
    p = fmaf(p, r, 8.333333333e-3f);
    p = fmaf(p, r, 4.166666667e-2f);
    p = fmaf(p, r, 1.666666667e-1f);
    p = fmaf(p, r, 0.5f);
    p = fmaf(p, r, 1.0f);
    p = fmaf(p, r, 1.0f);
    int ni = (int)n;
    float sc = __int_as_float((ni + 127) << 23);
    return p * sc;
}

__device__ __forceinline__ float log_acc(float x) {
    int xi = __float_as_int(x);
    int e = ((xi >> 23) & 0xff) - 127;
    float m = __int_as_float((xi & 0x7fffff) | 0x3f800000);
    if (m > 1.4142135623730951f) { m *= 0.5f; e += 1; }
    float fe = (float)e;
    float s = __fdiv_rn(m - 1.0f, m + 1.0f);
    float s2 = s * s;
    float p = 0.111111111f;
    p = fmaf(p, s2, 0.142857143f);
    p = fmaf(p, s2, 0.2f);
    p = fmaf(p, s2, 0.333333333f);
    p = p * s2;
    float logm = fmaf(2.0f * s, p, 2.0f * s);
    float res = fmaf(fe, 0.6931471824645996f, logm);
    res = fmaf(fe, -1.9046542121259063e-9f, res);
    return res;
}

__device__ __forceinline__ float sigmoid_acc(float x) {
    return __fdiv_rn(1.0f, 1.0f + exp_acc(-x));
}
__device__ __forceinline__ float tanh_acc(float x) {
    float a = fabsf(x);
    float e = exp_acc(-2.0f * a);
    float t = __fdiv_rn(1.0f - e, 1.0f + e);
    return copysignf(t, x);
}

#define MMA16(ACC, A0,A1,A2,A3, B0,B1)                                        \
    asm volatile(                                                             \
        "mma.sync.aligned.m16n8k16.row.col.f32.f16.f16.f32 "                  \
        "{%0,%1,%2,%3}, {%4,%5,%6,%7}, {%8,%9}, {%0,%1,%2,%3};\n"             \
        : "+f"(ACC[0]), "+f"(ACC[1]), "+f"(ACC[2]), "+f"(ACC[3])              \
        : "r"(A0), "r"(A1), "r"(A2), "r"(A3), "r"(B0), "r"(B1))

// ---------------- fp16x3 GEMM (templated on pre-split operands) --------------
// C[M,N] = A[M,K]*B[N,K]^T + bias. 128x64 tile, 8 warps, warp 32x32.
template<int PA, int PB>
__global__ __launch_bounds__(256)
void gemm_t(const void* __restrict__ Ap, int lda,
            const void* __restrict__ Bp, int ldb,
            float* __restrict__ C, int ldc,
            int K, const float* __restrict__ bias, int relu,
            const int* __restrict__ row_lens)
{
    __shared__ uint2 As2[128][16];
    __shared__ uint2 Bs2[64][16];

    const float* Af = (const float*)Ap;
    const uint2* Au = (const uint2*)Ap;
    const float* Bf = (const float*)Bp;
    const uint2* Bu = (const uint2*)Bp;
    const int ldau = lda >> 1, ldbu = ldb >> 1;

    const int tid  = threadIdx.x;
    const int warp = tid >> 5, lane = tid & 31;
    const int g    = lane >> 2, tig = lane & 3;
    const int m0   = blockIdx.y * 128, n0 = blockIdx.x * 64;
    const int wm   = (warp >> 1) * 32, wn = (warp & 1) * 32;
    const int swz  = (g & 3) << 2;

    if (row_lens) {
        int b = m0 >> 9;
        int ts = m0 & 511;
        if (ts >= row_lens[b]) return;
    }

    float accH[2][4][4], accC[2][4][4];
#pragma unroll
    for (int mi = 0; mi < 2; mi++)
#pragma unroll
        for (int ni = 0; ni < 4; ni++)
#pragma unroll
            for (int r = 0; r < 4; r++) { accH[mi][ni][r] = 0.f; accC[mi][ni][r] = 0.f; }

    float2 ra2[8], rb2[4];
    uint2  rau[8], rbu[4];
#pragma unroll
    for (int i = 0; i < 8; i++) {
        int idx = tid + i * 256; int m = idx >> 4, kp = idx & 15;
        if (PA) rau[i] = Au[(size_t)(m0 + m) * ldau + kp];
        else    ra2[i] = *(const float2*)(Af + (size_t)(m0 + m) * lda + kp * 2);
    }
#pragma unroll
    for (int i = 0; i < 4; i++) {
        int idx = tid + i * 256; int n = idx >> 4, kp = idx & 15;
        if (PB) rbu[i] = Bu[(size_t)(n0 + n) * ldbu + kp];
        else    rb2[i] = *(const float2*)(Bf + (size_t)(n0 + n) * ldb + kp * 2);
    }

    const int nchunk = K >> 5;
    for (int ch = 0; ch < nchunk; ch++) {
#pragma unroll
        for (int i = 0; i < 8; i++) {
            int idx = tid + i * 256; int m = idx >> 4, kp = idx & 15;
            As2[m][kp ^ ((m & 3) << 2)] = PA ? rau[i] : splitpk(ra2[i]);
        }
#pragma unroll
        for (int i = 0; i < 4; i++) {
            int idx = tid + i * 256; int n = idx >> 4, kp = idx & 15;
            Bs2[n][kp ^ ((n & 3) << 2)] = PB ? rbu[i] : splitpk(rb2[i]);
        }
        __syncthreads();

        if (ch + 1 < nchunk) {
            int k0 = (ch + 1) << 5;
            int kp0 = (ch + 1) << 4;
#pragma unroll
            for (int i = 0; i < 8; i++) {
                int idx = tid + i * 256; int m = idx >> 4, kp = idx & 15;
                if (PA) rau[i] = Au[(size_t)(m0 + m) * ldau + kp0 + kp];
                else    ra2[i] = *(const float2*)(Af + (size_t)(m0 + m) * lda + k0 + kp * 2);
            }
#pragma unroll
            for (int i = 0; i < 4; i++) {
                int idx = tid + i * 256; int n = idx >> 4, kp = idx & 15;
                if (PB) rbu[i] = Bu[(size_t)(n0 + n) * ldbu + kp0 + kp];
                else    rb2[i] = *(const float2*)(Bf + (size_t)(n0 + n) * ldb + k0 + kp * 2);
            }
        }

#pragma unroll
        for (int sub = 0; sub < 2; sub++) {
            int i0 = ((sub << 3) + tig)     ^ swz;
            int i1 = ((sub << 3) + tig + 4) ^ swz;
            uint2 a[2][4];
#pragma unroll
            for (int mi = 0; mi < 2; mi++) {
                int r0 = wm + mi * 16;
                a[mi][0] = As2[r0 + g    ][i0];
                a[mi][1] = As2[r0 + g + 8][i0];
                a[mi][2] = As2[r0 + g    ][i1];
                a[mi][3] = As2[r0 + g + 8][i1];
            }
            uint2 b[4][2];
#pragma unroll
            for (int ni = 0; ni < 4; ni++) {
                int nrow = wn + ni * 8 + g;
                b[ni][0] = Bs2[nrow][i0];
                b[ni][1] = Bs2[nrow][i1];
            }
#pragma unroll
            for (int mi = 0; mi < 2; mi++)
#pragma unroll
                for (int ni = 0; ni < 4; ni++)
                    MMA16(accC[mi][ni], a[mi][0].x,a[mi][1].x,a[mi][2].x,a[mi][3].x,
                          b[ni][0].y, b[ni][1].y);
#pragma unroll
            for (int mi = 0; mi < 2; mi++)
#pragma unroll
                for (int ni = 0; ni < 4; ni++)
                    MMA16(accC[mi][ni], a[mi][0].y,a[mi][1].y,a[mi][2].y,a[mi][3].y,
                          b[ni][0].x, b[ni][1].x);
#pragma unroll
            for (int mi = 0; mi < 2; mi++)
#pragma unroll
                for (int ni = 0; ni < 4; ni++)
                    MMA16(accH[mi][ni], a[mi][0].x,a[mi][1].x,a[mi][2].x,a[mi][3].x,
                          b[ni][0].x, b[ni][1].x);
        }
        __syncthreads();
    }

#pragma unroll
    for (int mi = 0; mi < 2; mi++)
#pragma unroll
        for (int ni = 0; ni < 4; ni++) {
            int r = m0 + wm + mi * 16 + g;
            int c = n0 + wn + ni * 8 + tig * 2;
            float b0 = bias ? bias[c]     : 0.f;
            float b1 = bias ? bias[c + 1] : 0.f;
            float v0 = fmaf(accC[mi][ni][0], INV2048, accH[mi][ni][0]) + b0;
            float v1 = fmaf(accC[mi][ni][1], INV2048, accH[mi][ni][1]) + b1;
            float v2 = fmaf(accC[mi][ni][2], INV2048, accH[mi][ni][2]) + b0;
            float v3 = fmaf(accC[mi][ni][3], INV2048, accH[mi][ni][3]) + b1;
            if (relu) { v0 = fmaxf(v0, 0.f); v1 = fmaxf(v1, 0.f);
                        v2 = fmaxf(v2, 0.f); v3 = fmaxf(v3, 0.f); }
            C[(size_t)r * ldc + c]           = v0;
            C[(size_t)r * ldc + c + 1]       = v1;
            C[(size_t)(r + 8) * ldc + c]     = v2;
            C[(size_t)(r + 8) * ldc + c + 1] = v3;
        }
}

// ---------------- persistent GRU recurrence (v7) -----------------------------
// Split-packed h in global (g_hsplit, dbl buf): loaders pure LDG.64->STS.64.
// 3-stage A pipeline, prefetch distance 2. Fragment gate math, fp32 h written
// only at the final step.
__device__ __forceinline__ void ld_chunk(const uint2* __restrict__ hs, int m0,
                                         int ch, int tid, uint2* r) {
    int base = ch << 5;
#pragma unroll
    for (int i = 0; i < 4; i++) {
        int idx = tid + i * 256; int m = idx >> 5, kp = idx & 31;
        r[i] = hs[(size_t)(m0 + m) * 256 + base + kp];
    }
}
__device__ __forceinline__ void st_chunk(uint2* __restrict__ buf, int tid,
                                         const uint2* r) {
#pragma unroll
    for (int i = 0; i < 4; i++) {
        int idx = tid + i * 256; int m = idx >> 5, kp = idx & 31;
        buf[(m << 5) + (kp & ~15) + ((kp & 15) ^ ((m & 3) << 2))] = r[i];
    }
}

__global__ __launch_bounds__(256, 1)
void gru_persistent(const float* __restrict__ GI,
                    const float* __restrict__ W_hh,
                    const float* __restrict__ b_hh,
                    const int*   __restrict__ lengths,
                    uint2* __restrict__ hsplit,
                    float* __restrict__ hfinal,
                    unsigned* __restrict__ bar)
{
    extern __shared__ uint2 smem2[];
    uint2* Ws2 = smem2;                      // 96*256 uint2 = 196608 B
    uint2* Ab2 = smem2 + WS_UNITS;           // 3 stages x 1024 uint2 = 24576 B

    const int tid  = threadIdx.x;
    const int warp = tid >> 5, lane = tid & 31;
    const int g    = lane >> 2, tig = lane & 3;
    const int swz  = (g & 3) << 2;
    const int cgp  = blockIdx.x & 15;
    const int bg   = blockIdx.x >> 4;
    const int m0   = bg * 32;
    const int jj0  = cgp * 32;
    const int wm   = (warp & 1) * 16;
    const int jg   = warp >> 1;
    unsigned* mybar = bar + bg;

    // one-time W slice preload. SMEM row n = jg*24 + gate*8 + jo.
    for (int i = tid; i < WS_UNITS; i += 256) {
        int n = i >> 8, kp = i & 255;
        int jgn = n / 24, rem = n - jgn * 24;
        int gate = rem >> 3, jo = rem & 7;
        int wrow = gate * Hn + jj0 + jgn * 8 + jo;
        float2 w = *(const float2*)(W_hh + (size_t)wrow * Hn + kp * 2);
        int off = (n << 8) + (kp & ~15) + ((kp & 15) ^ ((n & 3) << 2));
        Ws2[off] = splitpk(w);
    }
    __syncthreads();

    const int b0i = m0 + wm + g, b1i = b0i + 8;
    const int jjA = jj0 + jg * 8 + tig * 2, jjB = jjA + 1;
    const int kpidx = jjA >> 1;
    const int len0 = lengths[b0i], len1 = lengths[b1i];
    float bb[3][2];
#pragma unroll
    for (int gate = 0; gate < 3; gate++) {
        bb[gate][0] = b_hh[gate * Hn + jjA];
        bb[gate][1] = b_hh[gate * Hn + jjB];
    }
    float h_old[4] = {0.f, 0.f, 0.f, 0.f};

    float pg[3][4];
#pragma unroll
    for (int gate = 0; gate < 3; gate++) {
        const float* gb = GI + gate * Hn;
        pg[gate][0] = gb[(size_t)b0i * Tn * H3 + jjA];
        pg[gate][1] = gb[(size_t)b0i * Tn * H3 + jjB];
        pg[gate][2] = gb[(size_t)b1i * Tn * H3 + jjA];
        pg[gate][3] = gb[(size_t)b1i * Tn * H3 + jjB];
    }

    for (int t = 0; t < Tn; t++) {
        const uint2* hs_in = hsplit + (t & 1) * (Bn * 256);
        uint2*      hs_out = hsplit + ((t + 1) & 1) * (Bn * 256);

        float accP[3][4], accQ[3][4], accR[3][4];
#pragma unroll
        for (int nt = 0; nt < 3; nt++)
#pragma unroll
            for (int r = 0; r < 4; r++) {
                accP[nt][r] = 0.f; accQ[nt][r] = 0.f; accR[nt][r] = 0.f;
            }

        uint2 rA[4], rB[4];
        ld_chunk(hs_in, m0, 0, tid, rA);
        ld_chunk(hs_in, m0, 1, tid, rB);
        st_chunk(Ab2, tid, rA);
        __syncthreads();

        for (int ch = 0; ch < 8; ch++) {
            if (ch + 2 < 8) ld_chunk(hs_in, m0, ch + 2, tid, rA);

            const uint2* Ah = Ab2 + (ch % 3) * 1024;
            const int chbase = ch << 5;
#pragma unroll
            for (int sub = 0; sub < 4; sub++) {
                int i0 = ((sub << 3) + tig)     ^ swz;
                int i1 = ((sub << 3) + tig + 4) ^ swz;
                uint2 a0 = Ah[((wm + g)     << 5) + i0];
                uint2 a1 = Ah[((wm + g + 8) << 5) + i0];
                uint2 a2 = Ah[((wm + g)     << 5) + i1];
                uint2 a3 = Ah[((wm + g + 8) << 5) + i1];
                uint2 b0v[3], b1v[3];
#pragma unroll
                for (int nt = 0; nt < 3; nt++) {
                    int nrow = jg * 24 + nt * 8 + g;
                    int base = (nrow << 8) + chbase;
                    b0v[nt] = Ws2[base + i0];
                    b1v[nt] = Ws2[base + i1];
                }
#pragma unroll
                for (int nt = 0; nt < 3; nt++)
                    MMA16(accQ[nt], a0.x, a1.x, a2.x, a3.x, b0v[nt].y, b1v[nt].y);
#pragma unroll
                for (int nt = 0; nt < 3; nt++)
                    MMA16(accR[nt], a0.y, a1.y, a2.y, a3.y, b0v[nt].x, b1v[nt].x);
#pragma unroll
                for (int nt = 0; nt < 3; nt++)
                    MMA16(accP[nt], a0.x, a1.x, a2.x, a3.x, b0v[nt].x, b1v[nt].x);
            }
            if (ch + 1 < 8) {
                st_chunk(Ab2 + ((ch + 1) % 3) * 1024, tid, rB);
#pragma unroll
                for (int i = 0; i < 4; i++) rB[i] = rA[i];
            }
            __syncthreads();
        }

        // gate math fully in registers (nt 0=r, 1=z, 2=n)
        float gh[3][4];
#pragma unroll
        for (int nt = 0; nt < 3; nt++)
#pragma unroll
            for (int k = 0; k < 4; k++)
                gh[nt][k] = fmaf(accQ[nt][k] + accR[nt][k], INV2048,
                                 accP[nt][k]) + bb[nt][k & 1];
#pragma unroll
        for (int k = 0; k < 4; k++) {
            float r = sigmoid_acc(pg[0][k] + gh[0][k]);
            float z = sigmoid_acc(pg[1][k] + gh[1][k]);
            float n = tanh_acc(fmaf(r, gh[2][k], pg[2][k]));
            int blen = (k < 2) ? len0 : len1;
            float hv = (1.f - z) * n + z * h_old[k];
            h_old[k] = (t < blen) ? hv : h_old[k];
        }
        hs_out[(size_t)b0i * 256 + kpidx] = splitpk(make_float2(h_old[0], h_old[1]));
        hs_out[(size_t)b1i * 256 + kpidx] = splitpk(make_float2(h_old[2], h_old[3]));
        if (t == Tn - 1) {
            hfinal[(size_t)b0i * Hn + jjA] = h_old[0];
            hfinal[(size_t)b0i * Hn + jjB] = h_old[1];
            hfinal[(size_t)b1i * Hn + jjA] = h_old[2];
            hfinal[(size_t)b1i * Hn + jjB] = h_old[3];
        }

        // per-batch-group barrier (16 CTAs) + GI prefetch for t+1 during wait
        __syncthreads();
        if (tid == 0) {
            __threadfence();
            atomicAdd(mybar, 1u);
        }
        if (t + 1 < Tn) {
            size_t off0 = ((size_t)b0i * Tn + (t + 1)) * H3;
            size_t off1 = ((size_t)b1i * Tn + (t + 1)) * H3;
#pragma unroll
            for (int gate = 0; gate < 3; gate++) {
                pg[gate][0] = GI[off0 + gate * Hn + jjA];
                pg[gate][1] = GI[off0 + gate * Hn + jjB];
                pg[gate][2] = GI[off1 + gate * Hn + jjA];
                pg[gate][3] = GI[off1 + gate * Hn + jjB];
            }
        }
        if (tid == 0) {
            unsigned target = 16u * (unsigned)(t + 1);
            unsigned v;
            do {
                asm volatile("ld.acquire.gpu.global.b32 %0, [%1];"
                             : "=r"(v) : "l"(mybar) : "memory");
                if (v < target) __nanosleep(16);
            } while (v < target);
        }
        __syncthreads();
    }
}

// ---------------- misc -------------------------------------------------------
__global__ void init_kernel(uint2* hs0, unsigned* bar) {
    int i = blockIdx.x * blockDim.x + threadIdx.x;
    if (i < Bn * 256) hs0[i] = make_uint2(0u, 0u);
    if (i < 8) bar[i] = 0u;
}

// pre-split x (BT*256 pairs) then W_ih (H3*256 pairs)
#define XSP_N  ((size_t)BT * 256)
#define WSP_N  ((size_t)H3 * 256)
__global__ void presplit_kernel(const float* __restrict__ x,
                                const float* __restrict__ wih,
                                uint2* __restrict__ xsp,
                                uint2* __restrict__ wsp)
{
    size_t i = (size_t)blockIdx.x * 256 + threadIdx.x;
    if (i < XSP_N) {
        xsp[i] = splitpk(((const float2*)x)[i]);
    } else {
        size_t j = i - XSP_N;
        if (j < WSP_N) wsp[j] = splitpk(((const float2*)wih)[j]);
    }
}

__global__ void value_kernel(const float* __restrict__ h2,
                             const float* __restrict__ Wc3,
                             const float* __restrict__ bc3,
                             float* __restrict__ out)
{
    int gw = (blockIdx.x * blockDim.x + threadIdx.x) >> 5;
    int lane = threadIdx.x & 31;
    if (gw >= Bn) return;
    float s = 0.f;
    for (int k = lane; k < Hn; k += 32) s = fmaf(h2[gw * Hn + k], Wc3[k], s);
#pragma unroll
    for (int o = 16; o; o >>= 1) s += __shfl_xor_sync(0xffffffffu, s, o);
    if (lane == 0) out[gw] = s + bc3[0];
}

__global__ void gumbel_kernel(unsigned k0, unsigned k1, float* __restrict__ gout)
{
    unsigned i = blockIdx.x * blockDim.x + threadIdx.x;
    unsigned o0, o1;
    threefry2x32(k0, k1, 0u, i, &o0, &o1);
    unsigned bits = o0 ^ o1;
    float f = __uint_as_float((bits >> 9) | 0x3f800000u) - 1.0f;
    float u = fmaxf(f, 1.17549435e-38f);
    float g = -log_acc(-log_acc(u));
    gout[i] = g;
}

__global__ __launch_bounds__(256)
void sample_kernel(const float* __restrict__ logits,
                   const float* __restrict__ gumbel,
                   float* __restrict__ out_query,
                   float* __restrict__ out_lp)
{
    __shared__ float red[256];
    __shared__ int   redi[256];
    int row = blockIdx.x;
    int tid = threadIdx.x;
    const float* lg = logits + (size_t)row * DICTn;
    const float* gm = gumbel + (size_t)row * DICTn;

    float l[4];
#pragma unroll
    for (int i = 0; i < 4; i++) l[i] = lg[tid + i * 256];

    float mx = fmaxf(fmaxf(l[0], l[1]), fmaxf(l[2], l[3]));
    red[tid] = mx; __syncthreads();
    for (int s = 128; s > 0; s >>= 1) {
        if (tid < s) red[tid] = fmaxf(red[tid], red[tid + s]);
        __syncthreads();
    }
    mx = red[0]; __syncthreads();

    float se = 0.f;
#pragma unroll
    for (int i = 0; i < 4; i++) se += exp_acc(l[i] - mx);
    red[tid] = se; __syncthreads();
    for (int s = 128; s > 0; s >>= 1) {
        if (tid < s) red[tid] += red[tid + s];
        __syncthreads();
    }
    float logZ = mx + log_acc(red[0]); __syncthreads();

    float bv = -1e30f; int bi = 0x7fffffff;
#pragma unroll
    for (int i = 0; i < 4; i++) {
        int idx = tid + i * 256;
        float lp = l[i] - logZ;
        out_lp[(size_t)row * DICTn + idx] = lp;
        float v = lp + gm[idx];
        if (v > bv || (v == bv && idx < bi)) { bv = v; bi = idx; }
    }
    red[tid] = bv; redi[tid] = bi; __syncthreads();
    for (int s = 128; s > 0; s >>= 1) {
        if (tid < s) {
            if (red[tid + s] > red[tid] ||
                (red[tid + s] == red[tid] && redi[tid + s] < redi[tid])) {
                red[tid] = red[tid + s]; redi[tid] = redi[tid + s];
            }
        }
        __syncthreads();
    }
    int win = redi[0];
#pragma unroll
    for (int i = 0; i < 4; i++) {
        int idx = tid + i * 256;
        out_query[(size_t)row * DICTn + idx] = (idx == win) ? 1.f : 0.f;
    }
}

// ---------------- host -------------------------------------------------------
extern "C" void kernel_launch(void* const* d_in, const int* in_sizes, int n_in,
                              void* d_out, int out_size)
{
    const float* x      = (const float*)d_in[0];
    const int*   lens   = (const int*)  d_in[1];
    const float* W_ih   = (const float*)d_in[2];
    const float* W_hh   = (const float*)d_in[3];
    const float* b_ih   = (const float*)d_in[4];
    const float* b_hh   = (const float*)d_in[5];
    const float* W_out  = (const float*)d_in[6];
    const float* b_out  = (const float*)d_in[7];
    const float* Wc1    = (const float*)d_in[8];
    const float* bc1    = (const float*)d_in[9];
    const float* Wc2    = (const float*)d_in[10];
    const float* bc2    = (const float*)d_in[11];
    const float* Wc3    = (const float*)d_in[12];
    const float* bc3    = (const float*)d_in[13];

    float* out_value = (float*)d_out;
    float* out_query = out_value + Bn;
    float* out_lp    = out_query + (size_t)NSAMP;

    float *pGI, *ph, *pc1, *pc2, *plog, *pgum;
    unsigned* pbar;
    uint2 *phs, *pxsp, *pwsp;
    cudaGetSymbolAddress((void**)&pGI,  g_GI);
    cudaGetSymbolAddress((void**)&ph,   g_h);
    cudaGetSymbolAddress((void**)&pc1,  g_c1);
    cudaGetSymbolAddress((void**)&pc2,  g_c2);
    cudaGetSymbolAddress((void**)&plog, g_logits);
    cudaGetSymbolAddress((void**)&pgum, g_gumbel);
    cudaGetSymbolAddress((void**)&pbar, g_barrier);
    cudaGetSymbolAddress((void**)&phs,  g_hsplit);
    cudaGetSymbolAddress((void**)&pxsp, g_xsp);
    cudaGetSymbolAddress((void**)&pwsp, g_wihsp);

    const int rec_smem = WS_UNITS * 8 + 3 * 1024 * 8;   // 221184 B
    cudaFuncSetAttribute(gru_persistent,
        cudaFuncAttributeMaxDynamicSharedMemorySize, rec_smem);

    // 1) zero split-h buffer 0 + barriers
    init_kernel<<<(Bn * 256 + 255) / 256, 256>>>(phs, pbar);

    // 2) pre-split x and W_ih (packed fp16 hi/lo)
    presplit_kernel<<<(unsigned)((XSP_N + WSP_N + 255) / 256), 256>>>(
        x, W_ih, pxsp, pwsp);

    // 3) GI = x @ W_ih^T + b_ih (pre-split both operands, ragged skip)
    gemm_t<1,1><<<dim3(H3 / 64, BT / 128), 256>>>(pxsp, Dn, pwsp, Dn,
                                                  pGI, H3, Dn, b_ih, 0, lens);

    // 4) persistent recurrence (split-h resident in global)
    gru_persistent<<<NCTA_REC, 256, rec_smem>>>(pGI, W_hh, b_hh, lens,
                                                phs, ph, pbar);
    float* hfin = ph;                       // fp32 final hidden
    uint2* hfin_sp = phs;                   // pre-split final hidden (buf 0)

    // 5) critic
    gemm_t<1,0><<<dim3(Hn / 64, Bn / 128), 256>>>(hfin_sp, Hn, Wc1, Hn,
                                                  pc1, Hn, Hn, bc1, 1, nullptr);
    gemm_t<0,0><<<dim3(Hn / 64, Bn / 128), 256>>>(pc1, Hn, Wc2, Hn,
                                                  pc2, Hn, Hn, bc2, 1, nullptr);
    value_kernel<<<(Bn * 32 + 255) / 256, 256>>>(pc2, Wc3, bc3, out_value);

    // 6) actor logits
    gemm_t<1,0><<<dim3(DICTn * Qn / 64, Bn / 128), 256>>>(
        hfin_sp, Hn, W_out, Hn, plog, DICTn * Qn, Hn, b_out, 0, nullptr);

    // 7) gumbel noise
    unsigned s0, s1;
    threefry2x32(0u, 0u, 0u, 1234u, &s0, &s1);
    gumbel_kernel<<<NSAMP / 256, 256>>>(s0, s1, pgum);

    // 8) log-softmax + categorical sample + one-hot
    sample_kernel<<<Bn * Qn, 256>>>(plog, pgum, out_query, out_lp);
}

// round 13
// speedup vs baseline: 2.3214x; 1.0474x over previous
#include <cuda_runtime.h>
#include <cuda_fp16.h>
#include <math.h>
#include <stdint.h>

#define Bn    256
#define Tn    512
#define Dn    512
#define Hn    512
#define H3    1536
#define DICTn 1024
#define Qn    32
#define BT    (Bn*Tn)
#define NSAMP (Bn*Qn*DICTn)   // 8388608

#define NCTA_REC 128
#define WS_UNITS (96*256)     // W slice uint2 units (96 gh rows x 256 k-pairs)
#define INV2048  4.8828125e-4f

// ---------------- static device scratch -------------------------------------
__device__ float g_GI[(size_t)BT * H3];
__device__ float g_h[2][Bn * Hn];
__device__ float g_c1[Bn * Hn];
__device__ float g_c2[Bn * Hn];
__device__ float g_logits[(size_t)Bn * Qn * DICTn];
__device__ float g_gumbel[(size_t)NSAMP];
__device__ unsigned g_barrier[8];
__device__ uint2 g_hsplit[2][Bn * 256];            // packed split h (dbl buf)
__device__ uint2 g_xsp[(size_t)BT * 256];          // packed split x
__device__ uint2 g_wihsp[(size_t)H3 * 256];        // packed split W_ih

// ---------------- threefry2x32-20 (JAX-exact) --------------------------------
__host__ __device__ inline void threefry2x32(unsigned k0, unsigned k1,
                                             unsigned x0, unsigned x1,
                                             unsigned* o0, unsigned* o1) {
    unsigned ks2 = k0 ^ k1 ^ 0x1BD11BDAu;
    x0 += k0; x1 += k1;
#define TF_R(r) { x0 += x1; x1 = (x1 << (r)) | (x1 >> (32-(r))); x1 ^= x0; }
    TF_R(13) TF_R(15) TF_R(26) TF_R(6)   x0 += k1;  x1 += ks2 + 1u;
    TF_R(17) TF_R(29) TF_R(16) TF_R(24)  x0 += ks2; x1 += k0  + 2u;
    TF_R(13) TF_R(15) TF_R(26) TF_R(6)   x0 += k0;  x1 += k1  + 3u;
    TF_R(17) TF_R(29) TF_R(16) TF_R(24)  x0 += k1;  x1 += ks2 + 4u;
    TF_R(13) TF_R(15) TF_R(26) TF_R(6)   x0 += ks2; x1 += k0  + 5u;
#undef TF_R
    *o0 = x0; *o1 = x1;
}

// fp16x3 split: pack 2 consecutive k. .x = hi pair, .y = lo pair scaled x2048.
__device__ __forceinline__ uint2 splitpk(float2 v) {
    __half hx = __float2half_rn(v.x);
    __half hy = __float2half_rn(v.y);
    float rx = (v.x - __half2float(hx)) * 2048.0f;
    float ry = (v.y - __half2float(hy)) * 2048.0f;
    __half lx = __float2half_rn(rx);
    __half ly = __float2half_rn(ry);
    uint2 r;
    r.x = (unsigned)__half_as_ushort(hx) | ((unsigned)__half_as_ushort(hy) << 16);
    r.y = (unsigned)__half_as_ushort(lx) | ((unsigned)__half_as_ushort(ly) << 16);
    return r;
}

// ---------------- accurate fp32 exp/log --------------------------------------
__device__ __forceinline__ float exp_acc(float x) {
    x = fminf(fmaxf(x, -80.f), 80.f);
    float n = rintf(x * 1.4426950408889634f);
    float r = fmaf(n, -0.6931471824645996f, x);
    r = fmaf(n, 1.9046542121259063e-9f, r);
    float p = 1.984126984e-4f;
    p = fmaf(p, r, 1.388888889e-3f);
    p = fmaf(p, r, 8.333333333e-3f);
    p = fmaf(p, r, 4.166666667e-2f);
    p = fmaf(p, r, 1.666666667e-1f);
    p = fmaf(p, r, 0.5f);
    p = fmaf(p, r, 1.0f);
    p = fmaf(p, r, 1.0f);
    int ni = (int)n;
    float sc = __int_as_float((ni + 127) << 23);
    return p * sc;
}

__device__ __forceinline__ float log_acc(float x) {
    int xi = __float_as_int(x);
    int e = ((xi >> 23) & 0xff) - 127;
    float m = __int_as_float((xi & 0x7fffff) | 0x3f800000);
    if (m > 1.4142135623730951f) { m *= 0.5f; e += 1; }
    float fe = (float)e;
    float s = __fdiv_rn(m - 1.0f, m + 1.0f);
    float s2 = s * s;
    float p = 0.111111111f;
    p = fmaf(p, s2, 0.142857143f);
    p = fmaf(p, s2, 0.2f);
    p = fmaf(p, s2, 0.333333333f);
    p = p * s2;
    float logm = fmaf(2.0f * s, p, 2.0f * s);
    float res = fmaf(fe, 0.6931471824645996f, logm);
    res = fmaf(fe, -1.9046542121259063e-9f, res);
    return res;
}

__device__ __forceinline__ float sigmoid_acc(float x) {
    return __fdiv_rn(1.0f, 1.0f + exp_acc(-x));
}
__device__ __forceinline__ float tanh_acc(float x) {
    float a = fabsf(x);
    float e = exp_acc(-2.0f * a);
    float t = __fdiv_rn(1.0f - e, 1.0f + e);
    return copysignf(t, x);
}

#define MMA16(ACC, A0,A1,A2,A3, B0,B1)                                        \
    asm volatile(                                                             \
        "mma.sync.aligned.m16n8k16.row.col.f32.f16.f16.f32 "                  \
        "{%0,%1,%2,%3}, {%4,%5,%6,%7}, {%8,%9}, {%0,%1,%2,%3};\n"             \
        : "+f"(ACC[0]), "+f"(ACC[1]), "+f"(ACC[2]), "+f"(ACC[3])              \
        : "r"(A0), "r"(A1), "r"(A2), "r"(A3), "r"(B0), "r"(B1))

// ---------------- fp16x3 GEMM (templated on pre-split operands) --------------
template<int PA, int PB>
__global__ __launch_bounds__(256)
void gemm_t(const void* __restrict__ Ap, int lda,
            const void* __restrict__ Bp, int ldb,
            float* __restrict__ C, int ldc,
            int K, const float* __restrict__ bias, int relu,
            const int* __restrict__ row_lens)
{
    __shared__ uint2 As2[128][16];
    __shared__ uint2 Bs2[64][16];

    const float* Af = (const float*)Ap;
    const uint2* Au = (const uint2*)Ap;
    const float* Bf = (const float*)Bp;
    const uint2* Bu = (const uint2*)Bp;
    const int ldau = lda >> 1, ldbu = ldb >> 1;

    const int tid  = threadIdx.x;
    const int warp = tid >> 5, lane = tid & 31;
    const int g    = lane >> 2, tig = lane & 3;
    const int m0   = blockIdx.y * 128, n0 = blockIdx.x * 64;
    const int wm   = (warp >> 1) * 32, wn = (warp & 1) * 32;
    const int swz  = (g & 3) << 2;

    if (row_lens) {
        int b = m0 >> 9;
        int ts = m0 & 511;
        if (ts >= row_lens[b]) return;
    }

    float accH[2][4][4], accC[2][4][4];
#pragma unroll
    for (int mi = 0; mi < 2; mi++)
#pragma unroll
        for (int ni = 0; ni < 4; ni++)
#pragma unroll
            for (int r = 0; r < 4; r++) { accH[mi][ni][r] = 0.f; accC[mi][ni][r] = 0.f; }

    float2 ra2[8], rb2[4];
    uint2  rau[8], rbu[4];
#pragma unroll
    for (int i = 0; i < 8; i++) {
        int idx = tid + i * 256; int m = idx >> 4, kp = idx & 15;
        if (PA) rau[i] = Au[(size_t)(m0 + m) * ldau + kp];
        else    ra2[i] = *(const float2*)(Af + (size_t)(m0 + m) * lda + kp * 2);
    }
#pragma unroll
    for (int i = 0; i < 4; i++) {
        int idx = tid + i * 256; int n = idx >> 4, kp = idx & 15;
        if (PB) rbu[i] = Bu[(size_t)(n0 + n) * ldbu + kp];
        else    rb2[i] = *(const float2*)(Bf + (size_t)(n0 + n) * ldb + kp * 2);
    }

    const int nchunk = K >> 5;
    for (int ch = 0; ch < nchunk; ch++) {
#pragma unroll
        for (int i = 0; i < 8; i++) {
            int idx = tid + i * 256; int m = idx >> 4, kp = idx & 15;
            As2[m][kp ^ ((m & 3) << 2)] = PA ? rau[i] : splitpk(ra2[i]);
        }
#pragma unroll
        for (int i = 0; i < 4; i++) {
            int idx = tid + i * 256; int n = idx >> 4, kp = idx & 15;
            Bs2[n][kp ^ ((n & 3) << 2)] = PB ? rbu[i] : splitpk(rb2[i]);
        }
        __syncthreads();

        if (ch + 1 < nchunk) {
            int k0 = (ch + 1) << 5;
            int kp0 = (ch + 1) << 4;
#pragma unroll
            for (int i = 0; i < 8; i++) {
                int idx = tid + i * 256; int m = idx >> 4, kp = idx & 15;
                if (PA) rau[i] = Au[(size_t)(m0 + m) * ldau + kp0 + kp];
                else    ra2[i] = *(const float2*)(Af + (size_t)(m0 + m) * lda + k0 + kp * 2);
            }
#pragma unroll
            for (int i = 0; i < 4; i++) {
                int idx = tid + i * 256; int n = idx >> 4, kp = idx & 15;
                if (PB) rbu[i] = Bu[(size_t)(n0 + n) * ldbu + kp0 + kp];
                else    rb2[i] = *(const float2*)(Bf + (size_t)(n0 + n) * ldb + k0 + kp * 2);
            }
        }

#pragma unroll
        for (int sub = 0; sub < 2; sub++) {
            int i0 = ((sub << 3) + tig)     ^ swz;
            int i1 = ((sub << 3) + tig + 4) ^ swz;
            uint2 a[2][4];
#pragma unroll
            for (int mi = 0; mi < 2; mi++) {
                int r0 = wm + mi * 16;
                a[mi][0] = As2[r0 + g    ][i0];
                a[mi][1] = As2[r0 + g + 8][i0];
                a[mi][2] = As2[r0 + g    ][i1];
                a[mi][3] = As2[r0 + g + 8][i1];
            }
            uint2 b[4][2];
#pragma unroll
            for (int ni = 0; ni < 4; ni++) {
                int nrow = wn + ni * 8 + g;
                b[ni][0] = Bs2[nrow][i0];
                b[ni][1] = Bs2[nrow][i1];
            }
#pragma unroll
            for (int mi = 0; mi < 2; mi++)
#pragma unroll
                for (int ni = 0; ni < 4; ni++)
                    MMA16(accC[mi][ni], a[mi][0].x,a[mi][1].x,a[mi][2].x,a[mi][3].x,
                          b[ni][0].y, b[ni][1].y);
#pragma unroll
            for (int mi = 0; mi < 2; mi++)
#pragma unroll
                for (int ni = 0; ni < 4; ni++)
                    MMA16(accC[mi][ni], a[mi][0].y,a[mi][1].y,a[mi][2].y,a[mi][3].y,
                          b[ni][0].x, b[ni][1].x);
#pragma unroll
            for (int mi = 0; mi < 2; mi++)
#pragma unroll
                for (int ni = 0; ni < 4; ni++)
                    MMA16(accH[mi][ni], a[mi][0].x,a[mi][1].x,a[mi][2].x,a[mi][3].x,
                          b[ni][0].x, b[ni][1].x);
        }
        __syncthreads();
    }

#pragma unroll
    for (int mi = 0; mi < 2; mi++)
#pragma unroll
        for (int ni = 0; ni < 4; ni++) {
            int r = m0 + wm + mi * 16 + g;
            int c = n0 + wn + ni * 8 + tig * 2;
            float b0 = bias ? bias[c]     : 0.f;
            float b1 = bias ? bias[c + 1] : 0.f;
            float v0 = fmaf(accC[mi][ni][0], INV2048, accH[mi][ni][0]) + b0;
            float v1 = fmaf(accC[mi][ni][1], INV2048, accH[mi][ni][1]) + b1;
            float v2 = fmaf(accC[mi][ni][2], INV2048, accH[mi][ni][2]) + b0;
            float v3 = fmaf(accC[mi][ni][3], INV2048, accH[mi][ni][3]) + b1;
            if (relu) { v0 = fmaxf(v0, 0.f); v1 = fmaxf(v1, 0.f);
                        v2 = fmaxf(v2, 0.f); v3 = fmaxf(v3, 0.f); }
            C[(size_t)r * ldc + c]           = v0;
            C[(size_t)r * ldc + c + 1]       = v1;
            C[(size_t)(r + 8) * ldc + c]     = v2;
            C[(size_t)(r + 8) * ldc + c + 1] = v3;
        }
}

// ---------------- persistent GRU recurrence (v8: split-K, 512 threads) -------
// 128 CTAs = 8 batch-groups x 16 col-groups. 16 warps: warps 0-7 K[0,256),
// warps 8-15 K[256,512). Partials combined via conflict-free SMEM transpose;
// gate math + h store + GI prefetch in upper half only.
__device__ __forceinline__ void ld_chunk(const uint2* __restrict__ hs, int m0,
                                         int ch, int t256, uint2* r) {
    int base = ch << 5;
#pragma unroll
    for (int i = 0; i < 4; i++) {
        int idx = t256 + i * 256; int m = idx >> 5, kp = idx & 31;
        r[i] = hs[(size_t)(m0 + m) * 256 + base + kp];
    }
}
__device__ __forceinline__ void st_chunk(uint2* __restrict__ buf, int t256,
                                         const uint2* r) {
#pragma unroll
    for (int i = 0; i < 4; i++) {
        int idx = t256 + i * 256; int m = idx >> 5, kp = idx & 31;
        buf[(m << 5) + (kp & ~15) + ((kp & 15) ^ ((m & 3) << 2))] = r[i];
    }
}

__global__ __launch_bounds__(512, 1)
void gru_persistent(const float* __restrict__ GI,
                    const float* __restrict__ W_hh,
                    const float* __restrict__ b_hh,
                    const int*   __restrict__ lengths,
                    uint2* __restrict__ hsplit,
                    float* __restrict__ hfinal,
                    unsigned* __restrict__ bar)
{
    extern __shared__ uint2 smem2[];
    uint2* Ws2 = smem2;                      // 96*256 uint2 = 196608 B
    uint2* Ab2 = smem2 + WS_UNITS;           // 4 stages x 1024 uint2 = 32768 B
    float* ghp = (float*)(smem2 + WS_UNITS); // [12][256] overlay after K loop

    const int tid  = threadIdx.x;
    const int warp = tid >> 5, lane = tid & 31;
    const int g    = lane >> 2, tig = lane & 3;
    const int swz  = (g & 3) << 2;
    const int cgp  = blockIdx.x & 15;
    const int bg   = blockIdx.x >> 4;
    const int m0   = bg * 32;
    const int jj0  = cgp * 32;
    const int half = warp >> 3;              // K-half
    const int w8   = warp & 7;
    const int t256 = tid & 255;
    const int wm   = (w8 & 1) * 16;
    const int jg   = w8 >> 1;
    const bool upper = (half == 1);
    unsigned* mybar = bar + bg;

    // one-time W slice preload. SMEM row n = jg*24 + gate*8 + jo.
    for (int i = tid; i < WS_UNITS; i += 512) {
        int n = i >> 8, kp = i & 255;
        int jgn = n / 24, rem = n - jgn * 24;
        int gate = rem >> 3, jo = rem & 7;
        int wrow = gate * Hn + jj0 + jgn * 8 + jo;
        float2 w = *(const float2*)(W_hh + (size_t)wrow * Hn + kp * 2);
        int off = (n << 8) + (kp & ~15) + ((kp & 15) ^ ((n & 3) << 2));
        Ws2[off] = splitpk(w);
    }
    __syncthreads();

    const int b0i = m0 + wm + g, b1i = b0i + 8;
    const int jjA = jj0 + jg * 8 + tig * 2, jjB = jjA + 1;
    const int kpidx = jjA >> 1;
    int len0 = 0, len1 = 0;
    float bb[3][2];
    float h_old[4] = {0.f, 0.f, 0.f, 0.f};
    float pg[3][4];
    if (upper) {
        len0 = lengths[b0i]; len1 = lengths[b1i];
#pragma unroll
        for (int gate = 0; gate < 3; gate++) {
            bb[gate][0] = b_hh[gate * Hn + jjA];
            bb[gate][1] = b_hh[gate * Hn + jjB];
        }
#pragma unroll
        for (int gate = 0; gate < 3; gate++) {
            const float* gb = GI + gate * Hn;
            pg[gate][0] = gb[(size_t)b0i * Tn * H3 + jjA];
            pg[gate][1] = gb[(size_t)b0i * Tn * H3 + jjB];
            pg[gate][2] = gb[(size_t)b1i * Tn * H3 + jjA];
            pg[gate][3] = gb[(size_t)b1i * Tn * H3 + jjB];
        }
    }

    uint2* stage0 = Ab2 + half * 2048;
    uint2* stage1 = stage0 + 1024;
    const int ch0 = half * 4;                // this half's first chunk

    for (int t = 0; t < Tn; t++) {
        const uint2* hs_in = hsplit + (t & 1) * (Bn * 256);
        uint2*      hs_out = hsplit + ((t + 1) & 1) * (Bn * 256);

        float accP[3][4], accQ[3][4], accR[3][4];
#pragma unroll
        for (int nt = 0; nt < 3; nt++)
#pragma unroll
            for (int r = 0; r < 4; r++) {
                accP[nt][r] = 0.f; accQ[nt][r] = 0.f; accR[nt][r] = 0.f;
            }

        uint2 rA[4];
        ld_chunk(hs_in, m0, ch0, t256, rA);
        st_chunk(stage0, t256, rA);
        ld_chunk(hs_in, m0, ch0 + 1, t256, rA);
        __syncthreads();

#pragma unroll
        for (int it = 0; it < 4; it++) {
            const uint2* Ah = (it & 1) ? stage1 : stage0;
            const int chbase = (ch0 + it) << 5;
#pragma unroll
            for (int sub = 0; sub < 4; sub++) {
                int i0 = ((sub << 3) + tig)     ^ swz;
                int i1 = ((sub << 3) + tig + 4) ^ swz;
                uint2 a0 = Ah[((wm + g)     << 5) + i0];
                uint2 a1 = Ah[((wm + g + 8) << 5) + i0];
                uint2 a2 = Ah[((wm + g)     << 5) + i1];
                uint2 a3 = Ah[((wm + g + 8) << 5) + i1];
                uint2 b0v[3], b1v[3];
#pragma unroll
                for (int nt = 0; nt < 3; nt++) {
                    int nrow = jg * 24 + nt * 8 + g;
                    int base = (nrow << 8) + chbase;
                    b0v[nt] = Ws2[base + i0];
                    b1v[nt] = Ws2[base + i1];
                }
#pragma unroll
                for (int nt = 0; nt < 3; nt++)
                    MMA16(accQ[nt], a0.x, a1.x, a2.x, a3.x, b0v[nt].y, b1v[nt].y);
#pragma unroll
                for (int nt = 0; nt < 3; nt++)
                    MMA16(accR[nt], a0.y, a1.y, a2.y, a3.y, b0v[nt].x, b1v[nt].x);
#pragma unroll
                for (int nt = 0; nt < 3; nt++)
                    MMA16(accP[nt], a0.x, a1.x, a2.x, a3.x, b0v[nt].x, b1v[nt].x);
            }
            if (it < 3) {
                st_chunk((it & 1) ? stage0 : stage1, t256, rA);
                if (it < 2) ld_chunk(hs_in, m0, ch0 + it + 2, t256, rA);
            }
            __syncthreads();
        }

        // combine split-K partials: lower half stages, upper half sums
        float part[12];
#pragma unroll
        for (int nt = 0; nt < 3; nt++)
#pragma unroll
            for (int k = 0; k < 4; k++)
                part[nt * 4 + k] = fmaf(accQ[nt][k] + accR[nt][k], INV2048,
                                        accP[nt][k]);
        if (!upper) {
#pragma unroll
            for (int i = 0; i < 12; i++)
                ghp[i * 256 + t256] = part[i];
        }
        __syncthreads();

        if (upper) {
            float gh[3][4];
#pragma unroll
            for (int nt = 0; nt < 3; nt++)
#pragma unroll
                for (int k = 0; k < 4; k++)
                    gh[nt][k] = part[nt * 4 + k] + ghp[(nt * 4 + k) * 256 + t256]
                              + bb[nt][k & 1];
#pragma unroll
            for (int k = 0; k < 4; k++) {
                float r = sigmoid_acc(pg[0][k] + gh[0][k]);
                float z = sigmoid_acc(pg[1][k] + gh[1][k]);
                float n = tanh_acc(fmaf(r, gh[2][k], pg[2][k]));
                int blen = (k < 2) ? len0 : len1;
                float hv = (1.f - z) * n + z * h_old[k];
                h_old[k] = (t < blen) ? hv : h_old[k];
            }
            hs_out[(size_t)b0i * 256 + kpidx] = splitpk(make_float2(h_old[0], h_old[1]));
            hs_out[(size_t)b1i * 256 + kpidx] = splitpk(make_float2(h_old[2], h_old[3]));
            if (t == Tn - 1) {
                hfinal[(size_t)b0i * Hn + jjA] = h_old[0];
                hfinal[(size_t)b0i * Hn + jjB] = h_old[1];
                hfinal[(size_t)b1i * Hn + jjA] = h_old[2];
                hfinal[(size_t)b1i * Hn + jjB] = h_old[3];
            }
        }

        // per-batch-group barrier (16 CTAs) + GI prefetch for t+1 during wait
        __syncthreads();
        if (tid == 0) {
            __threadfence();
            atomicAdd(mybar, 1u);
        }
        if (upper && t + 1 < Tn) {
            size_t off0 = ((size_t)b0i * Tn + (t + 1)) * H3;
            size_t off1 = ((size_t)b1i * Tn + (t + 1)) * H3;
#pragma unroll
            for (int gate = 0; gate < 3; gate++) {
                pg[gate][0] = GI[off0 + gate * Hn + jjA];
                pg[gate][1] = GI[off0 + gate * Hn + jjB];
                pg[gate][2] = GI[off1 + gate * Hn + jjA];
                pg[gate][3] = GI[off1 + gate * Hn + jjB];
            }
        }
        if (tid == 0) {
            unsigned target = 16u * (unsigned)(t + 1);
            unsigned v;
            do {
                asm volatile("ld.acquire.gpu.global.b32 %0, [%1];"
                             : "=r"(v) : "l"(mybar) : "memory");
                if (v < target) __nanosleep(16);
            } while (v < target);
        }
        __syncthreads();
    }
}

// ---------------- misc -------------------------------------------------------
__global__ void init_kernel(uint2* hs0, unsigned* bar) {
    int i = blockIdx.x * blockDim.x + threadIdx.x;
    if (i < Bn * 256) hs0[i] = make_uint2(0u, 0u);
    if (i < 8) bar[i] = 0u;
}

#define XSP_N  ((size_t)BT * 256)
#define WSP_N  ((size_t)H3 * 256)
__global__ void presplit_kernel(const float* __restrict__ x,
                                const float* __restrict__ wih,
                                uint2* __restrict__ xsp,
                                uint2* __restrict__ wsp)
{
    size_t i = (size_t)blockIdx.x * 256 + threadIdx.x;
    if (i < XSP_N) {
        xsp[i] = splitpk(((const float2*)x)[i]);
    } else {
        size_t j = i - XSP_N;
        if (j < WSP_N) wsp[j] = splitpk(((const float2*)wih)[j]);
    }
}

__global__ void value_kernel(const float* __restrict__ h2,
                             const float* __restrict__ Wc3,
                             const float* __restrict__ bc3,
                             float* __restrict__ out)
{
    int gw = (blockIdx.x * blockDim.x + threadIdx.x) >> 5;
    int lane = threadIdx.x & 31;
    if (gw >= Bn) return;
    float s = 0.f;
    for (int k = lane; k < Hn; k += 32) s = fmaf(h2[gw * Hn + k], Wc3[k], s);
#pragma unroll
    for (int o = 16; o; o >>= 1) s += __shfl_xor_sync(0xffffffffu, s, o);
    if (lane == 0) out[gw] = s + bc3[0];
}

__global__ void gumbel_kernel(unsigned k0, unsigned k1, float* __restrict__ gout)
{
    unsigned i = blockIdx.x * blockDim.x + threadIdx.x;
    unsigned o0, o1;
    threefry2x32(k0, k1, 0u, i, &o0, &o1);
    unsigned bits = o0 ^ o1;
    float f = __uint_as_float((bits >> 9) | 0x3f800000u) - 1.0f;
    float u = fmaxf(f, 1.17549435e-38f);
    float g = -log_acc(-log_acc(u));
    gout[i] = g;
}

__global__ __launch_bounds__(256)
void sample_kernel(const float* __restrict__ logits,
                   const float* __restrict__ gumbel,
                   float* __restrict__ out_query,
                   float* __restrict__ out_lp)
{
    __shared__ float red[256];
    __shared__ int   redi[256];
    int row = blockIdx.x;
    int tid = threadIdx.x;
    const float* lg = logits + (size_t)row * DICTn;
    const float* gm = gumbel + (size_t)row * DICTn;

    float l[4];
#pragma unroll
    for (int i = 0; i < 4; i++) l[i] = lg[tid + i * 256];

    float mx = fmaxf(fmaxf(l[0], l[1]), fmaxf(l[2], l[3]));
    red[tid] = mx; __syncthreads();
    for (int s = 128; s > 0; s >>= 1) {
        if (tid < s) red[tid] = fmaxf(red[tid], red[tid + s]);
        __syncthreads();
    }
    mx = red[0]; __syncthreads();

    float se = 0.f;
#pragma unroll
    for (int i = 0; i < 4; i++) se += exp_acc(l[i] - mx);
    red[tid] = se; __syncthreads();
    for (int s = 128; s > 0; s >>= 1) {
        if (tid < s) red[tid] += red[tid + s];
        __syncthreads();
    }
    float logZ = mx + log_acc(red[0]); __syncthreads();

    float bv = -1e30f; int bi = 0x7fffffff;
#pragma unroll
    for (int i = 0; i < 4; i++) {
        int idx = tid + i * 256;
        float lp = l[i] - logZ;
        out_lp[(size_t)row * DICTn + idx] = lp;
        float v = lp + gm[idx];
        if (v > bv || (v == bv && idx < bi)) { bv = v; bi = idx; }
    }
    red[tid] = bv; redi[tid] = bi; __syncthreads();
    for (int s = 128; s > 0; s >>= 1) {
        if (tid < s) {
            if (red[tid + s] > red[tid] ||
                (red[tid + s] == red[tid] && redi[tid + s] < redi[tid])) {
                red[tid] = red[tid + s]; redi[tid] = redi[tid + s];
            }
        }
        __syncthreads();
    }
    int win = redi[0];
#pragma unroll
    for (int i = 0; i < 4; i++) {
        int idx = tid + i * 256;
        out_query[(size_t)row * DICTn + idx] = (idx == win) ? 1.f : 0.f;
    }
}

// ---------------- host -------------------------------------------------------
extern "C" void kernel_launch(void* const* d_in, const int* in_sizes, int n_in,
                              void* d_out, int out_size)
{
    const float* x      = (const float*)d_in[0];
    const int*   lens   = (const int*)  d_in[1];
    const float* W_ih   = (const float*)d_in[2];
    const float* W_hh   = (const float*)d_in[3];
    const float* b_ih   = (const float*)d_in[4];
    const float* b_hh   = (const float*)d_in[5];
    const float* W_out  = (const float*)d_in[6];
    const float* b_out  = (const float*)d_in[7];
    const float* Wc1    = (const float*)d_in[8];
    const float* bc1    = (const float*)d_in[9];
    const float* Wc2    = (const float*)d_in[10];
    const float* bc2    = (const float*)d_in[11];
    const float* Wc3    = (const float*)d_in[12];
    const float* bc3    = (const float*)d_in[13];

    float* out_value = (float*)d_out;
    float* out_query = out_value + Bn;
    float* out_lp    = out_query + (size_t)NSAMP;

    float *pGI, *ph, *pc1, *pc2, *plog, *pgum;
    unsigned* pbar;
    uint2 *phs, *pxsp, *pwsp;
    cudaGetSymbolAddress((void**)&pGI,  g_GI);
    cudaGetSymbolAddress((void**)&ph,   g_h);
    cudaGetSymbolAddress((void**)&pc1,  g_c1);
    cudaGetSymbolAddress((void**)&pc2,  g_c2);
    cudaGetSymbolAddress((void**)&plog, g_logits);
    cudaGetSymbolAddress((void**)&pgum, g_gumbel);
    cudaGetSymbolAddress((void**)&pbar, g_barrier);
    cudaGetSymbolAddress((void**)&phs,  g_hsplit);
    cudaGetSymbolAddress((void**)&pxsp, g_xsp);
    cudaGetSymbolAddress((void**)&pwsp, g_wihsp);

    const int rec_smem = WS_UNITS * 8 + 4 * 1024 * 8;   // 229376 B
    cudaFuncSetAttribute(gru_persistent,
        cudaFuncAttributeMaxDynamicSharedMemorySize, rec_smem);

    // 1) zero split-h buffer 0 + barriers
    init_kernel<<<(Bn * 256 + 255) / 256, 256>>>(phs, pbar);

    // 2) pre-split x and W_ih (packed fp16 hi/lo)
    presplit_kernel<<<(unsigned)((XSP_N + WSP_N + 255) / 256), 256>>>(
        x, W_ih, pxsp, pwsp);

    // 3) GI = x @ W_ih^T + b_ih
    gemm_t<1,1><<<dim3(H3 / 64, BT / 128), 256>>>(pxsp, Dn, pwsp, Dn,
                                                  pGI, H3, Dn, b_ih, 0, lens);

    // 4) persistent recurrence (split-K, 512 threads)
    gru_persistent<<<NCTA_REC, 512, rec_smem>>>(pGI, W_hh, b_hh, lens,
                                                phs, ph, pbar);
    float* hfin = ph;
    uint2* hfin_sp = phs;

    // 5) critic
    gemm_t<1,0><<<dim3(Hn / 64, Bn / 128), 256>>>(hfin_sp, Hn, Wc1, Hn,
                                                  pc1, Hn, Hn, bc1, 1, nullptr);
    gemm_t<0,0><<<dim3(Hn / 64, Bn / 128), 256>>>(pc1, Hn, Wc2, Hn,
                                                  pc2, Hn, Hn, bc2, 1, nullptr);
    value_kernel<<<(Bn * 32 + 255) / 256, 256>>>(pc2, Wc3, bc3, out_value);

    // 6) actor logits
    gemm_t<1,0><<<dim3(DICTn * Qn / 64, Bn / 128), 256>>>(
        hfin_sp, Hn, W_out, Hn, plog, DICTn * Qn, Hn, b_out, 0, nullptr);

    // 7) gumbel noise
    unsigned s0, s1;
    threefry2x32(0u, 0u, 0u, 1234u, &s0, &s1);
    gumbel_kernel<<<NSAMP / 256, 256>>>(s0, s1, pgum);

    // 8) log-softmax + categorical sample + one-hot
    sample_kernel<<<Bn * Qn, 256>>>(plog, pgum, out_query, out_lp);
}